// round 1
// baseline (speedup 1.0000x reference)
#include <cuda_runtime.h>
#include <math.h>

#define Bc 256
#define Tc 512
#define Dc 256
#define Hc 256
#define Ac 128
#define ZC 1024   // 4*H

// ---------------- scratch (device globals; no allocations allowed) ----------
__device__ float g_xz[(size_t)Bc * Tc * ZC];    // 512 MB: e @ W_x + bias
__device__ float g_outs[(size_t)Bc * Tc * Hc];  // 128 MB: masked h outputs
__device__ float g_vu[Bc * Tc];                 // attention scores pre-softmax
__device__ int   g_seqlen[Bc];

typedef unsigned long long u64;

// ---------------- packed f32x2 helpers (2x FFMA rate on sm_103a) ------------
__device__ __forceinline__ u64 pack2(float lo, float hi) {
    u64 r;
    asm("mov.b64 %0, {%1, %2};" : "=l"(r) : "f"(lo), "f"(hi));
    return r;
}
__device__ __forceinline__ void fma2(u64& d, u64 a, u64 b) {
    asm("fma.rn.f32x2 %0, %1, %2, %0;" : "+l"(d) : "l"(a), "l"(b));
}
__device__ __forceinline__ float2 unpack2(u64 v) {
    float2 f;
    asm("mov.b64 {%0, %1}, %2;" : "=f"(f.x), "=f"(f.y) : "l"(v));
    return f;
}

__device__ __forceinline__ float sigm(float x) { return 1.0f / (1.0f + expf(-x)); }

// ---------------- K0: seq_len[b] = count of nonzero tokens ------------------
__global__ void k_seqlen(const int* __restrict__ x) {
    const int b = blockIdx.x, tid = threadIdx.x;
    int c = (x[b * Tc + tid] != 0) + (x[b * Tc + 256 + tid] != 0);
    #pragma unroll
    for (int o = 16; o; o >>= 1) c += __shfl_xor_sync(~0u, c, o);
    __shared__ int s[8];
    if ((tid & 31) == 0) s[tid >> 5] = c;
    __syncthreads();
    if (tid == 0) {
        int t = 0;
        #pragma unroll
        for (int i = 0; i < 8; i++) t += s[i];
        g_seqlen[b] = t;
    }
}

// ---------------- K1: xz[m,n] = sum_k embed[x[m]][k] * W[k][n] + bias[n] ----
// M = B*T = 131072, K = D = 256, N = 4H = 1024. Tile 128x128x16, 256 threads,
// 8x8 per thread, packed-f32x2 FMAs.
__global__ __launch_bounds__(256, 2)
void k_xgemm(const int* __restrict__ x, const float* __restrict__ embed,
             const float* __restrict__ lk, const float* __restrict__ bias) {
    __shared__ float As[16][132];   // [k][m], padded
    __shared__ float Bs[16][128];   // [k][n]

    const int tid = threadIdx.x;
    const int bm = blockIdx.y * 128;
    const int bn = blockIdx.x * 128;

    // A-load mapping: 2 gathered float4 per thread
    const int arow = tid >> 2;            // 0..63
    const int akc  = (tid & 3) << 2;      // k offset 0,4,8,12
    const float* ap0 = embed + (size_t)x[bm + arow] * Dc + akc;
    const float* ap1 = embed + (size_t)x[bm + arow + 64] * Dc + akc;

    // B-load mapping: 2 float4 per thread
    const int bk  = tid >> 5;             // 0..7
    const int bn0 = (tid & 31) << 2;      // 0..124
    const float* bp = lk + (size_t)bk * ZC + bn + bn0;

    const int tx = tid & 15, ty = tid >> 4;

    u64 acc[8][4];
    #pragma unroll
    for (int i = 0; i < 8; i++)
        #pragma unroll
        for (int p = 0; p < 4; p++) acc[i][p] = 0ull;  // bits 0 == {0.f,0.f}

    for (int k0 = 0; k0 < Dc; k0 += 16) {
        float4 a0 = *(const float4*)(ap0 + k0);
        float4 a1 = *(const float4*)(ap1 + k0);
        float4 b0 = *(const float4*)(bp + (size_t)k0 * ZC);
        float4 b1 = *(const float4*)(bp + (size_t)(k0 + 8) * ZC);

        As[akc + 0][arow] = a0.x;  As[akc + 1][arow] = a0.y;
        As[akc + 2][arow] = a0.z;  As[akc + 3][arow] = a0.w;
        As[akc + 0][arow + 64] = a1.x;  As[akc + 1][arow + 64] = a1.y;
        As[akc + 2][arow + 64] = a1.z;  As[akc + 3][arow + 64] = a1.w;
        *(float4*)&Bs[bk][bn0]     = b0;
        *(float4*)&Bs[bk + 8][bn0] = b1;
        __syncthreads();

        #pragma unroll
        for (int kk = 0; kk < 16; kk++) {
            float4 av0 = *(const float4*)&As[kk][ty * 8];
            float4 av1 = *(const float4*)&As[kk][ty * 8 + 4];
            ulonglong2 bq0 = *(const ulonglong2*)&Bs[kk][tx * 8];
            ulonglong2 bq1 = *(const ulonglong2*)&Bs[kk][tx * 8 + 4];
            float a[8] = {av0.x, av0.y, av0.z, av0.w, av1.x, av1.y, av1.z, av1.w};
            #pragma unroll
            for (int i = 0; i < 8; i++) {
                u64 aa = pack2(a[i], a[i]);
                fma2(acc[i][0], aa, bq0.x);
                fma2(acc[i][1], aa, bq0.y);
                fma2(acc[i][2], aa, bq1.x);
                fma2(acc[i][3], aa, bq1.y);
            }
        }
        __syncthreads();
    }

    // epilogue: + bias, streaming store
    const int col0 = bn + tx * 8;
    float bb[8];
    #pragma unroll
    for (int j = 0; j < 8; j++) bb[j] = bias[col0 + j];
    #pragma unroll
    for (int i = 0; i < 8; i++) {
        float* dst = g_xz + (size_t)(bm + ty * 8 + i) * ZC + col0;
        float o[8];
        #pragma unroll
        for (int p = 0; p < 4; p++) {
            float2 f = unpack2(acc[i][p]);
            o[2 * p] = f.x + bb[2 * p];
            o[2 * p + 1] = f.y + bb[2 * p + 1];
        }
        __stcs((float4*)dst,       make_float4(o[0], o[1], o[2], o[3]));
        __stcs((float4*)(dst + 4), make_float4(o[4], o[5], o[6], o[7]));
    }
}

// ---------------- K2: sequential LSTM, batch-parallel ------------------------
// 64 blocks x 4 batch rows x 256 threads. h,c in SMEM; W_h (1 MB) from L2.
// Per step: z[4,1024] = xz + h @ W_h; gates; write masked h to g_outs.
__global__ __launch_bounds__(256)
void k_lstm(const float* __restrict__ lk) {
    __shared__ float sh_h[4][Hc];
    __shared__ float sh_c[4][Hc];
    __shared__ float sh_z[4][ZC];

    const int tid = threadIdx.x;
    const int b0 = blockIdx.x * 4;
    const ulonglong2* __restrict__ W =
        (const ulonglong2*)(lk + (size_t)Dc * ZC);  // rows D..D+H-1

    int slr[4];
    #pragma unroll
    for (int r = 0; r < 4; r++) {
        sh_h[r][tid] = 0.f;
        sh_c[r][tid] = 0.f;
        slr[r] = g_seqlen[b0 + r];
    }
    __syncthreads();

    const ulonglong2* wp = W + tid;  // column group [4*tid .. 4*tid+3]

    for (int t = 0; t < Tc; t++) {
        u64 acc[4][2];
        #pragma unroll
        for (int r = 0; r < 4; r++) {
            float4 v = __ldcs((const float4*)(g_xz +
                        ((size_t)(b0 + r) * Tc + t) * ZC + tid * 4));
            acc[r][0] = pack2(v.x, v.y);
            acc[r][1] = pack2(v.z, v.w);
        }
        #pragma unroll 4
        for (int k = 0; k < Hc; k++) {
            ulonglong2 w = wp[(size_t)k * 256];
            #pragma unroll
            for (int r = 0; r < 4; r++) {
                float hv = sh_h[r][k];
                u64 hh = pack2(hv, hv);
                fma2(acc[r][0], hh, w.x);
                fma2(acc[r][1], hh, w.y);
            }
        }
        #pragma unroll
        for (int r = 0; r < 4; r++) {
            ulonglong2 v;
            v.x = acc[r][0];
            v.y = acc[r][1];
            *(ulonglong2*)&sh_z[r][tid * 4] = v;
        }
        __syncthreads();

        #pragma unroll
        for (int r = 0; r < 4; r++) {
            float iv = sh_z[r][tid];
            float jv = sh_z[r][tid + 256];
            float fv = sh_z[r][tid + 512];
            float ov = sh_z[r][tid + 768];
            float co = sh_c[r][tid];
            float cn = co * sigm(fv + 1.0f) + sigm(iv) * tanhf(jv);
            float hn = tanhf(cn) * sigm(ov);
            bool m = (t < slr[r]);
            sh_c[r][tid] = m ? cn : co;
            if (m) sh_h[r][tid] = hn;
            g_outs[((size_t)(b0 + r) * Tc + t) * Hc + tid] = m ? hn : 0.f;
        }
        __syncthreads();
    }
}

// ---------------- K3: vu[m] = sum_a tanh(outs[m,:]@w_omega[:,a]+b_om[a])*u_om[a]
// 16 rows per block, 128 threads (one per attention col a).
__global__ __launch_bounds__(128)
void k_vu(const float* __restrict__ w_om, const float* __restrict__ b_om,
          const float* __restrict__ u_om) {
    __shared__ float so[16][Hc];
    __shared__ float sred[16][4];

    const int tid = threadIdx.x;
    const size_t base = (size_t)blockIdx.x * 16;

    for (int i = tid; i < 16 * 64; i += 128) {
        int r = i >> 6, c = (i & 63) << 2;
        *(float4*)&so[r][c] = *(const float4*)&g_outs[(base + r) * Hc + c];
    }
    __syncthreads();

    float acc[16];
    #pragma unroll
    for (int r = 0; r < 16; r++) acc[r] = 0.f;

    #pragma unroll 4
    for (int k = 0; k < Hc; k++) {
        float w = w_om[k * Ac + tid];
        #pragma unroll
        for (int r = 0; r < 16; r++) acc[r] = fmaf(so[r][k], w, acc[r]);
    }

    const float bo = b_om[tid], uo = u_om[tid];
    #pragma unroll
    for (int r = 0; r < 16; r++) {
        float v = tanhf(acc[r] + bo) * uo;
        #pragma unroll
        for (int o = 16; o; o >>= 1) v += __shfl_xor_sync(~0u, v, o);
        if ((tid & 31) == 0) sred[r][tid >> 5] = v;
    }
    __syncthreads();
    if (tid < 16)
        g_vu[base + tid] = sred[tid][0] + sred[tid][1] + sred[tid][2] + sred[tid][3];
}

// ---------------- block reductions for K4 -----------------------------------
__device__ __forceinline__ float blk_sum(float v, float* sr, int tid) {
    #pragma unroll
    for (int o = 16; o; o >>= 1) v += __shfl_xor_sync(~0u, v, o);
    if ((tid & 31) == 0) sr[tid >> 5] = v;
    __syncthreads();
    if (tid < 32) {
        float x = (tid < 8) ? sr[tid] : 0.f;
        #pragma unroll
        for (int o = 4; o; o >>= 1) x += __shfl_xor_sync(~0u, x, o);
        if (tid == 0) sr[0] = x;
    }
    __syncthreads();
    float r = sr[0];
    __syncthreads();
    return r;
}
__device__ __forceinline__ float blk_max(float v, float* sr, int tid) {
    #pragma unroll
    for (int o = 16; o; o >>= 1) v = fmaxf(v, __shfl_xor_sync(~0u, v, o));
    if ((tid & 31) == 0) sr[tid >> 5] = v;
    __syncthreads();
    if (tid < 32) {
        float x = (tid < 8) ? sr[tid] : -INFINITY;
        #pragma unroll
        for (int o = 4; o; o >>= 1) x = fmaxf(x, __shfl_xor_sync(~0u, x, o));
        if (tid == 0) sr[0] = x;
    }
    __syncthreads();
    float r = sr[0];
    __syncthreads();
    return r;
}

// ---------------- K4: softmax over T, weighted sum, 2-class head ------------
__global__ __launch_bounds__(256)
void k_final(const float* __restrict__ w2, const float* __restrict__ b2,
             float* __restrict__ out) {
    __shared__ float sa[Tc];
    __shared__ float sr[32];

    const int b = blockIdx.x, tid = threadIdx.x;
    const float v0 = g_vu[b * Tc + tid];
    const float v1 = g_vu[b * Tc + 256 + tid];

    const float m = blk_max(fmaxf(v0, v1), sr, tid);
    const float e0 = expf(v0 - m), e1 = expf(v1 - m);
    sa[tid] = e0;
    sa[tid + 256] = e1;
    const float Z = blk_sum(e0 + e1, sr, tid);   // also orders sa writes
    const float Zinv = 1.0f / Z;

    // last[j] = sum_t outs[b,t,j] * alpha[t]
    const float* op = g_outs + (size_t)b * Tc * Hc + tid;
    float acc = 0.f;
    #pragma unroll 4
    for (int t = 0; t < Tc; t++) acc = fmaf(op[(size_t)t * Hc], sa[t], acc);
    acc *= Zinv;

    const float l0 = blk_sum(acc * w2[tid * 2], sr, tid);
    const float l1 = blk_sum(acc * w2[tid * 2 + 1], sr, tid);

    if (tid == 0) {
        float a0 = l0 + b2[0], a1 = l1 + b2[1];
        float mm = fmaxf(a0, a1);
        float x0 = expf(a0 - mm), x1 = expf(a1 - mm);
        float s = 1.0f / (x0 + x1);
        out[b * 2 + 0] = x0 * s;
        out[b * 2 + 1] = x1 * s;
    }
}

// ---------------- launcher ---------------------------------------------------
extern "C" void kernel_launch(void* const* d_in, const int* in_sizes, int n_in,
                              void* d_out, int out_size) {
    const int*   x     = (const int*)  d_in[0];
    const float* embed = (const float*)d_in[1];
    const float* lk    = (const float*)d_in[2];
    const float* bias  = (const float*)d_in[3];
    const float* w_om  = (const float*)d_in[4];
    const float* b_om  = (const float*)d_in[5];
    const float* u_om  = (const float*)d_in[6];
    const float* w2    = (const float*)d_in[7];
    const float* b2    = (const float*)d_in[8];
    float* out = (float*)d_out;

    k_seqlen<<<Bc, 256>>>(x);

    dim3 g1(ZC / 128, (Bc * Tc) / 128);   // (8, 1024)
    k_xgemm<<<g1, 256>>>(x, embed, lk, bias);

    k_lstm<<<Bc / 4, 256>>>(lk);          // 64 persistent-ish blocks

    k_vu<<<(Bc * Tc) / 16, 128>>>(w_om, b_om, u_om);

    k_final<<<Bc, 256>>>(w2, b2, out);
}

// round 2
// speedup vs baseline: 3.1945x; 3.1945x over previous
#include <cuda_runtime.h>
#include <math.h>

#define Bc 256
#define Tc 512
#define Dc 256
#define Hc 256
#define Ac 128
#define ZC 1024   // 4*H

#define NCTA_L 128         // persistent LSTM CTAs (8 col-groups x 16 batch-groups)
#define SMEM_LSTM ((256*128 + 16*256 + 16*128) * 4)   // sW + sH + sZ = 155648 B

// ---------------- scratch (device globals; no allocations allowed) ----------
__device__ float g_xz[(size_t)Bc * Tc * ZC];    // 512 MB: e @ W_x + bias
__device__ float g_outs[(size_t)Bc * Tc * Hc];  // 128 MB: masked h outputs
__device__ float g_vu[Bc * Tc];                 // attention scores pre-softmax
__device__ int   g_seqlen[Bc];
__device__ float g_h[2][Bc][Hc];                // double-buffered h exchange
__device__ unsigned g_count;                    // grid barrier counter

typedef unsigned long long u64;

// ---------------- packed f32x2 helpers (2x FFMA rate on sm_103a) ------------
__device__ __forceinline__ u64 pack2(float lo, float hi) {
    u64 r;
    asm("mov.b64 %0, {%1, %2};" : "=l"(r) : "f"(lo), "f"(hi));
    return r;
}
__device__ __forceinline__ void fma2(u64& d, u64 a, u64 b) {
    asm("fma.rn.f32x2 %0, %1, %2, %0;" : "+l"(d) : "l"(a), "l"(b));
}
__device__ __forceinline__ float2 unpack2(u64 v) {
    float2 f;
    asm("mov.b64 {%0, %1}, %2;" : "=f"(f.x), "=f"(f.y) : "l"(v));
    return f;
}

__device__ __forceinline__ float sigm(float x) { return 1.0f / (1.0f + __expf(-x)); }
// overflow-safe fast tanh (~1e-7 rel err)
__device__ __forceinline__ float tanh_f(float x) {
    float ax = fabsf(x);
    float e = __expf(-2.0f * ax);
    float r = (1.0f - e) / (1.0f + e);
    return copysignf(r, x);
}

// ---------------- K0: seq_len + reset barrier/h state -----------------------
__global__ void k_seqlen(const int* __restrict__ x) {
    const int b = blockIdx.x, tid = threadIdx.x;
    int c = (x[b * Tc + tid] != 0) + (x[b * Tc + 256 + tid] != 0);
    #pragma unroll
    for (int o = 16; o; o >>= 1) c += __shfl_xor_sync(~0u, c, o);
    __shared__ int s[8];
    if ((tid & 31) == 0) s[tid >> 5] = c;
    __syncthreads();
    if (tid == 0) {
        int t = 0;
        #pragma unroll
        for (int i = 0; i < 8; i++) t += s[i];
        g_seqlen[b] = t;
    }
}

// zero g_h (both buffers) and the barrier counter — runs before k_lstm2 every
// call, making the persistent kernel's global state replay-safe.
__global__ void k_init() {
    size_t i = ((size_t)blockIdx.x * 256 + threadIdx.x) * 4;  // 32768 threads * 4 floats = 131072
    *(float4*)&(((float*)g_h)[i]) = make_float4(0.f, 0.f, 0.f, 0.f);
    if (blockIdx.x == 0 && threadIdx.x == 0) g_count = 0u;
}

// ---------------- K1: xz[m,n] = sum_k embed[x[m]][k] * W[k][n] + bias[n] ----
__global__ __launch_bounds__(256, 2)
void k_xgemm(const int* __restrict__ x, const float* __restrict__ embed,
             const float* __restrict__ lk, const float* __restrict__ bias) {
    __shared__ float As[16][132];
    __shared__ float Bs[16][128];

    const int tid = threadIdx.x;
    const int bm = blockIdx.y * 128;
    const int bn = blockIdx.x * 128;

    const int arow = tid >> 2;
    const int akc  = (tid & 3) << 2;
    const float* ap0 = embed + (size_t)x[bm + arow] * Dc + akc;
    const float* ap1 = embed + (size_t)x[bm + arow + 64] * Dc + akc;

    const int bk  = tid >> 5;
    const int bn0 = (tid & 31) << 2;
    const float* bp = lk + (size_t)bk * ZC + bn + bn0;

    const int tx = tid & 15, ty = tid >> 4;

    u64 acc[8][4];
    #pragma unroll
    for (int i = 0; i < 8; i++)
        #pragma unroll
        for (int p = 0; p < 4; p++) acc[i][p] = 0ull;

    for (int k0 = 0; k0 < Dc; k0 += 16) {
        float4 a0 = *(const float4*)(ap0 + k0);
        float4 a1 = *(const float4*)(ap1 + k0);
        float4 b0 = *(const float4*)(bp + (size_t)k0 * ZC);
        float4 b1 = *(const float4*)(bp + (size_t)(k0 + 8) * ZC);

        As[akc + 0][arow] = a0.x;  As[akc + 1][arow] = a0.y;
        As[akc + 2][arow] = a0.z;  As[akc + 3][arow] = a0.w;
        As[akc + 0][arow + 64] = a1.x;  As[akc + 1][arow + 64] = a1.y;
        As[akc + 2][arow + 64] = a1.z;  As[akc + 3][arow + 64] = a1.w;
        *(float4*)&Bs[bk][bn0]     = b0;
        *(float4*)&Bs[bk + 8][bn0] = b1;
        __syncthreads();

        #pragma unroll
        for (int kk = 0; kk < 16; kk++) {
            float4 av0 = *(const float4*)&As[kk][ty * 8];
            float4 av1 = *(const float4*)&As[kk][ty * 8 + 4];
            ulonglong2 bq0 = *(const ulonglong2*)&Bs[kk][tx * 8];
            ulonglong2 bq1 = *(const ulonglong2*)&Bs[kk][tx * 8 + 4];
            float a[8] = {av0.x, av0.y, av0.z, av0.w, av1.x, av1.y, av1.z, av1.w};
            #pragma unroll
            for (int i = 0; i < 8; i++) {
                u64 aa = pack2(a[i], a[i]);
                fma2(acc[i][0], aa, bq0.x);
                fma2(acc[i][1], aa, bq0.y);
                fma2(acc[i][2], aa, bq1.x);
                fma2(acc[i][3], aa, bq1.y);
            }
        }
        __syncthreads();
    }

    const int col0 = bn + tx * 8;
    float bb[8];
    #pragma unroll
    for (int j = 0; j < 8; j++) bb[j] = bias[col0 + j];
    #pragma unroll
    for (int i = 0; i < 8; i++) {
        float* dst = g_xz + (size_t)(bm + ty * 8 + i) * ZC + col0;
        float o[8];
        #pragma unroll
        for (int p = 0; p < 4; p++) {
            float2 f = unpack2(acc[i][p]);
            o[2 * p] = f.x + bb[2 * p];
            o[2 * p + 1] = f.y + bb[2 * p + 1];
        }
        __stcs((float4*)dst,       make_float4(o[0], o[1], o[2], o[3]));
        __stcs((float4*)(dst + 4), make_float4(o[4], o[5], o[6], o[7]));
    }
}

// ---------------- grid-wide spin barrier (all CTAs co-resident) -------------
__device__ __forceinline__ void grid_bar(unsigned target) {
    __threadfence();            // release this thread's global writes
    __syncthreads();            // all block threads fenced before arrive
    if (threadIdx.x == 0) {
        atomicAdd(&g_count, 1u);
        unsigned v;
        do {
            asm volatile("ld.global.acquire.gpu.u32 %0, [%1];"
                         : "=r"(v) : "l"(&g_count) : "memory");
        } while (v < target);
    }
    __syncthreads();
}

// ---------------- K2: persistent LSTM, W_h slice resident in SMEM -----------
// Grid = 128 CTAs: g = blockIdx.x & 7 (column group: 32 hidden units =
// 4 gate-strips of 32 z-cols), bg = blockIdx.x >> 3 (16 batches).
// Per step: z-strip = xz + h @ Wh_slice (all from SMEM), gates, h exchanged
// through double-buffered g_h with a grid barrier.
__global__ __launch_bounds__(256, 1)
void k_lstm2(const float* __restrict__ lk) {
    extern __shared__ float sm[];
    float* sW = sm;                       // [256][128]  W_h slice
    float* sH = sm + 256 * 128;           // [16][256]   h for our batches
    float* sZ = sm + 256 * 128 + 16 * 256;// [16][128]   z exchange

    const int tid = threadIdx.x;
    const int g  = blockIdx.x & 7;
    const int bg = blockIdx.x >> 3;
    const int u0 = g * 32;
    const int b0 = bg * 16;

    // ---- load W_h slice into SMEM (once) ----
    for (int idx = tid; idx < 256 * 32; idx += 256) {
        int k  = idx >> 5;
        int cq = idx & 31;
        int zc = (cq >> 3) * 256 + u0 + ((cq & 7) << 2);
        *(float4*)&sW[k * 128 + cq * 4] =
            *(const float4*)&lk[(size_t)(Dc + k) * ZC + zc];
    }

    // ---- z-thread mapping: 32 col-quads x 8 batch-pairs ----
    const int cq = tid & 31;          // col quad within the 128-col strip set
    const int bp = tid >> 5;          // batch pair: batches 2bp, 2bp+1
    const int zbase = (cq >> 3) * 256 + u0 + ((cq & 7) << 2);
    const size_t xz0 = ((size_t)(b0 + 2 * bp) * Tc) * ZC + zbase;
    const size_t xz1 = ((size_t)(b0 + 2 * bp + 1) * Tc) * ZC + zbase;

    // ---- gate-thread mapping: 32 units x 8 batch-slots (b and b+8) ----
    const int gu = tid & 31;
    const int gb = tid >> 5;
    float c0 = 0.f, c1 = 0.f;
    const int sl0 = g_seqlen[b0 + gb];
    const int sl1 = g_seqlen[b0 + gb + 8];

    for (int t = 0; t < Tc; t++) {
        // ---- stage h (prev step, all 256 units, our 16 batches) ----
        {
            const float* hsrc = &g_h[t & 1][b0][0];
            int b = tid >> 4, seg = tid & 15;
            const float4* src = (const float4*)(hsrc + b * Hc + seg * 16);
            float4 v0 = __ldcg(src + 0);
            float4 v1 = __ldcg(src + 1);
            float4 v2 = __ldcg(src + 2);
            float4 v3 = __ldcg(src + 3);
            float4* d = (float4*)&sH[b * 256 + seg * 16];
            d[0] = v0; d[1] = v1; d[2] = v2; d[3] = v3;
        }
        // xz loads (latency overlapped with staging + k-loop)
        float4 xa = __ldcs((const float4*)&g_xz[xz0 + (size_t)t * ZC]);
        float4 xb = __ldcs((const float4*)&g_xz[xz1 + (size_t)t * ZC]);
        __syncthreads();

        // ---- z = h @ W (SMEM-only operands) ----
        u64 a00 = 0ull, a01 = 0ull, a10 = 0ull, a11 = 0ull;
        const float* hA = &sH[(2 * bp) * 256];
        const float* hB = &sH[(2 * bp + 1) * 256];
        #pragma unroll 2
        for (int k = 0; k < Hc; k += 4) {
            float4 ha = *(const float4*)(hA + k);   // broadcast LDS
            float4 hb = *(const float4*)(hB + k);
            #pragma unroll
            for (int kk = 0; kk < 4; kk++) {
                float hax = (kk == 0) ? ha.x : (kk == 1) ? ha.y : (kk == 2) ? ha.z : ha.w;
                float hbx = (kk == 0) ? hb.x : (kk == 1) ? hb.y : (kk == 2) ? hb.z : hb.w;
                ulonglong2 w = *(const ulonglong2*)&sW[(k + kk) * 128 + cq * 4];
                u64 h0 = pack2(hax, hax);
                u64 h1 = pack2(hbx, hbx);
                fma2(a00, h0, w.x); fma2(a01, h0, w.y);
                fma2(a10, h1, w.x); fma2(a11, h1, w.y);
            }
        }
        {
            float2 f00 = unpack2(a00), f01 = unpack2(a01);
            float2 f10 = unpack2(a10), f11 = unpack2(a11);
            *(float4*)&sZ[(2 * bp) * 128 + cq * 4] =
                make_float4(f00.x + xa.x, f00.y + xa.y, f01.x + xa.z, f01.y + xa.w);
            *(float4*)&sZ[(2 * bp + 1) * 128 + cq * 4] =
                make_float4(f10.x + xb.x, f10.y + xb.y, f11.x + xb.z, f11.y + xb.w);
        }
        __syncthreads();

        // ---- gates for (unit gu, batches gb and gb+8) ----
        float* hdst = &g_h[(t + 1) & 1][0][0];
        {
            float zi = sZ[gb * 128 + gu],      zj = sZ[gb * 128 + 32 + gu];
            float zf = sZ[gb * 128 + 64 + gu], zo = sZ[gb * 128 + 96 + gu];
            float cn = c0 * sigm(zf + 1.f) + sigm(zi) * tanh_f(zj);
            float hn = tanh_f(cn) * sigm(zo);
            bool  m  = (t < sl0);
            c0 = m ? cn : c0;
            float hsel = m ? hn : sH[gb * 256 + u0 + gu];
            hdst[(size_t)(b0 + gb) * Hc + u0 + gu] = hsel;
            g_outs[((size_t)(b0 + gb) * Tc + t) * Hc + u0 + gu] = m ? hn : 0.f;
        }
        {
            int b = gb + 8;
            float zi = sZ[b * 128 + gu],      zj = sZ[b * 128 + 32 + gu];
            float zf = sZ[b * 128 + 64 + gu], zo = sZ[b * 128 + 96 + gu];
            float cn = c1 * sigm(zf + 1.f) + sigm(zi) * tanh_f(zj);
            float hn = tanh_f(cn) * sigm(zo);
            bool  m  = (t < sl1);
            c1 = m ? cn : c1;
            float hsel = m ? hn : sH[b * 256 + u0 + gu];
            hdst[(size_t)(b0 + b) * Hc + u0 + gu] = hsel;
            g_outs[((size_t)(b0 + b) * Tc + t) * Hc + u0 + gu] = m ? hn : 0.f;
        }

        grid_bar((unsigned)(t + 1) * NCTA_L);
    }
}

// ---------------- K3: attention scores --------------------------------------
__global__ __launch_bounds__(128)
void k_vu(const float* __restrict__ w_om, const float* __restrict__ b_om,
          const float* __restrict__ u_om) {
    __shared__ float so[16][Hc];
    __shared__ float sred[16][4];

    const int tid = threadIdx.x;
    const size_t base = (size_t)blockIdx.x * 16;

    for (int i = tid; i < 16 * 64; i += 128) {
        int r = i >> 6, c = (i & 63) << 2;
        *(float4*)&so[r][c] = *(const float4*)&g_outs[(base + r) * Hc + c];
    }
    __syncthreads();

    float acc[16];
    #pragma unroll
    for (int r = 0; r < 16; r++) acc[r] = 0.f;

    #pragma unroll 4
    for (int k = 0; k < Hc; k++) {
        float w = w_om[k * Ac + tid];
        #pragma unroll
        for (int r = 0; r < 16; r++) acc[r] = fmaf(so[r][k], w, acc[r]);
    }

    const float bo = b_om[tid], uo = u_om[tid];
    #pragma unroll
    for (int r = 0; r < 16; r++) {
        float v = tanh_f(acc[r] + bo) * uo;
        #pragma unroll
        for (int o = 16; o; o >>= 1) v += __shfl_xor_sync(~0u, v, o);
        if ((tid & 31) == 0) sred[r][tid >> 5] = v;
    }
    __syncthreads();
    if (tid < 16)
        g_vu[base + tid] = sred[tid][0] + sred[tid][1] + sred[tid][2] + sred[tid][3];
}

// ---------------- block reductions for K4 -----------------------------------
__device__ __forceinline__ float blk_sum(float v, float* sr, int tid) {
    #pragma unroll
    for (int o = 16; o; o >>= 1) v += __shfl_xor_sync(~0u, v, o);
    if ((tid & 31) == 0) sr[tid >> 5] = v;
    __syncthreads();
    if (tid < 32) {
        float x = (tid < 8) ? sr[tid] : 0.f;
        #pragma unroll
        for (int o = 4; o; o >>= 1) x += __shfl_xor_sync(~0u, x, o);
        if (tid == 0) sr[0] = x;
    }
    __syncthreads();
    float r = sr[0];
    __syncthreads();
    return r;
}
__device__ __forceinline__ float blk_max(float v, float* sr, int tid) {
    #pragma unroll
    for (int o = 16; o; o >>= 1) v = fmaxf(v, __shfl_xor_sync(~0u, v, o));
    if ((tid & 31) == 0) sr[tid >> 5] = v;
    __syncthreads();
    if (tid < 32) {
        float x = (tid < 8) ? sr[tid] : -INFINITY;
        #pragma unroll
        for (int o = 4; o; o >>= 1) x = fmaxf(x, __shfl_xor_sync(~0u, x, o));
        if (tid == 0) sr[0] = x;
    }
    __syncthreads();
    float r = sr[0];
    __syncthreads();
    return r;
}

// ---------------- K4: softmax over T, weighted sum, 2-class head ------------
__global__ __launch_bounds__(256)
void k_final(const float* __restrict__ w2, const float* __restrict__ b2,
             float* __restrict__ out) {
    __shared__ float sa[Tc];
    __shared__ float sr[32];

    const int b = blockIdx.x, tid = threadIdx.x;
    const float v0 = g_vu[b * Tc + tid];
    const float v1 = g_vu[b * Tc + 256 + tid];

    const float m = blk_max(fmaxf(v0, v1), sr, tid);
    const float e0 = expf(v0 - m), e1 = expf(v1 - m);
    sa[tid] = e0;
    sa[tid + 256] = e1;
    const float Z = blk_sum(e0 + e1, sr, tid);
    const float Zinv = 1.0f / Z;

    const float* op = g_outs + (size_t)b * Tc * Hc + tid;
    float acc = 0.f;
    #pragma unroll 4
    for (int t = 0; t < Tc; t++) acc = fmaf(op[(size_t)t * Hc], sa[t], acc);
    acc *= Zinv;

    const float l0 = blk_sum(acc * w2[tid * 2], sr, tid);
    const float l1 = blk_sum(acc * w2[tid * 2 + 1], sr, tid);

    if (tid == 0) {
        float a0 = l0 + b2[0], a1 = l1 + b2[1];
        float mm = fmaxf(a0, a1);
        float x0 = expf(a0 - mm), x1 = expf(a1 - mm);
        float s = 1.0f / (x0 + x1);
        out[b * 2 + 0] = x0 * s;
        out[b * 2 + 1] = x1 * s;
    }
}

// ---------------- launcher ---------------------------------------------------
extern "C" void kernel_launch(void* const* d_in, const int* in_sizes, int n_in,
                              void* d_out, int out_size) {
    const int*   x     = (const int*)  d_in[0];
    const float* embed = (const float*)d_in[1];
    const float* lk    = (const float*)d_in[2];
    const float* bias  = (const float*)d_in[3];
    const float* w_om  = (const float*)d_in[4];
    const float* b_om  = (const float*)d_in[5];
    const float* u_om  = (const float*)d_in[6];
    const float* w2    = (const float*)d_in[7];
    const float* b2    = (const float*)d_in[8];
    float* out = (float*)d_out;

    cudaFuncSetAttribute(k_lstm2, cudaFuncAttributeMaxDynamicSharedMemorySize,
                         SMEM_LSTM);

    k_seqlen<<<Bc, 256>>>(x);
    k_init<<<128, 256>>>();

    dim3 g1(ZC / 128, (Bc * Tc) / 128);
    k_xgemm<<<g1, 256>>>(x, embed, lk, bias);

    k_lstm2<<<NCTA_L, 256, SMEM_LSTM>>>(lk);

    k_vu<<<(Bc * Tc) / 16, 128>>>(w_om, b_om, u_om);

    k_final<<<Bc, 256>>>(w2, b2, out);
}

// round 4
// speedup vs baseline: 4.1363x; 1.2948x over previous
#include <cuda_runtime.h>
#include <math.h>

#define Bc 256
#define Tc 512
#define Dc 256
#define Hc 256
#define Ac 128
#define ZC 1024   // 4*H

#define NCTA_L 128
#define SMEM_L3 (128*1024 + 16*1024 + 64*1024)   // sW + sH + sZp = 208 KB

// ---------------- scratch (device globals; no allocations allowed) ----------
__device__ float g_xz[(size_t)Bc * Tc * ZC];    // 512 MB
__device__ float g_outs[(size_t)Bc * Tc * Hc];  // 128 MB
__device__ float g_vu[Bc * Tc];
__device__ int   g_seqlen[Bc];
__device__ float g_h[2][Bc][Hc];                // double-buffered h exchange
__device__ unsigned g_bar[16 * 32];             // per-batch-group counters, 128B apart

typedef unsigned long long u64;

__device__ __forceinline__ u64 pack2(float lo, float hi) {
    u64 r;
    asm("mov.b64 %0, {%1, %2};" : "=l"(r) : "f"(lo), "f"(hi));
    return r;
}
__device__ __forceinline__ void fma2(u64& d, u64 a, u64 b) {
    asm("fma.rn.f32x2 %0, %1, %2, %0;" : "+l"(d) : "l"(a), "l"(b));
}
__device__ __forceinline__ float2 unpack2(u64 v) {
    float2 f;
    asm("mov.b64 {%0, %1}, %2;" : "=f"(f.x), "=f"(f.y) : "l"(v));
    return f;
}

__device__ __forceinline__ float sigm(float x) { return 1.0f / (1.0f + __expf(-x)); }
__device__ __forceinline__ float tanh_f(float x) {
    float ax = fabsf(x);
    float e = __expf(-2.0f * ax);
    float r = (1.0f - e) / (1.0f + e);
    return copysignf(r, x);
}

// ---------------- K0: seq_len + barrier reset --------------------------------
__global__ void k_seqlen(const int* __restrict__ x) {
    const int b = blockIdx.x, tid = threadIdx.x;
    int c = (x[b * Tc + tid] != 0) + (x[b * Tc + 256 + tid] != 0);
    #pragma unroll
    for (int o = 16; o; o >>= 1) c += __shfl_xor_sync(~0u, c, o);
    __shared__ int s[8];
    if ((tid & 31) == 0) s[tid >> 5] = c;
    __syncthreads();
    if (tid == 0) {
        int t = 0;
        #pragma unroll
        for (int i = 0; i < 8; i++) t += s[i];
        g_seqlen[b] = t;
    }
}

__global__ void k_init() {
    if (threadIdx.x < 16 * 32) g_bar[threadIdx.x] = 0u;  // replay-safe reset
}

// ---------------- K1: xz = embed[x] @ W_x + bias, pipelined ------------------
__global__ __launch_bounds__(256, 2)
void k_xgemm(const int* __restrict__ x, const float* __restrict__ embed,
             const float* __restrict__ lk, const float* __restrict__ bias) {
    __shared__ float As[2][16][132];
    __shared__ float Bs[2][16][128];

    const int tid = threadIdx.x;
    const int bm = blockIdx.y * 128;
    const int bn = blockIdx.x * 128;

    const int arow = tid >> 2;
    const int akc  = (tid & 3) << 2;
    const float* ap0 = embed + (size_t)x[bm + arow] * Dc + akc;
    const float* ap1 = embed + (size_t)x[bm + arow + 64] * Dc + akc;

    const int bk  = tid >> 5;
    const int bn0 = (tid & 31) << 2;
    const float* bp = lk + (size_t)bk * ZC + bn + bn0;

    const int tx = tid & 15, ty = tid >> 4;

    u64 acc[8][4];
    #pragma unroll
    for (int i = 0; i < 8; i++)
        #pragma unroll
        for (int p = 0; p < 4; p++) acc[i][p] = 0ull;

    float4 ra0, ra1, rb0, rb1;

#define K1_LOAD(K0)                                                   \
    ra0 = *(const float4*)(ap0 + (K0));                               \
    ra1 = *(const float4*)(ap1 + (K0));                               \
    rb0 = *(const float4*)(bp + (size_t)(K0) * ZC);                   \
    rb1 = *(const float4*)(bp + (size_t)((K0) + 8) * ZC);

#define K1_STS(BUF)                                                   \
    As[BUF][akc + 0][arow] = ra0.x;  As[BUF][akc + 1][arow] = ra0.y;  \
    As[BUF][akc + 2][arow] = ra0.z;  As[BUF][akc + 3][arow] = ra0.w;  \
    As[BUF][akc + 0][arow + 64] = ra1.x;  As[BUF][akc + 1][arow + 64] = ra1.y; \
    As[BUF][akc + 2][arow + 64] = ra1.z;  As[BUF][akc + 3][arow + 64] = ra1.w; \
    *(float4*)&Bs[BUF][bk][bn0]     = rb0;                            \
    *(float4*)&Bs[BUF][bk + 8][bn0] = rb1;

    K1_LOAD(0);
    K1_STS(0);
    __syncthreads();

    for (int s = 0; s < 16; s++) {
        const int buf = s & 1;
        if (s < 15) { K1_LOAD((s + 1) * 16); }   // overlapped with compute

        #pragma unroll
        for (int kk = 0; kk < 16; kk++) {
            float4 av0 = *(const float4*)&As[buf][kk][ty * 8];
            float4 av1 = *(const float4*)&As[buf][kk][ty * 8 + 4];
            ulonglong2 bq0 = *(const ulonglong2*)&Bs[buf][kk][tx * 8];
            ulonglong2 bq1 = *(const ulonglong2*)&Bs[buf][kk][tx * 8 + 4];
            float a[8] = {av0.x, av0.y, av0.z, av0.w, av1.x, av1.y, av1.z, av1.w};
            #pragma unroll
            for (int i = 0; i < 8; i++) {
                u64 aa = pack2(a[i], a[i]);
                fma2(acc[i][0], aa, bq0.x);
                fma2(acc[i][1], aa, bq0.y);
                fma2(acc[i][2], aa, bq1.x);
                fma2(acc[i][3], aa, bq1.y);
            }
        }
        if (s < 15) {
            K1_STS(buf ^ 1);
            __syncthreads();
        }
    }

    const int col0 = bn + tx * 8;
    float bb[8];
    #pragma unroll
    for (int j = 0; j < 8; j++) bb[j] = bias[col0 + j];
    #pragma unroll
    for (int i = 0; i < 8; i++) {
        float* dst = g_xz + (size_t)(bm + ty * 8 + i) * ZC + col0;
        float o[8];
        #pragma unroll
        for (int p = 0; p < 4; p++) {
            float2 f = unpack2(acc[i][p]);
            o[2 * p] = f.x + bb[2 * p];
            o[2 * p + 1] = f.y + bb[2 * p + 1];
        }
        __stcs((float4*)dst,       make_float4(o[0], o[1], o[2], o[3]));
        __stcs((float4*)(dst + 4), make_float4(o[4], o[5], o[6], o[7]));
    }
}

// ---------------- per-batch-group barrier (8 CTAs, padded counter) ----------
__device__ __forceinline__ void group_bar(unsigned* ctr, unsigned target) {
    __threadfence();            // release g_h/g_outs writes
    __syncthreads();
    if (threadIdx.x == 0) {
        atomicAdd(ctr, 1u);
        unsigned v;
        do {
            asm volatile("ld.global.acquire.gpu.u32 %0, [%1];"
                         : "=r"(v) : "l"(ctr) : "memory");
        } while (v < target);
    }
    __syncthreads();
}

// ---------------- K2: LSTM, 16 groups x 8 column-CTAs, 8-way K-split --------
// CTA (g, bg): g owns units [32g, 32g+32) with its W_h slice in SMEM.
// 512 threads z-phase: cq=tid&31 (4 z-cols), bb=((tid>>5)&1)*8 (8 batches),
// kg=tid>>6 (32-k slice). Gate phase: gu=tid&31, gb=tid>>5 (16 batches).
// h exchanged via double-buffered g_h + per-group spin barrier.
__global__ __launch_bounds__(512, 1)
void k_lstm3(const float* __restrict__ lk) {
    extern __shared__ float sm[];
    float* sW  = sm;                             // [256][128]
    float* sH  = sm + 256 * 128;                 // [16][256]
    float* sZp = sm + 256 * 128 + 16 * 256;      // [8][16][128]

    const int tid = threadIdx.x;
    const int g  = blockIdx.x & 7;
    const int bg = blockIdx.x >> 3;
    const int u0 = g * 32;
    const int b0 = bg * 16;
    unsigned* const ctr = &g_bar[bg * 32];

    // ---- W_h slice -> SMEM (once) ----
    #pragma unroll 4
    for (int idx = tid; idx < 256 * 32; idx += 512) {
        int k = idx >> 5, cqq = idx & 31;
        int zc = (cqq >> 3) * 256 + u0 + ((cqq & 7) << 2);
        *(float4*)&sW[k * 128 + cqq * 4] =
            *(const float4*)&lk[(size_t)(Dc + k) * ZC + zc];
    }

    // z mapping
    const int cq = tid & 31;
    const int bb = ((tid >> 5) & 1) * 8;
    const int k0 = (tid >> 6) * 32;
    const int kg = tid >> 6;

    // gate mapping
    const int gu = tid & 31;
    const int gb = tid >> 5;               // 0..15
    float c_reg = 0.f, h_reg = 0.f;
    const int sl = g_seqlen[b0 + gb];
    const size_t xzg = ((size_t)(b0 + gb) * Tc) * ZC + u0 + gu;
    const size_t og  = ((size_t)(b0 + gb) * Tc) * Hc + u0 + gu;
    float* const gh0 = &g_h[0][b0 + gb][u0 + gu];
    float* const gh1 = &g_h[1][b0 + gb][u0 + gu];

    // h staging mapping (512 threads x 8 floats = 16x256)
    const int sb   = tid >> 5;
    const int soff = (tid & 31) * 8;
    const float* const hs0 = &g_h[0][b0 + sb][soff];
    const float* const hs1 = &g_h[1][b0 + sb][soff];
    float* const hdst = &sH[sb * 256 + soff];

    for (int t = 0; t < Tc; t++) {
        // prefetch this thread's 4 gate xz values (consumed after k-loop)
        const size_t xb = xzg + (size_t)t * ZC;
        float xg0 = __ldcs(&g_xz[xb]);
        float xg1 = __ldcs(&g_xz[xb + 256]);
        float xg2 = __ldcs(&g_xz[xb + 512]);
        float xg3 = __ldcs(&g_xz[xb + 768]);

        // stage h(t-1) into SMEM
        if (t == 0) {
            *(float4*)hdst       = make_float4(0.f, 0.f, 0.f, 0.f);
            *(float4*)(hdst + 4) = make_float4(0.f, 0.f, 0.f, 0.f);
        } else {
            const float* hs = (t & 1) ? hs1 : hs0;
            float4 v0 = __ldcg((const float4*)hs);
            float4 v1 = __ldcg((const float4*)(hs + 4));
            *(float4*)hdst       = v0;
            *(float4*)(hdst + 4) = v1;
        }
        __syncthreads();

        // ---- partial z over 32 k values: 8 batches x 4 cols ----
        u64 acc[8][2];
        #pragma unroll
        for (int i = 0; i < 8; i++) { acc[i][0] = 0ull; acc[i][1] = 0ull; }

        #pragma unroll 2
        for (int kk4 = 0; kk4 < 32; kk4 += 4) {
            const int k = k0 + kk4;
            float4 hv[8];
            #pragma unroll
            for (int i = 0; i < 8; i++)
                hv[i] = *(const float4*)&sH[(bb + i) * 256 + k];
            #pragma unroll
            for (int kk = 0; kk < 4; kk++) {
                ulonglong2 w = *(const ulonglong2*)&sW[(k + kk) * 128 + cq * 4];
                #pragma unroll
                for (int i = 0; i < 8; i++) {
                    float h = (kk == 0) ? hv[i].x : (kk == 1) ? hv[i].y
                            : (kk == 2) ? hv[i].z : hv[i].w;
                    u64 hh = pack2(h, h);
                    fma2(acc[i][0], hh, w.x);
                    fma2(acc[i][1], hh, w.y);
                }
            }
        }
        #pragma unroll
        for (int i = 0; i < 8; i++) {
            ulonglong2 v;
            v.x = acc[i][0];
            v.y = acc[i][1];
            *(ulonglong2*)&sZp[((kg * 16) + bb + i) * 128 + cq * 4] = v;
        }
        __syncthreads();

        // ---- gates: reduce 8 K-partials + xz ----
        float zi = xg0, zj = xg1, zf = xg2, zo = xg3;
        #pragma unroll
        for (int p = 0; p < 8; p++) {
            const float* zp = &sZp[(p * 16 + gb) * 128];
            zi += zp[gu];
            zj += zp[32 + gu];
            zf += zp[64 + gu];
            zo += zp[96 + gu];
        }
        float cn = c_reg * sigm(zf + 1.f) + sigm(zi) * tanh_f(zj);
        float hn = tanh_f(cn) * sigm(zo);
        bool m = (t < sl);
        c_reg = m ? cn : c_reg;
        h_reg = m ? hn : h_reg;
        __stcs(&g_outs[og + (size_t)t * Hc], m ? hn : 0.f);
        __stcg(((t + 1) & 1) ? gh1 : gh0, h_reg);

        group_bar(ctr, (unsigned)(t + 1) * 8u);
    }
}

// ---------------- K3: attention scores (f32x2, k-blocked) -------------------
__global__ __launch_bounds__(128)
void k_vu(const float* __restrict__ w_om, const float* __restrict__ b_om,
          const float* __restrict__ u_om) {
    __shared__ float so[16][Hc];
    __shared__ float sred[16][4];

    const int tid = threadIdx.x;
    const size_t base = (size_t)blockIdx.x * 16;

    for (int i = tid; i < 16 * 64; i += 128) {
        int r = i >> 6, c = (i & 63) << 2;
        *(float4*)&so[r][c] = *(const float4*)&g_outs[(base + r) * Hc + c];
    }
    __syncthreads();

    u64 acc[8];
    #pragma unroll
    for (int r = 0; r < 8; r++) acc[r] = 0ull;

    for (int k = 0; k < Hc; k += 4) {
        float w0 = w_om[(k + 0) * Ac + tid];
        float w1 = w_om[(k + 1) * Ac + tid];
        float w2 = w_om[(k + 2) * Ac + tid];
        float w3 = w_om[(k + 3) * Ac + tid];
        u64 p0 = pack2(w0, w0), p1 = pack2(w1, w1);
        u64 p2 = pack2(w2, w2), p3 = pack2(w3, w3);
        #pragma unroll
        for (int r = 0; r < 8; r++) {
            float4 va = *(const float4*)&so[2 * r][k];
            float4 vb = *(const float4*)&so[2 * r + 1][k];
            fma2(acc[r], pack2(va.x, vb.x), p0);
            fma2(acc[r], pack2(va.y, vb.y), p1);
            fma2(acc[r], pack2(va.z, vb.z), p2);
            fma2(acc[r], pack2(va.w, vb.w), p3);
        }
    }

    const float bo = b_om[tid], uo = u_om[tid];
    float vr[16];
    #pragma unroll
    for (int r = 0; r < 8; r++) {
        float2 f = unpack2(acc[r]);
        vr[2 * r] = f.x;
        vr[2 * r + 1] = f.y;
    }
    #pragma unroll
    for (int r = 0; r < 16; r++) {
        float v = tanh_f(vr[r] + bo) * uo;
        #pragma unroll
        for (int o = 16; o; o >>= 1) v += __shfl_xor_sync(~0u, v, o);
        if ((tid & 31) == 0) sred[r][tid >> 5] = v;
    }
    __syncthreads();
    if (tid < 16)
        g_vu[base + tid] = sred[tid][0] + sred[tid][1] + sred[tid][2] + sred[tid][3];
}

// ---------------- block reductions -------------------------------------------
__device__ __forceinline__ float blk_sum(float v, float* sr, int tid) {
    #pragma unroll
    for (int o = 16; o; o >>= 1) v += __shfl_xor_sync(~0u, v, o);
    if ((tid & 31) == 0) sr[tid >> 5] = v;
    __syncthreads();
    if (tid < 32) {
        float x = (tid < 8) ? sr[tid] : 0.f;
        #pragma unroll
        for (int o = 4; o; o >>= 1) x += __shfl_xor_sync(~0u, x, o);
        if (tid == 0) sr[0] = x;
    }
    __syncthreads();
    float r = sr[0];
    __syncthreads();
    return r;
}
__device__ __forceinline__ float blk_max(float v, float* sr, int tid) {
    #pragma unroll
    for (int o = 16; o; o >>= 1) v = fmaxf(v, __shfl_xor_sync(~0u, v, o));
    if ((tid & 31) == 0) sr[tid >> 5] = v;
    __syncthreads();
    if (tid < 32) {
        float x = (tid < 8) ? sr[tid] : -INFINITY;
        #pragma unroll
        for (int o = 4; o; o >>= 1) x = fmaxf(x, __shfl_xor_sync(~0u, x, o));
        if (tid == 0) sr[0] = x;
    }
    __syncthreads();
    float r = sr[0];
    __syncthreads();
    return r;
}

// ---------------- K4: softmax over T, weighted sum, head ---------------------
__global__ __launch_bounds__(256)
void k_final(const float* __restrict__ w2, const float* __restrict__ b2,
             float* __restrict__ out) {
    __shared__ float sa[Tc];
    __shared__ float sr[32];

    const int b = blockIdx.x, tid = threadIdx.x;
    const float v0 = g_vu[b * Tc + tid];
    const float v1 = g_vu[b * Tc + 256 + tid];

    const float m = blk_max(fmaxf(v0, v1), sr, tid);
    const float e0 = expf(v0 - m), e1 = expf(v1 - m);
    sa[tid] = e0;
    sa[tid + 256] = e1;
    const float Z = blk_sum(e0 + e1, sr, tid);
    const float Zinv = 1.0f / Z;

    const float* op = g_outs + (size_t)b * Tc * Hc + tid;
    float acc = 0.f;
    #pragma unroll 4
    for (int t = 0; t < Tc; t++) acc = fmaf(__ldcs(&op[(size_t)t * Hc]), sa[t], acc);
    acc *= Zinv;

    const float l0 = blk_sum(acc * w2[tid * 2], sr, tid);
    const float l1 = blk_sum(acc * w2[tid * 2 + 1], sr, tid);

    if (tid == 0) {
        float a0 = l0 + b2[0], a1 = l1 + b2[1];
        float mm = fmaxf(a0, a1);
        float x0 = expf(a0 - mm), x1 = expf(a1 - mm);
        float s = 1.0f / (x0 + x1);
        out[b * 2 + 0] = x0 * s;
        out[b * 2 + 1] = x1 * s;
    }
}

// ---------------- launcher ----------------------------------------------------
extern "C" void kernel_launch(void* const* d_in, const int* in_sizes, int n_in,
                              void* d_out, int out_size) {
    const int*   x     = (const int*)  d_in[0];
    const float* embed = (const float*)d_in[1];
    const float* lk    = (const float*)d_in[2];
    const float* bias  = (const float*)d_in[3];
    const float* w_om  = (const float*)d_in[4];
    const float* b_om  = (const float*)d_in[5];
    const float* u_om  = (const float*)d_in[6];
    const float* w2    = (const float*)d_in[7];
    const float* b2    = (const float*)d_in[8];
    float* out = (float*)d_out;

    cudaFuncSetAttribute(k_lstm3, cudaFuncAttributeMaxDynamicSharedMemorySize,
                         SMEM_L3);

    k_seqlen<<<Bc, 256>>>(x);
    k_init<<<1, 512>>>();

    dim3 g1(ZC / 128, (Bc * Tc) / 128);
    k_xgemm<<<g1, 256>>>(x, embed, lk, bias);

    k_lstm3<<<NCTA_L, 512, SMEM_L3>>>(lk);

    k_vu<<<(Bc * Tc) / 16, 128>>>(w_om, b_om, u_om);

    k_final<<<Bc, 256>>>(w2, b2, out);
}

// round 8
// speedup vs baseline: 4.4222x; 1.0691x over previous
#include <cuda_runtime.h>
#include <cuda_bf16.h>
#include <stdint.h>
#include <math.h>

#define Bc 256
#define Tc 512
#define Dc 256
#define Hc 256
#define Ac 128
#define ZC 1024

#define NCTA_L 128
#define SMEM_L3 (128*1024 + 16*1024 + 64*1024)

// ---------------- scratch globals --------------------------------------------
__device__ float g_xz[(size_t)Bc * Tc * ZC];
__device__ float g_outs[(size_t)Bc * Tc * Hc];
__device__ float g_vu[Bc * Tc];
__device__ int   g_seqlen[Bc];
__device__ float g_h[2][Bc][Hc];
__device__ unsigned g_bar[16 * 32];
__device__ __nv_bfloat16 g_Bhi[1024 * 256];   // W_x^T hi, [n][k]
__device__ __nv_bfloat16 g_Blo[1024 * 256];   // W_x^T lo, [n][k]

typedef unsigned long long u64;

__device__ __forceinline__ u64 pack2(float lo, float hi) {
    u64 r;
    asm("mov.b64 %0, {%1, %2};" : "=l"(r) : "f"(lo), "f"(hi));
    return r;
}
__device__ __forceinline__ void fma2(u64& d, u64 a, u64 b) {
    asm("fma.rn.f32x2 %0, %1, %2, %0;" : "+l"(d) : "l"(a), "l"(b));
}
__device__ __forceinline__ float2 unpack2(u64 v) {
    float2 f;
    asm("mov.b64 {%0, %1}, %2;" : "=f"(f.x), "=f"(f.y) : "l"(v));
    return f;
}
__device__ __forceinline__ float sigm(float x) { return 1.0f / (1.0f + __expf(-x)); }
__device__ __forceinline__ float tanh_f(float x) {
    float ax = fabsf(x);
    float e = __expf(-2.0f * ax);
    float r = (1.0f - e) / (1.0f + e);
    return copysignf(r, x);
}
__device__ __forceinline__ uint32_t smem_u32(const void* p) {
    uint32_t a;
    asm("{ .reg .u64 t; cvta.to.shared.u64 t, %1; cvt.u32.u64 %0, t; }"
        : "=r"(a) : "l"(p));
    return a;
}

// ---------------- mma.sync helpers (sm_80+ PTX, compiles for sm_103) ----------
__device__ __forceinline__ void ldmx4(uint32_t* r, uint32_t addr) {
    asm volatile("ldmatrix.sync.aligned.m8n8.x4.shared.b16 {%0,%1,%2,%3}, [%4];"
                 : "=r"(r[0]), "=r"(r[1]), "=r"(r[2]), "=r"(r[3]) : "r"(addr));
}
__device__ __forceinline__ void mma16816(float* c, const uint32_t* a,
                                         uint32_t b0, uint32_t b1) {
    asm volatile(
        "mma.sync.aligned.m16n8k16.row.col.f32.bf16.bf16.f32 "
        "{%0,%1,%2,%3}, {%4,%5,%6,%7}, {%8,%9}, {%0,%1,%2,%3};"
        : "+f"(c[0]), "+f"(c[1]), "+f"(c[2]), "+f"(c[3])
        : "r"(a[0]), "r"(a[1]), "r"(a[2]), "r"(a[3]), "r"(b0), "r"(b1));
}

// ---------------- K0: seq_len --------------------------------------------------
__global__ void k_seqlen(const int* __restrict__ x) {
    const int b = blockIdx.x;
    const int tid = threadIdx.x;
    int c = (x[b * Tc + tid] != 0) + (x[b * Tc + 256 + tid] != 0);
    #pragma unroll
    for (int o = 16; o; o >>= 1) c += __shfl_xor_sync(~0u, c, o);
    __shared__ int s[8];
    if ((tid & 31) == 0) s[tid >> 5] = c;
    __syncthreads();
    if (tid == 0) {
        int t = 0;
        #pragma unroll
        for (int i = 0; i < 8; i++) t += s[i];
        g_seqlen[b] = t;
    }
}

__global__ void k_init() {
    if (threadIdx.x < 16 * 32) g_bar[threadIdx.x] = 0u;
}

// ---------------- K0b: W_x transpose + bf16 hi/lo split ------------------------
__global__ void k_wsplit(const float* __restrict__ lk) {
    __shared__ float s[32][33];
    const int kt = blockIdx.x * 32;
    const int nt = blockIdx.y * 32;
    const int tx = threadIdx.x;
    const int ty = threadIdx.y;
    #pragma unroll
    for (int i = 0; i < 4; i++) {
        s[ty + 8 * i][tx] = lk[(size_t)(kt + ty + 8 * i) * ZC + nt + tx];
    }
    __syncthreads();
    #pragma unroll
    for (int i = 0; i < 4; i++) {
        const int n = ty + 8 * i;
        float v = s[tx][n];
        __nv_bfloat16 h = __float2bfloat16(v);
        float lo = v - __bfloat162float(h);
        g_Bhi[(size_t)(nt + n) * 256 + kt + tx] = h;
        g_Blo[(size_t)(nt + n) * 256 + kt + tx] = __float2bfloat16(lo);
    }
}

// ---------------- K1: xz = embed[x] @ W_x + bias via mma.sync ------------------
// CTA tile 128x128, K=256 in 4 chunks of 64. 8 warps, warp tile 64x32.
// 3-term bf16 split: Ahi*Bhi + Alo*Bhi + Ahi*Blo. smem [row][k], stride 72.
#define AST 72                       // bf16 stride (144B row, conflict-free LDSM)
#define OFF_TOK  0
#define OFF_BIAS 512
#define OFF_AHI  1024
#define OFF_ALO  (OFF_AHI + 128*AST*2)
#define OFF_BHI  (OFF_ALO + 128*AST*2)
#define OFF_BLO  (OFF_BHI + 128*AST*2)
#define SMX_TOTAL (OFF_BLO + 128*AST*2)   // 74752 bytes

extern __shared__ char smx[];

__global__ __launch_bounds__(256, 2)
void k_xgemm_mma(const int* __restrict__ x, const float* __restrict__ embed,
                 const float* __restrict__ bias) {
    const uint32_t sb = smem_u32(smx);
    const int tid  = threadIdx.x;
    const int wid  = tid >> 5;
    const int lane = tid & 31;
    const int bn = blockIdx.x * 128;
    const int bm = blockIdx.y * 128;

    int*   stok  = (int*)(smx + OFF_TOK);
    float* sbias = (float*)(smx + OFF_BIAS);
    __nv_bfloat16* sAhi = (__nv_bfloat16*)(smx + OFF_AHI);
    __nv_bfloat16* sAlo = (__nv_bfloat16*)(smx + OFF_ALO);
    __nv_bfloat16* sBhi = (__nv_bfloat16*)(smx + OFF_BHI);
    __nv_bfloat16* sBlo = (__nv_bfloat16*)(smx + OFF_BLO);

    if (tid < 128) {
        stok[tid]  = x[bm + tid];
        sbias[tid] = bias[bn + tid];
    }
    __syncthreads();

    const int wm = (wid & 1) * 64;     // warp m offset
    const int wn = (wid >> 1) * 32;    // warp n offset

    float acc[4][4][4];
    #pragma unroll
    for (int mt = 0; mt < 4; mt++)
        #pragma unroll
        for (int nt = 0; nt < 4; nt++)
            #pragma unroll
            for (int i = 0; i < 4; i++) acc[mt][nt][i] = 0.f;

    // loader mapping (256 threads): row = tid>>1 (0..127), kh = (tid&1)*32
    const int lrow = tid >> 1;
    const int lkh  = (tid & 1) * 32;
    const float* arow_p = embed + (size_t)stok[lrow] * Dc;

    // ldmatrix per-thread address components
    const uint32_t a_row = (uint32_t)(wm + (lane & 15));
    const uint32_t a_kof = (uint32_t)((lane >> 4) * 8);
    const uint32_t b_row = (uint32_t)(wn + ((lane >> 4) & 1) * 8 + (lane & 7));
    const uint32_t b_kof = (uint32_t)(((lane >> 3) & 1) * 8);

    for (int ck = 0; ck < 4; ck++) {
        const int kbase = ck * 64;

        // ---- load A chunk: 128 rows x 64 k fp32 -> split hi/lo bf16 ----
        {
            const float* src = arow_p + kbase + lkh;
            #pragma unroll
            for (int i = 0; i < 8; i++) {
                float4 v = *(const float4*)(src + i * 4);
                __nv_bfloat162 h0 = __floats2bfloat162_rn(v.x, v.y);
                __nv_bfloat162 h1 = __floats2bfloat162_rn(v.z, v.w);
                __nv_bfloat162 l0 = __floats2bfloat162_rn(v.x - __bfloat162float(h0.x),
                                                          v.y - __bfloat162float(h0.y));
                __nv_bfloat162 l1 = __floats2bfloat162_rn(v.z - __bfloat162float(h1.x),
                                                          v.w - __bfloat162float(h1.y));
                const int off = lrow * AST + lkh + i * 4;
                uint2 ph; ph.x = *(uint32_t*)&h0; ph.y = *(uint32_t*)&h1;
                uint2 pl; pl.x = *(uint32_t*)&l0; pl.y = *(uint32_t*)&l1;
                *(uint2*)&sAhi[off] = ph;
                *(uint2*)&sAlo[off] = pl;
            }
        }
        // ---- load B chunk: 128 n-rows x 64 k bf16 (hi, lo) ----
        {
            const size_t src = (size_t)(bn + lrow) * 256 + kbase + lkh;
            #pragma unroll
            for (int i = 0; i < 4; i++) {
                uint4 vh = *(const uint4*)&g_Bhi[src + i * 8];
                uint4 vl = *(const uint4*)&g_Blo[src + i * 8];
                const int off = lrow * AST + lkh + i * 8;
                uint2 h0; h0.x = vh.x; h0.y = vh.y;
                uint2 h1; h1.x = vh.z; h1.y = vh.w;
                uint2 l0; l0.x = vl.x; l0.y = vl.y;
                uint2 l1; l1.x = vl.z; l1.y = vl.w;
                *(uint2*)&sBhi[off]     = h0;
                *(uint2*)&sBhi[off + 4] = h1;
                *(uint2*)&sBlo[off]     = l0;
                *(uint2*)&sBlo[off + 4] = l1;
            }
        }
        __syncthreads();

        // ---- 3 split terms x 4 k-steps of 16 ----
        #pragma unroll
        for (int term = 0; term < 3; term++) {
            const uint32_t abase = sb + (uint32_t)((term == 1) ? OFF_ALO : OFF_AHI);
            const uint32_t bbase = sb + (uint32_t)((term == 2) ? OFF_BLO : OFF_BHI);
            #pragma unroll
            for (int ks = 0; ks < 4; ks++) {
                uint32_t afr[4][4];
                #pragma unroll
                for (int mt = 0; mt < 4; mt++) {
                    uint32_t addr = abase +
                        ((a_row + mt * 16) * AST + ks * 16 + a_kof) * 2;
                    ldmx4(afr[mt], addr);
                }
                uint32_t bfr[2][4];
                #pragma unroll
                for (int np = 0; np < 2; np++) {
                    uint32_t addr = bbase +
                        ((b_row + np * 16) * AST + ks * 16 + b_kof) * 2;
                    ldmx4(bfr[np], addr);
                }
                #pragma unroll
                for (int mt = 0; mt < 4; mt++) {
                    #pragma unroll
                    for (int nt = 0; nt < 4; nt++) {
                        mma16816(acc[mt][nt], afr[mt],
                                 bfr[nt >> 1][(nt & 1) * 2],
                                 bfr[nt >> 1][(nt & 1) * 2 + 1]);
                    }
                }
            }
        }
        __syncthreads();
    }

    // ---- epilogue: + bias, direct stores ----
    #pragma unroll
    for (int mt = 0; mt < 4; mt++) {
        const int m0 = bm + wm + mt * 16 + (lane >> 2);
        #pragma unroll
        for (int nt = 0; nt < 4; nt++) {
            const int nl = wn + nt * 8 + (lane & 3) * 2;
            const float b0 = sbias[nl];
            const float b1 = sbias[nl + 1];
            float2 v0;
            float2 v1;
            v0.x = acc[mt][nt][0] + b0;
            v0.y = acc[mt][nt][1] + b1;
            v1.x = acc[mt][nt][2] + b0;
            v1.y = acc[mt][nt][3] + b1;
            __stcs((float2*)&g_xz[(size_t)m0 * ZC + bn + nl], v0);
            __stcs((float2*)&g_xz[(size_t)(m0 + 8) * ZC + bn + nl], v1);
        }
    }
}

// ---------------- per-batch-group barrier --------------------------------------
__device__ __forceinline__ void group_bar(unsigned* ctr, unsigned target) {
    __threadfence();
    __syncthreads();
    if (threadIdx.x == 0) {
        atomicAdd(ctr, 1u);
        unsigned v;
        do {
            asm volatile("ld.global.acquire.gpu.u32 %0, [%1];"
                         : "=r"(v) : "l"(ctr) : "memory");
        } while (v < target);
    }
    __syncthreads();
}

// ---------------- K2: LSTM (R4-passing version) --------------------------------
__global__ __launch_bounds__(512, 1)
void k_lstm3(const float* __restrict__ lk) {
    extern __shared__ float sm[];
    float* sW  = sm;
    float* sH  = sm + 256 * 128;
    float* sZp = sm + 256 * 128 + 16 * 256;

    const int tid = threadIdx.x;
    const int g  = blockIdx.x & 7;
    const int bg = blockIdx.x >> 3;
    const int u0 = g * 32;
    const int b0 = bg * 16;
    unsigned* const ctr = &g_bar[bg * 32];

    #pragma unroll 4
    for (int idx = tid; idx < 256 * 32; idx += 512) {
        int k = idx >> 5;
        int cqq = idx & 31;
        int zc = (cqq >> 3) * 256 + u0 + ((cqq & 7) << 2);
        *(float4*)&sW[k * 128 + cqq * 4] =
            *(const float4*)&lk[(size_t)(Dc + k) * ZC + zc];
    }

    const int cq = tid & 31;
    const int bb = ((tid >> 5) & 1) * 8;
    const int k0 = (tid >> 6) * 32;
    const int kg = tid >> 6;

    const int gu = tid & 31;
    const int gb = tid >> 5;
    float c_reg = 0.f;
    float h_reg = 0.f;
    const int slen = g_seqlen[b0 + gb];
    const size_t xzg = ((size_t)(b0 + gb) * Tc) * ZC + u0 + gu;
    const size_t og  = ((size_t)(b0 + gb) * Tc) * Hc + u0 + gu;
    float* const gh0 = &g_h[0][b0 + gb][u0 + gu];
    float* const gh1 = &g_h[1][b0 + gb][u0 + gu];

    const int sbi  = tid >> 5;
    const int soff = (tid & 31) * 8;
    const float* const hs0 = &g_h[0][b0 + sbi][soff];
    const float* const hs1 = &g_h[1][b0 + sbi][soff];
    float* const hdst = &sH[sbi * 256 + soff];

    for (int t = 0; t < Tc; t++) {
        const size_t xb = xzg + (size_t)t * ZC;
        float xg0 = __ldcs(&g_xz[xb]);
        float xg1 = __ldcs(&g_xz[xb + 256]);
        float xg2 = __ldcs(&g_xz[xb + 512]);
        float xg3 = __ldcs(&g_xz[xb + 768]);

        if (t == 0) {
            *(float4*)hdst       = make_float4(0.f, 0.f, 0.f, 0.f);
            *(float4*)(hdst + 4) = make_float4(0.f, 0.f, 0.f, 0.f);
        } else {
            const float* hs = (t & 1) ? hs1 : hs0;
            float4 v0 = __ldcg((const float4*)hs);
            float4 v1 = __ldcg((const float4*)(hs + 4));
            *(float4*)hdst       = v0;
            *(float4*)(hdst + 4) = v1;
        }
        __syncthreads();

        u64 acc[8][2];
        #pragma unroll
        for (int i = 0; i < 8; i++) {
            acc[i][0] = 0ull;
            acc[i][1] = 0ull;
        }

        #pragma unroll 2
        for (int kk4 = 0; kk4 < 32; kk4 += 4) {
            const int k = k0 + kk4;
            float4 hv[8];
            #pragma unroll
            for (int i = 0; i < 8; i++) {
                hv[i] = *(const float4*)&sH[(bb + i) * 256 + k];
            }
            #pragma unroll
            for (int kk = 0; kk < 4; kk++) {
                ulonglong2 w = *(const ulonglong2*)&sW[(k + kk) * 128 + cq * 4];
                #pragma unroll
                for (int i = 0; i < 8; i++) {
                    float h = (kk == 0) ? hv[i].x : (kk == 1) ? hv[i].y
                            : (kk == 2) ? hv[i].z : hv[i].w;
                    u64 hh = pack2(h, h);
                    fma2(acc[i][0], hh, w.x);
                    fma2(acc[i][1], hh, w.y);
                }
            }
        }
        #pragma unroll
        for (int i = 0; i < 8; i++) {
            ulonglong2 v;
            v.x = acc[i][0];
            v.y = acc[i][1];
            *(ulonglong2*)&sZp[((kg * 16) + bb + i) * 128 + cq * 4] = v;
        }
        __syncthreads();

        float zi = xg0;
        float zj = xg1;
        float zf = xg2;
        float zo = xg3;
        #pragma unroll
        for (int p = 0; p < 8; p++) {
            const float* zp = &sZp[(p * 16 + gb) * 128];
            zi += zp[gu];
            zj += zp[32 + gu];
            zf += zp[64 + gu];
            zo += zp[96 + gu];
        }
        float cn = c_reg * sigm(zf + 1.f) + sigm(zi) * tanh_f(zj);
        float hn = tanh_f(cn) * sigm(zo);
        bool m = (t < slen);
        c_reg = m ? cn : c_reg;
        h_reg = m ? hn : h_reg;
        __stcs(&g_outs[og + (size_t)t * Hc], m ? hn : 0.f);
        __stcg(((t + 1) & 1) ? gh1 : gh0, h_reg);

        group_bar(ctr, (unsigned)(t + 1) * 8u);
    }
}

// ---------------- K3: attention scores -----------------------------------------
__global__ __launch_bounds__(128)
void k_vu(const float* __restrict__ w_om, const float* __restrict__ b_om,
          const float* __restrict__ u_om) {
    __shared__ float so[16][Hc];
    __shared__ float sred[16][4];

    const int tid = threadIdx.x;
    const size_t base = (size_t)blockIdx.x * 16;

    for (int i = tid; i < 16 * 64; i += 128) {
        int r = i >> 6;
        int c = (i & 63) << 2;
        *(float4*)&so[r][c] = *(const float4*)&g_outs[(base + r) * Hc + c];
    }
    __syncthreads();

    u64 acc[8];
    #pragma unroll
    for (int r = 0; r < 8; r++) acc[r] = 0ull;

    for (int k = 0; k < Hc; k += 4) {
        float wa = w_om[(k + 0) * Ac + tid];
        float wb = w_om[(k + 1) * Ac + tid];
        float wc = w_om[(k + 2) * Ac + tid];
        float wd = w_om[(k + 3) * Ac + tid];
        u64 p0 = pack2(wa, wa);
        u64 p1 = pack2(wb, wb);
        u64 p2 = pack2(wc, wc);
        u64 p3 = pack2(wd, wd);
        #pragma unroll
        for (int r = 0; r < 8; r++) {
            float4 va = *(const float4*)&so[2 * r][k];
            float4 vb = *(const float4*)&so[2 * r + 1][k];
            fma2(acc[r], pack2(va.x, vb.x), p0);
            fma2(acc[r], pack2(va.y, vb.y), p1);
            fma2(acc[r], pack2(va.z, vb.z), p2);
            fma2(acc[r], pack2(va.w, vb.w), p3);
        }
    }

    const float bo = b_om[tid];
    const float uo = u_om[tid];
    float vr[16];
    #pragma unroll
    for (int r = 0; r < 8; r++) {
        float2 f = unpack2(acc[r]);
        vr[2 * r] = f.x;
        vr[2 * r + 1] = f.y;
    }
    #pragma unroll
    for (int r = 0; r < 16; r++) {
        float v = tanh_f(vr[r] + bo) * uo;
        #pragma unroll
        for (int o = 16; o; o >>= 1) v += __shfl_xor_sync(~0u, v, o);
        if ((tid & 31) == 0) sred[r][tid >> 5] = v;
    }
    __syncthreads();
    if (tid < 16) {
        g_vu[base + tid] = sred[tid][0] + sred[tid][1] + sred[tid][2] + sred[tid][3];
    }
}

// ---------------- block reductions ----------------------------------------------
__device__ __forceinline__ float blk_sum(float v, float* sr, int tid) {
    #pragma unroll
    for (int o = 16; o; o >>= 1) v += __shfl_xor_sync(~0u, v, o);
    if ((tid & 31) == 0) sr[tid >> 5] = v;
    __syncthreads();
    if (tid < 32) {
        float xx = (tid < 8) ? sr[tid] : 0.f;
        #pragma unroll
        for (int o = 4; o; o >>= 1) xx += __shfl_xor_sync(~0u, xx, o);
        if (tid == 0) sr[0] = xx;
    }
    __syncthreads();
    float r = sr[0];
    __syncthreads();
    return r;
}
__device__ __forceinline__ float blk_max(float v, float* sr, int tid) {
    #pragma unroll
    for (int o = 16; o; o >>= 1) v = fmaxf(v, __shfl_xor_sync(~0u, v, o));
    if ((tid & 31) == 0) sr[tid >> 5] = v;
    __syncthreads();
    if (tid < 32) {
        float xx = (tid < 8) ? sr[tid] : -INFINITY;
        #pragma unroll
        for (int o = 4; o; o >>= 1) xx = fmaxf(xx, __shfl_xor_sync(~0u, xx, o));
        if (tid == 0) sr[0] = xx;
    }
    __syncthreads();
    float r = sr[0];
    __syncthreads();
    return r;
}

// ---------------- K4: softmax over T, weighted sum, head ------------------------
__global__ __launch_bounds__(256)
void k_final(const float* __restrict__ w2, const float* __restrict__ b2,
             float* __restrict__ out) {
    __shared__ float sa[Tc];
    __shared__ float sr[32];

    const int b = blockIdx.x;
    const int tid = threadIdx.x;
    const float v0 = g_vu[b * Tc + tid];
    const float v1 = g_vu[b * Tc + 256 + tid];

    const float m = blk_max(fmaxf(v0, v1), sr, tid);
    const float e0 = expf(v0 - m);
    const float e1 = expf(v1 - m);
    sa[tid] = e0;
    sa[tid + 256] = e1;
    const float Z = blk_sum(e0 + e1, sr, tid);
    const float Zinv = 1.0f / Z;

    const float* op = g_outs + (size_t)b * Tc * Hc + tid;
    float acc = 0.f;
    #pragma unroll 4
    for (int t = 0; t < Tc; t++) {
        acc = fmaf(__ldcs(&op[(size_t)t * Hc]), sa[t], acc);
    }
    acc *= Zinv;

    const float l0 = blk_sum(acc * w2[tid * 2], sr, tid);
    const float l1 = blk_sum(acc * w2[tid * 2 + 1], sr, tid);

    if (tid == 0) {
        float a0 = l0 + b2[0];
        float a1 = l1 + b2[1];
        float mm = fmaxf(a0, a1);
        float x0 = expf(a0 - mm);
        float x1 = expf(a1 - mm);
        float s = 1.0f / (x0 + x1);
        out[b * 2 + 0] = x0 * s;
        out[b * 2 + 1] = x1 * s;
    }
}

// ---------------- launcher -------------------------------------------------------
extern "C" void kernel_launch(void* const* d_in, const int* in_sizes, int n_in,
                              void* d_out, int out_size) {
    const int*   x     = (const int*)  d_in[0];
    const float* embed = (const float*)d_in[1];
    const float* lk    = (const float*)d_in[2];
    const float* bias  = (const float*)d_in[3];
    const float* w_om  = (const float*)d_in[4];
    const float* b_om  = (const float*)d_in[5];
    const float* u_om  = (const float*)d_in[6];
    const float* w2    = (const float*)d_in[7];
    const float* b2    = (const float*)d_in[8];
    float* out = (float*)d_out;

    cudaFuncSetAttribute(k_lstm3, cudaFuncAttributeMaxDynamicSharedMemorySize,
                         SMEM_L3);
    cudaFuncSetAttribute(k_xgemm_mma, cudaFuncAttributeMaxDynamicSharedMemorySize,
                         SMX_TOTAL);

    k_seqlen<<<Bc, 256>>>(x);
    k_init<<<1, 512>>>();

    dim3 gw(8, 32);
    dim3 bw(32, 8);
    k_wsplit<<<gw, bw>>>(lk);

    dim3 g1(ZC / 128, (Bc * Tc) / 128);
    k_xgemm_mma<<<g1, 256, SMX_TOTAL>>>(x, embed, bias);

    k_lstm3<<<NCTA_L, 512, SMEM_L3>>>(lk);

    k_vu<<<(Bc * Tc) / 16, 128>>>(w_om, b_om, u_om);

    k_final<<<Bc, 256>>>(w2, b2, out);
}

// round 9
// speedup vs baseline: 5.5264x; 1.2497x over previous
#include <cuda_runtime.h>
#include <cuda_bf16.h>
#include <stdint.h>
#include <math.h>

#define Bc 256
#define Tc 512
#define Dc 256
#define Hc 256
#define Ac 128
#define ZC 1024

#define NCTA_L 128

// ---------------- scratch globals --------------------------------------------
__device__ float g_xz[(size_t)Bc * Tc * ZC];
__device__ float g_outs[(size_t)Bc * Tc * Hc];
__device__ float g_vu[Bc * Tc];
__device__ int   g_seqlen[Bc];
__device__ float g_h[2][Bc][Hc];
__device__ unsigned g_bar[16 * 32];
__device__ __nv_bfloat16 g_Bhi[1024 * 256];   // W_x^T hi, [n][k]
__device__ __nv_bfloat16 g_Blo[1024 * 256];   // W_x^T lo, [n][k]
__device__ __nv_bfloat16 g_Whhi[1024 * 256];  // W_h^T hi, [n][k]
__device__ __nv_bfloat16 g_Whlo[1024 * 256];  // W_h^T lo, [n][k]

typedef unsigned long long u64;

__device__ __forceinline__ u64 pack2(float lo, float hi) {
    u64 r;
    asm("mov.b64 %0, {%1, %2};" : "=l"(r) : "f"(lo), "f"(hi));
    return r;
}
__device__ __forceinline__ void fma2(u64& d, u64 a, u64 b) {
    asm("fma.rn.f32x2 %0, %1, %2, %0;" : "+l"(d) : "l"(a), "l"(b));
}
__device__ __forceinline__ float2 unpack2(u64 v) {
    float2 f;
    asm("mov.b64 {%0, %1}, %2;" : "=f"(f.x), "=f"(f.y) : "l"(v));
    return f;
}
__device__ __forceinline__ float sigm(float x) { return 1.0f / (1.0f + __expf(-x)); }
__device__ __forceinline__ float tanh_f(float x) {
    float ax = fabsf(x);
    float e = __expf(-2.0f * ax);
    float r = (1.0f - e) / (1.0f + e);
    return copysignf(r, x);
}
__device__ __forceinline__ uint32_t smem_u32(const void* p) {
    uint32_t a;
    asm("{ .reg .u64 t; cvta.to.shared.u64 t, %1; cvt.u32.u64 %0, t; }"
        : "=r"(a) : "l"(p));
    return a;
}

// ---------------- mma.sync helpers --------------------------------------------
__device__ __forceinline__ void ldmx4(uint32_t* r, uint32_t addr) {
    asm volatile("ldmatrix.sync.aligned.m8n8.x4.shared.b16 {%0,%1,%2,%3}, [%4];"
                 : "=r"(r[0]), "=r"(r[1]), "=r"(r[2]), "=r"(r[3]) : "r"(addr));
}
__device__ __forceinline__ void mma16816(float* c, const uint32_t* a,
                                         uint32_t b0, uint32_t b1) {
    asm volatile(
        "mma.sync.aligned.m16n8k16.row.col.f32.bf16.bf16.f32 "
        "{%0,%1,%2,%3}, {%4,%5,%6,%7}, {%8,%9}, {%0,%1,%2,%3};"
        : "+f"(c[0]), "+f"(c[1]), "+f"(c[2]), "+f"(c[3])
        : "r"(a[0]), "r"(a[1]), "r"(a[2]), "r"(a[3]), "r"(b0), "r"(b1));
}

// ---------------- K0: seq_len --------------------------------------------------
__global__ void k_seqlen(const int* __restrict__ x) {
    const int b = blockIdx.x;
    const int tid = threadIdx.x;
    int c = (x[b * Tc + tid] != 0) + (x[b * Tc + 256 + tid] != 0);
    #pragma unroll
    for (int o = 16; o; o >>= 1) c += __shfl_xor_sync(~0u, c, o);
    __shared__ int s[8];
    if ((tid & 31) == 0) s[tid >> 5] = c;
    __syncthreads();
    if (tid == 0) {
        int t = 0;
        #pragma unroll
        for (int i = 0; i < 8; i++) t += s[i];
        g_seqlen[b] = t;
    }
}

__global__ void k_init() {
    if (threadIdx.x < 16 * 32) g_bar[threadIdx.x] = 0u;
}

// ---------------- K0b: W transpose + bf16 hi/lo split --------------------------
// which=0: rows 0..255 of lk (W_x) -> g_Bhi/g_Blo
// which=1: rows 256..511 of lk (W_h) -> g_Whhi/g_Whlo
__global__ void k_wsplit(const float* __restrict__ lk, int koff, int which) {
    __shared__ float s[32][33];
    const int kt = blockIdx.x * 32;
    const int nt = blockIdx.y * 32;
    const int tx = threadIdx.x;
    const int ty = threadIdx.y;
    #pragma unroll
    for (int i = 0; i < 4; i++) {
        s[ty + 8 * i][tx] = lk[(size_t)(koff + kt + ty + 8 * i) * ZC + nt + tx];
    }
    __syncthreads();
    __nv_bfloat16* dhi = which ? g_Whhi : g_Bhi;
    __nv_bfloat16* dlo = which ? g_Whlo : g_Blo;
    #pragma unroll
    for (int i = 0; i < 4; i++) {
        const int n = ty + 8 * i;
        float v = s[tx][n];
        __nv_bfloat16 h = __float2bfloat16(v);
        float lo = v - __bfloat162float(h);
        dhi[(size_t)(nt + n) * 256 + kt + tx] = h;
        dlo[(size_t)(nt + n) * 256 + kt + tx] = __float2bfloat16(lo);
    }
}

// ---------------- K1: xz = embed[x] @ W_x + bias via mma.sync (R8, unchanged) --
#define AST 72
#define OFF_TOK  0
#define OFF_BIAS 512
#define OFF_AHI  1024
#define OFF_ALO  (OFF_AHI + 128*AST*2)
#define OFF_BHI  (OFF_ALO + 128*AST*2)
#define OFF_BLO  (OFF_BHI + 128*AST*2)
#define SMX_TOTAL (OFF_BLO + 128*AST*2)

extern __shared__ char smx[];

__global__ __launch_bounds__(256, 2)
void k_xgemm_mma(const int* __restrict__ x, const float* __restrict__ embed,
                 const float* __restrict__ bias) {
    const uint32_t sb = smem_u32(smx);
    const int tid  = threadIdx.x;
    const int wid  = tid >> 5;
    const int lane = tid & 31;
    const int bn = blockIdx.x * 128;
    const int bm = blockIdx.y * 128;

    int*   stok  = (int*)(smx + OFF_TOK);
    float* sbias = (float*)(smx + OFF_BIAS);
    __nv_bfloat16* sAhi = (__nv_bfloat16*)(smx + OFF_AHI);
    __nv_bfloat16* sAlo = (__nv_bfloat16*)(smx + OFF_ALO);
    __nv_bfloat16* sBhi = (__nv_bfloat16*)(smx + OFF_BHI);
    __nv_bfloat16* sBlo = (__nv_bfloat16*)(smx + OFF_BLO);

    if (tid < 128) {
        stok[tid]  = x[bm + tid];
        sbias[tid] = bias[bn + tid];
    }
    __syncthreads();

    const int wm = (wid & 1) * 64;
    const int wn = (wid >> 1) * 32;

    float acc[4][4][4];
    #pragma unroll
    for (int mt = 0; mt < 4; mt++)
        #pragma unroll
        for (int nt = 0; nt < 4; nt++)
            #pragma unroll
            for (int i = 0; i < 4; i++) acc[mt][nt][i] = 0.f;

    const int lrow = tid >> 1;
    const int lkh  = (tid & 1) * 32;
    const float* arow_p = embed + (size_t)stok[lrow] * Dc;

    const uint32_t a_row = (uint32_t)(wm + (lane & 15));
    const uint32_t a_kof = (uint32_t)((lane >> 4) * 8);
    const uint32_t b_row = (uint32_t)(wn + ((lane >> 4) & 1) * 8 + (lane & 7));
    const uint32_t b_kof = (uint32_t)(((lane >> 3) & 1) * 8);

    for (int ck = 0; ck < 4; ck++) {
        const int kbase = ck * 64;
        {
            const float* src = arow_p + kbase + lkh;
            #pragma unroll
            for (int i = 0; i < 8; i++) {
                float4 v = *(const float4*)(src + i * 4);
                __nv_bfloat162 h0 = __floats2bfloat162_rn(v.x, v.y);
                __nv_bfloat162 h1 = __floats2bfloat162_rn(v.z, v.w);
                __nv_bfloat162 l0 = __floats2bfloat162_rn(v.x - __bfloat162float(h0.x),
                                                          v.y - __bfloat162float(h0.y));
                __nv_bfloat162 l1 = __floats2bfloat162_rn(v.z - __bfloat162float(h1.x),
                                                          v.w - __bfloat162float(h1.y));
                const int off = lrow * AST + lkh + i * 4;
                uint2 ph; ph.x = *(uint32_t*)&h0; ph.y = *(uint32_t*)&h1;
                uint2 pl; pl.x = *(uint32_t*)&l0; pl.y = *(uint32_t*)&l1;
                *(uint2*)&sAhi[off] = ph;
                *(uint2*)&sAlo[off] = pl;
            }
        }
        {
            const size_t src = (size_t)(bn + lrow) * 256 + kbase + lkh;
            #pragma unroll
            for (int i = 0; i < 4; i++) {
                uint4 vh = *(const uint4*)&g_Bhi[src + i * 8];
                uint4 vl = *(const uint4*)&g_Blo[src + i * 8];
                const int off = lrow * AST + lkh + i * 8;
                uint2 h0; h0.x = vh.x; h0.y = vh.y;
                uint2 h1; h1.x = vh.z; h1.y = vh.w;
                uint2 l0; l0.x = vl.x; l0.y = vl.y;
                uint2 l1; l1.x = vl.z; l1.y = vl.w;
                *(uint2*)&sBhi[off]     = h0;
                *(uint2*)&sBhi[off + 4] = h1;
                *(uint2*)&sBlo[off]     = l0;
                *(uint2*)&sBlo[off + 4] = l1;
            }
        }
        __syncthreads();

        #pragma unroll
        for (int term = 0; term < 3; term++) {
            const uint32_t abase = sb + (uint32_t)((term == 1) ? OFF_ALO : OFF_AHI);
            const uint32_t bbase = sb + (uint32_t)((term == 2) ? OFF_BLO : OFF_BHI);
            #pragma unroll
            for (int ks = 0; ks < 4; ks++) {
                uint32_t afr[4][4];
                #pragma unroll
                for (int mt = 0; mt < 4; mt++) {
                    uint32_t addr = abase +
                        ((a_row + mt * 16) * AST + ks * 16 + a_kof) * 2;
                    ldmx4(afr[mt], addr);
                }
                uint32_t bfr[2][4];
                #pragma unroll
                for (int np = 0; np < 2; np++) {
                    uint32_t addr = bbase +
                        ((b_row + np * 16) * AST + ks * 16 + b_kof) * 2;
                    ldmx4(bfr[np], addr);
                }
                #pragma unroll
                for (int mt = 0; mt < 4; mt++) {
                    #pragma unroll
                    for (int nt = 0; nt < 4; nt++) {
                        mma16816(acc[mt][nt], afr[mt],
                                 bfr[nt >> 1][(nt & 1) * 2],
                                 bfr[nt >> 1][(nt & 1) * 2 + 1]);
                    }
                }
            }
        }
        __syncthreads();
    }

    #pragma unroll
    for (int mt = 0; mt < 4; mt++) {
        const int m0 = bm + wm + mt * 16 + (lane >> 2);
        #pragma unroll
        for (int nt = 0; nt < 4; nt++) {
            const int nl = wn + nt * 8 + (lane & 3) * 2;
            const float b0 = sbias[nl];
            const float b1 = sbias[nl + 1];
            float2 v0;
            float2 v1;
            v0.x = acc[mt][nt][0] + b0;
            v0.y = acc[mt][nt][1] + b1;
            v1.x = acc[mt][nt][2] + b0;
            v1.y = acc[mt][nt][3] + b1;
            __stcs((float2*)&g_xz[(size_t)m0 * ZC + bn + nl], v0);
            __stcs((float2*)&g_xz[(size_t)(m0 + 8) * ZC + bn + nl], v1);
        }
    }
}

// ---------------- per-batch-group barrier --------------------------------------
__device__ __forceinline__ void group_bar(unsigned* ctr, unsigned target) {
    __threadfence();
    __syncthreads();
    if (threadIdx.x == 0) {
        atomicAdd(ctr, 1u);
        unsigned v;
        do {
            asm volatile("ld.global.acquire.gpu.u32 %0, [%1];"
                         : "=r"(v) : "l"(ctr) : "memory");
        } while (v < target);
    }
    __syncthreads();
}

// ---------------- K2: LSTM via mma.sync -----------------------------------------
// 128 CTAs: g = column group (32 units = 128 z-cols), bg = batch group (16).
// W_h slice (bf16 hi/lo, ldmatrix layout, stride 264) resident in SMEM.
// Per step: h (16x256) -> bf16 hi/lo; 16 warps = 8 k-groups x 2 n-halves;
// 3-term split HMMA; partials reduced via sZp; gates; h exchange + group bar.
#define WST 264              // bf16 row stride (528B = 4-bank shift, LDSM clean)
#define ZST 136              // fp32 partials row stride
#define L4_WHI 0
#define L4_WLO 67584
#define L4_HHI 135168
#define L4_HLO 143616
#define L4_ZP  152064
#define SMEM_L4 221696

__global__ __launch_bounds__(512, 1)
void k_lstm4() {
    extern __shared__ char sml[];
    __nv_bfloat16* sWhi = (__nv_bfloat16*)(sml + L4_WHI);
    __nv_bfloat16* sWlo = (__nv_bfloat16*)(sml + L4_WLO);
    __nv_bfloat16* sHhi = (__nv_bfloat16*)(sml + L4_HHI);
    __nv_bfloat16* sHlo = (__nv_bfloat16*)(sml + L4_HLO);
    float* sZp = (float*)(sml + L4_ZP);
    const uint32_t sbase = smem_u32(sml);

    const int tid = threadIdx.x;
    const int g  = blockIdx.x & 7;
    const int bg = blockIdx.x >> 3;
    const int u0 = g * 32;
    const int b0 = bg * 16;
    unsigned* const ctr = &g_bar[bg * 32];

    // ---- W_h slice -> SMEM (once): local n -> global z col ----
    {
        const int n = tid >> 2;
        const int c = tid & 3;
        const int gcol = (n >> 5) * 256 + u0 + (n & 31);
        const size_t src = (size_t)gcol * 256 + c * 64;
        const int dst = n * WST + c * 64;
        #pragma unroll
        for (int i = 0; i < 8; i++) {
            *(uint4*)&sWhi[dst + i * 8] = *(const uint4*)&g_Whhi[src + i * 8];
            *(uint4*)&sWlo[dst + i * 8] = *(const uint4*)&g_Whlo[src + i * 8];
        }
    }

    const int wid  = tid >> 5;
    const int lane = tid & 31;
    const int nh = wid & 1;        // n-half (64 cols)
    const int kg = wid >> 1;       // k-group (32 k)
    const int n0 = nh * 64;
    const int k0 = kg * 32;

    // ldmatrix byte-address bases
    const uint32_t a_part = (uint32_t)((lane & 15) * WST + (lane >> 4) * 8) * 2;
    const uint32_t aoff_hi = sbase + L4_HHI + a_part;
    const uint32_t aoff_lo = sbase + L4_HLO + a_part;
    const uint32_t brow = (uint32_t)(n0 + ((lane >> 4) & 1) * 8 + (lane & 7));
    const uint32_t bk   = (uint32_t)(((lane >> 3) & 1) * 8);
    const uint32_t b_part = (brow * WST + bk) * 2;
    const uint32_t boff_hi = sbase + L4_WHI + b_part;
    const uint32_t boff_lo = sbase + L4_WLO + b_part;

    // gate mapping (512 threads: 16 batches x 32 units)
    const int gu = lane;
    const int gb = wid;
    float c_reg = 0.f;
    float h_reg = 0.f;
    const int slen = g_seqlen[b0 + gb];
    const size_t xzg = ((size_t)(b0 + gb) * Tc) * ZC + u0 + gu;
    const size_t og  = ((size_t)(b0 + gb) * Tc) * Hc + u0 + gu;
    float* const gh0 = &g_h[0][b0 + gb][u0 + gu];
    float* const gh1 = &g_h[1][b0 + gb][u0 + gu];

    // staging mapping: 512 threads x 8 floats = 16x256
    const int srow = tid >> 5;
    const int skof = (lane) * 8;
    const float* const hsrc0 = &g_h[0][b0 + srow][skof];
    const float* const hsrc1 = &g_h[1][b0 + srow][skof];
    const int hdst = srow * WST + skof;

    for (int t = 0; t < Tc; t++) {
        // gate xz prefetch (consumed after MMA)
        const size_t xb = xzg + (size_t)t * ZC;
        float xg0 = __ldcs(&g_xz[xb]);
        float xg1 = __ldcs(&g_xz[xb + 256]);
        float xg2 = __ldcs(&g_xz[xb + 512]);
        float xg3 = __ldcs(&g_xz[xb + 768]);

        // stage h(t-1) -> bf16 hi/lo
        if (t == 0) {
            uint4 z4 = make_uint4(0u, 0u, 0u, 0u);
            *(uint4*)&sHhi[hdst] = z4;
            *(uint4*)&sHlo[hdst] = z4;
        } else {
            const float* hs = (t & 1) ? hsrc1 : hsrc0;
            float4 v0 = __ldcg((const float4*)hs);
            float4 v1 = __ldcg((const float4*)(hs + 4));
            __nv_bfloat162 h0 = __floats2bfloat162_rn(v0.x, v0.y);
            __nv_bfloat162 h1 = __floats2bfloat162_rn(v0.z, v0.w);
            __nv_bfloat162 h2 = __floats2bfloat162_rn(v1.x, v1.y);
            __nv_bfloat162 h3 = __floats2bfloat162_rn(v1.z, v1.w);
            __nv_bfloat162 l0 = __floats2bfloat162_rn(v0.x - __bfloat162float(h0.x),
                                                      v0.y - __bfloat162float(h0.y));
            __nv_bfloat162 l1 = __floats2bfloat162_rn(v0.z - __bfloat162float(h1.x),
                                                      v0.w - __bfloat162float(h1.y));
            __nv_bfloat162 l2 = __floats2bfloat162_rn(v1.x - __bfloat162float(h2.x),
                                                      v1.y - __bfloat162float(h2.y));
            __nv_bfloat162 l3 = __floats2bfloat162_rn(v1.z - __bfloat162float(h3.x),
                                                      v1.w - __bfloat162float(h3.y));
            uint4 ph;
            ph.x = *(uint32_t*)&h0; ph.y = *(uint32_t*)&h1;
            ph.z = *(uint32_t*)&h2; ph.w = *(uint32_t*)&h3;
            uint4 pl;
            pl.x = *(uint32_t*)&l0; pl.y = *(uint32_t*)&l1;
            pl.z = *(uint32_t*)&l2; pl.w = *(uint32_t*)&l3;
            *(uint4*)&sHhi[hdst] = ph;
            *(uint4*)&sHlo[hdst] = pl;
        }
        __syncthreads();

        // ---- z partial: 16 m x 64 n x 32 k, 3 split terms ----
        float acc[8][4];
        #pragma unroll
        for (int nt = 0; nt < 8; nt++)
            #pragma unroll
            for (int i = 0; i < 4; i++) acc[nt][i] = 0.f;

        #pragma unroll
        for (int ks = 0; ks < 2; ks++) {
            const uint32_t kb = (uint32_t)((k0 + ks * 16) * 2);
            uint32_t ahi[4], alo[4];
            ldmx4(ahi, aoff_hi + kb);
            ldmx4(alo, aoff_lo + kb);
            #pragma unroll
            for (int p = 0; p < 4; p++) {
                const uint32_t pb = (uint32_t)(p * 16 * WST * 2) + kb;
                uint32_t bhi[4], blo[4];
                ldmx4(bhi, boff_hi + pb);
                ldmx4(blo, boff_lo + pb);
                mma16816(acc[2 * p],     ahi, bhi[0], bhi[1]);
                mma16816(acc[2 * p + 1], ahi, bhi[2], bhi[3]);
                mma16816(acc[2 * p],     alo, bhi[0], bhi[1]);
                mma16816(acc[2 * p + 1], alo, bhi[2], bhi[3]);
                mma16816(acc[2 * p],     ahi, blo[0], blo[1]);
                mma16816(acc[2 * p + 1], ahi, blo[2], blo[3]);
            }
        }

        // ---- store partials ----
        {
            const int m  = lane >> 2;
            const int cb = (lane & 3) * 2;
            #pragma unroll
            for (int nt = 0; nt < 8; nt++) {
                const int col = n0 + nt * 8 + cb;
                *(float2*)&sZp[(kg * 16 + m) * ZST + col] =
                    make_float2(acc[nt][0], acc[nt][1]);
                *(float2*)&sZp[(kg * 16 + m + 8) * ZST + col] =
                    make_float2(acc[nt][2], acc[nt][3]);
            }
        }
        __syncthreads();

        // ---- gates: reduce 8 k-partials + xz ----
        float zi = xg0;
        float zj = xg1;
        float zf = xg2;
        float zo = xg3;
        #pragma unroll
        for (int p = 0; p < 8; p++) {
            const float* zp = &sZp[(p * 16 + gb) * ZST];
            zi += zp[gu];
            zj += zp[32 + gu];
            zf += zp[64 + gu];
            zo += zp[96 + gu];
        }
        float cn = c_reg * sigm(zf + 1.f) + sigm(zi) * tanh_f(zj);
        float hn = tanh_f(cn) * sigm(zo);
        bool m = (t < slen);
        c_reg = m ? cn : c_reg;
        h_reg = m ? hn : h_reg;
        __stcs(&g_outs[og + (size_t)t * Hc], m ? hn : 0.f);
        __stcg(((t + 1) & 1) ? gh1 : gh0, h_reg);

        group_bar(ctr, (unsigned)(t + 1) * 8u);
    }
}

// ---------------- K3: attention scores -----------------------------------------
__global__ __launch_bounds__(128)
void k_vu(const float* __restrict__ w_om, const float* __restrict__ b_om,
          const float* __restrict__ u_om) {
    __shared__ float so[16][Hc];
    __shared__ float sred[16][4];

    const int tid = threadIdx.x;
    const size_t base = (size_t)blockIdx.x * 16;

    for (int i = tid; i < 16 * 64; i += 128) {
        int r = i >> 6;
        int c = (i & 63) << 2;
        *(float4*)&so[r][c] = *(const float4*)&g_outs[(base + r) * Hc + c];
    }
    __syncthreads();

    u64 acc[8];
    #pragma unroll
    for (int r = 0; r < 8; r++) acc[r] = 0ull;

    for (int k = 0; k < Hc; k += 4) {
        float wa = w_om[(k + 0) * Ac + tid];
        float wb = w_om[(k + 1) * Ac + tid];
        float wc = w_om[(k + 2) * Ac + tid];
        float wd = w_om[(k + 3) * Ac + tid];
        u64 p0 = pack2(wa, wa);
        u64 p1 = pack2(wb, wb);
        u64 p2 = pack2(wc, wc);
        u64 p3 = pack2(wd, wd);
        #pragma unroll
        for (int r = 0; r < 8; r++) {
            float4 va = *(const float4*)&so[2 * r][k];
            float4 vb = *(const float4*)&so[2 * r + 1][k];
            fma2(acc[r], pack2(va.x, vb.x), p0);
            fma2(acc[r], pack2(va.y, vb.y), p1);
            fma2(acc[r], pack2(va.z, vb.z), p2);
            fma2(acc[r], pack2(va.w, vb.w), p3);
        }
    }

    const float bo = b_om[tid];
    const float uo = u_om[tid];
    float vr[16];
    #pragma unroll
    for (int r = 0; r < 8; r++) {
        float2 f = unpack2(acc[r]);
        vr[2 * r] = f.x;
        vr[2 * r + 1] = f.y;
    }
    #pragma unroll
    for (int r = 0; r < 16; r++) {
        float v = tanh_f(vr[r] + bo) * uo;
        #pragma unroll
        for (int o = 16; o; o >>= 1) v += __shfl_xor_sync(~0u, v, o);
        if ((tid & 31) == 0) sred[r][tid >> 5] = v;
    }
    __syncthreads();
    if (tid < 16) {
        g_vu[base + tid] = sred[tid][0] + sred[tid][1] + sred[tid][2] + sred[tid][3];
    }
}

// ---------------- block reductions ----------------------------------------------
__device__ __forceinline__ float blk_sum(float v, float* sr, int tid) {
    #pragma unroll
    for (int o = 16; o; o >>= 1) v += __shfl_xor_sync(~0u, v, o);
    if ((tid & 31) == 0) sr[tid >> 5] = v;
    __syncthreads();
    if (tid < 32) {
        float xx = (tid < 8) ? sr[tid] : 0.f;
        #pragma unroll
        for (int o = 4; o; o >>= 1) xx += __shfl_xor_sync(~0u, xx, o);
        if (tid == 0) sr[0] = xx;
    }
    __syncthreads();
    float r = sr[0];
    __syncthreads();
    return r;
}
__device__ __forceinline__ float blk_max(float v, float* sr, int tid) {
    #pragma unroll
    for (int o = 16; o; o >>= 1) v = fmaxf(v, __shfl_xor_sync(~0u, v, o));
    if ((tid & 31) == 0) sr[tid >> 5] = v;
    __syncthreads();
    if (tid < 32) {
        float xx = (tid < 8) ? sr[tid] : -INFINITY;
        #pragma unroll
        for (int o = 4; o; o >>= 1) xx = fmaxf(xx, __shfl_xor_sync(~0u, xx, o));
        if (tid == 0) sr[0] = xx;
    }
    __syncthreads();
    float r = sr[0];
    __syncthreads();
    return r;
}

// ---------------- K4: softmax over T, weighted sum, head ------------------------
__global__ __launch_bounds__(256)
void k_final(const float* __restrict__ w2, const float* __restrict__ b2,
             float* __restrict__ out) {
    __shared__ float sa[Tc];
    __shared__ float sr[32];

    const int b = blockIdx.x;
    const int tid = threadIdx.x;
    const float v0 = g_vu[b * Tc + tid];
    const float v1 = g_vu[b * Tc + 256 + tid];

    const float m = blk_max(fmaxf(v0, v1), sr, tid);
    const float e0 = expf(v0 - m);
    const float e1 = expf(v1 - m);
    sa[tid] = e0;
    sa[tid + 256] = e1;
    const float Z = blk_sum(e0 + e1, sr, tid);
    const float Zinv = 1.0f / Z;

    const float* op = g_outs + (size_t)b * Tc * Hc + tid;
    float acc = 0.f;
    #pragma unroll 4
    for (int t = 0; t < Tc; t++) {
        acc = fmaf(__ldcs(&op[(size_t)t * Hc]), sa[t], acc);
    }
    acc *= Zinv;

    const float l0 = blk_sum(acc * w2[tid * 2], sr, tid);
    const float l1 = blk_sum(acc * w2[tid * 2 + 1], sr, tid);

    if (tid == 0) {
        float a0 = l0 + b2[0];
        float a1 = l1 + b2[1];
        float mm = fmaxf(a0, a1);
        float x0 = expf(a0 - mm);
        float x1 = expf(a1 - mm);
        float s = 1.0f / (x0 + x1);
        out[b * 2 + 0] = x0 * s;
        out[b * 2 + 1] = x1 * s;
    }
}

// ---------------- launcher -------------------------------------------------------
extern "C" void kernel_launch(void* const* d_in, const int* in_sizes, int n_in,
                              void* d_out, int out_size) {
    const int*   x     = (const int*)  d_in[0];
    const float* embed = (const float*)d_in[1];
    const float* lk    = (const float*)d_in[2];
    const float* bias  = (const float*)d_in[3];
    const float* w_om  = (const float*)d_in[4];
    const float* b_om  = (const float*)d_in[5];
    const float* u_om  = (const float*)d_in[6];
    const float* w2    = (const float*)d_in[7];
    const float* b2    = (const float*)d_in[8];
    float* out = (float*)d_out;

    cudaFuncSetAttribute(k_xgemm_mma, cudaFuncAttributeMaxDynamicSharedMemorySize,
                         SMX_TOTAL);
    cudaFuncSetAttribute(k_lstm4, cudaFuncAttributeMaxDynamicSharedMemorySize,
                         SMEM_L4);

    k_seqlen<<<Bc, 256>>>(x);
    k_init<<<1, 512>>>();

    dim3 gw(8, 32);
    dim3 bw(32, 8);
    k_wsplit<<<gw, bw>>>(lk, 0, 0);     // W_x -> g_Bhi/g_Blo
    k_wsplit<<<gw, bw>>>(lk, 256, 1);   // W_h -> g_Whhi/g_Whlo

    dim3 g1(ZC / 128, (Bc * Tc) / 128);
    k_xgemm_mma<<<g1, 256, SMX_TOTAL>>>(x, embed, bias);

    k_lstm4<<<NCTA_L, 512, SMEM_L4>>>();

    k_vu<<<(Bc * Tc) / 16, 128>>>(w_om, b_om, u_om);

    k_final<<<Bc, 256>>>(w2, b2, out);
}

// round 10
// speedup vs baseline: 5.5931x; 1.0121x over previous
#include <cuda_runtime.h>
#include <cuda_bf16.h>
#include <stdint.h>
#include <math.h>

#define Bc 256
#define Tc 512
#define Dc 256
#define Hc 256
#define Ac 128
#define ZC 1024

#define NCTA_L 128

// ---------------- scratch globals --------------------------------------------
__device__ float g_xz[(size_t)Bc * Tc * ZC];
__device__ float g_outs[(size_t)Bc * Tc * Hc];
__device__ float g_vu[Bc * Tc];
__device__ int   g_seqlen[Bc];
__device__ float g_h[2][Bc][Hc];
__device__ unsigned g_bar[16 * 32];
__device__ __nv_bfloat16 g_Bhi[1024 * 256];   // W_x^T hi, [n][k]
__device__ __nv_bfloat16 g_Blo[1024 * 256];   // W_x^T lo, [n][k]
__device__ __nv_bfloat16 g_Whhi[1024 * 256];  // W_h^T hi, [n][k]
__device__ __nv_bfloat16 g_Whlo[1024 * 256];  // W_h^T lo, [n][k]

typedef unsigned long long u64;

__device__ __forceinline__ u64 pack2(float lo, float hi) {
    u64 r;
    asm("mov.b64 %0, {%1, %2};" : "=l"(r) : "f"(lo), "f"(hi));
    return r;
}
__device__ __forceinline__ void fma2(u64& d, u64 a, u64 b) {
    asm("fma.rn.f32x2 %0, %1, %2, %0;" : "+l"(d) : "l"(a), "l"(b));
}
__device__ __forceinline__ float2 unpack2(u64 v) {
    float2 f;
    asm("mov.b64 {%0, %1}, %2;" : "=f"(f.x), "=f"(f.y) : "l"(v));
    return f;
}
__device__ __forceinline__ float sigm(float x) { return 1.0f / (1.0f + __expf(-x)); }
__device__ __forceinline__ float tanh_f(float x) {
    float ax = fabsf(x);
    float e = __expf(-2.0f * ax);
    float r = (1.0f - e) / (1.0f + e);
    return copysignf(r, x);
}
__device__ __forceinline__ uint32_t smem_u32(const void* p) {
    uint32_t a;
    asm("{ .reg .u64 t; cvta.to.shared.u64 t, %1; cvt.u32.u64 %0, t; }"
        : "=r"(a) : "l"(p));
    return a;
}

// ---------------- mma.sync helpers --------------------------------------------
__device__ __forceinline__ void ldmx4(uint32_t* r, uint32_t addr) {
    asm volatile("ldmatrix.sync.aligned.m8n8.x4.shared.b16 {%0,%1,%2,%3}, [%4];"
                 : "=r"(r[0]), "=r"(r[1]), "=r"(r[2]), "=r"(r[3]) : "r"(addr));
}
__device__ __forceinline__ void mma16816(float* c, const uint32_t* a,
                                         uint32_t b0, uint32_t b1) {
    asm volatile(
        "mma.sync.aligned.m16n8k16.row.col.f32.bf16.bf16.f32 "
        "{%0,%1,%2,%3}, {%4,%5,%6,%7}, {%8,%9}, {%0,%1,%2,%3};"
        : "+f"(c[0]), "+f"(c[1]), "+f"(c[2]), "+f"(c[3])
        : "r"(a[0]), "r"(a[1]), "r"(a[2]), "r"(a[3]), "r"(b0), "r"(b1));
}

// ---------------- K0: seq_len --------------------------------------------------
__global__ void k_seqlen(const int* __restrict__ x) {
    const int b = blockIdx.x;
    const int tid = threadIdx.x;
    int c = (x[b * Tc + tid] != 0) + (x[b * Tc + 256 + tid] != 0);
    #pragma unroll
    for (int o = 16; o; o >>= 1) c += __shfl_xor_sync(~0u, c, o);
    __shared__ int s[8];
    if ((tid & 31) == 0) s[tid >> 5] = c;
    __syncthreads();
    if (tid == 0) {
        int t = 0;
        #pragma unroll
        for (int i = 0; i < 8; i++) t += s[i];
        g_seqlen[b] = t;
    }
}

__global__ void k_init() {
    if (threadIdx.x < 16 * 32) g_bar[threadIdx.x] = 0u;
}

// ---------------- K0b: W transpose + bf16 hi/lo split --------------------------
__global__ void k_wsplit(const float* __restrict__ lk, int koff, int which) {
    __shared__ float s[32][33];
    const int kt = blockIdx.x * 32;
    const int nt = blockIdx.y * 32;
    const int tx = threadIdx.x;
    const int ty = threadIdx.y;
    #pragma unroll
    for (int i = 0; i < 4; i++) {
        s[ty + 8 * i][tx] = lk[(size_t)(koff + kt + ty + 8 * i) * ZC + nt + tx];
    }
    __syncthreads();
    __nv_bfloat16* dhi = which ? g_Whhi : g_Bhi;
    __nv_bfloat16* dlo = which ? g_Whlo : g_Blo;
    #pragma unroll
    for (int i = 0; i < 4; i++) {
        const int n = ty + 8 * i;
        float v = s[tx][n];
        __nv_bfloat16 h = __float2bfloat16(v);
        float lo = v - __bfloat162float(h);
        dhi[(size_t)(nt + n) * 256 + kt + tx] = h;
        dlo[(size_t)(nt + n) * 256 + kt + tx] = __float2bfloat16(lo);
    }
}

// ---------------- K1: xz = embed[x] @ W_x + bias via mma.sync ------------------
// CTA tile 128x64, K=256 in 4 chunks of 64. 8 warps, warp tile 64x16.
// Hoisted fragments (load once per k-step, 3 split terms reuse), A prefetch.
#define AST 72
#define X_TOK  0
#define X_BIAS 512
#define X_AHI  1024
#define X_ALO  (X_AHI + 128*AST*2)     // 19456
#define X_BHI  (X_ALO + 128*AST*2)     // 37888
#define X_BLO  (X_BHI + 64*AST*2)      // 47104
#define SMX_TOTAL (X_BLO + 64*AST*2)   // 56320

extern __shared__ char smx[];

__global__ __launch_bounds__(256, 2)
void k_xgemm2(const int* __restrict__ x, const float* __restrict__ embed,
              const float* __restrict__ bias) {
    const uint32_t sb = smem_u32(smx);
    const int tid  = threadIdx.x;
    const int wid  = tid >> 5;
    const int lane = tid & 31;
    const int bn = blockIdx.x * 64;
    const int bm = blockIdx.y * 128;

    int*   stok  = (int*)(smx + X_TOK);
    float* sbias = (float*)(smx + X_BIAS);
    __nv_bfloat16* sAhi = (__nv_bfloat16*)(smx + X_AHI);
    __nv_bfloat16* sAlo = (__nv_bfloat16*)(smx + X_ALO);
    __nv_bfloat16* sBhi = (__nv_bfloat16*)(smx + X_BHI);
    __nv_bfloat16* sBlo = (__nv_bfloat16*)(smx + X_BLO);

    if (tid < 128) stok[tid] = x[bm + tid];
    if (tid < 64)  sbias[tid] = bias[bn + tid];
    __syncthreads();

    const int wm = (wid & 1) * 64;     // warp m offset (0/64)
    const int wn = (wid >> 1) * 16;    // warp n offset (0..48)

    float acc[4][2][4];
    #pragma unroll
    for (int mt = 0; mt < 4; mt++)
        #pragma unroll
        for (int nt = 0; nt < 2; nt++)
            #pragma unroll
            for (int i = 0; i < 4; i++) acc[mt][nt][i] = 0.f;

    // A loader: 2 threads/row, 32 k each
    const int lrow = tid >> 1;
    const int lkh  = (tid & 1) * 32;
    const float* arow_p = embed + (size_t)stok[lrow] * Dc;

    // B loader: 4 threads/row, 16 k each
    const int brl  = tid >> 2;
    const int bseg = (tid & 3) * 16;

    // ldmatrix address components (identical mapping to R8-validated kernel)
    const uint32_t a_row = (uint32_t)(wm + (lane & 15));
    const uint32_t a_kof = (uint32_t)((lane >> 4) * 8);
    const uint32_t b_row = (uint32_t)(wn + ((lane >> 4) & 1) * 8 + (lane & 7));
    const uint32_t b_kof = (uint32_t)(((lane >> 3) & 1) * 8);
    const uint32_t aoff_hi = sb + X_AHI + (a_row * AST + a_kof) * 2;
    const uint32_t aoff_lo = sb + X_ALO + (a_row * AST + a_kof) * 2;
    const uint32_t boff_hi = sb + X_BHI + (b_row * AST + b_kof) * 2;
    const uint32_t boff_lo = sb + X_BLO + (b_row * AST + b_kof) * 2;

    // prefetch A chunk 0
    float4 av[8];
    #pragma unroll
    for (int i = 0; i < 8; i++) av[i] = *(const float4*)(arow_p + lkh + i * 4);

    for (int ck = 0; ck < 4; ck++) {
        // ---- STS A (split hi/lo) ----
        #pragma unroll
        for (int i = 0; i < 8; i++) {
            float4 v = av[i];
            __nv_bfloat162 h0 = __floats2bfloat162_rn(v.x, v.y);
            __nv_bfloat162 h1 = __floats2bfloat162_rn(v.z, v.w);
            __nv_bfloat162 l0 = __floats2bfloat162_rn(v.x - __bfloat162float(h0.x),
                                                      v.y - __bfloat162float(h0.y));
            __nv_bfloat162 l1 = __floats2bfloat162_rn(v.z - __bfloat162float(h1.x),
                                                      v.w - __bfloat162float(h1.y));
            const int off = lrow * AST + lkh + i * 4;
            uint2 ph; ph.x = *(uint32_t*)&h0; ph.y = *(uint32_t*)&h1;
            uint2 pl; pl.x = *(uint32_t*)&l0; pl.y = *(uint32_t*)&l1;
            *(uint2*)&sAhi[off] = ph;
            *(uint2*)&sAlo[off] = pl;
        }
        // ---- load + STS B (64 n x 64 k, hi/lo; from L2-resident split W) ----
        {
            const size_t src = (size_t)(bn + brl) * 256 + ck * 64 + bseg;
            uint4 h0 = *(const uint4*)&g_Bhi[src];
            uint4 h1 = *(const uint4*)&g_Bhi[src + 8];
            uint4 l0 = *(const uint4*)&g_Blo[src];
            uint4 l1 = *(const uint4*)&g_Blo[src + 8];
            const int dst = brl * AST + bseg;
            *(uint4*)&sBhi[dst]     = h0;
            *(uint4*)&sBhi[dst + 8] = h1;
            *(uint4*)&sBlo[dst]     = l0;
            *(uint4*)&sBlo[dst + 8] = l1;
        }
        __syncthreads();

        // prefetch next A chunk (overlaps MMA phase)
        if (ck < 3) {
            const float* src = arow_p + (ck + 1) * 64 + lkh;
            #pragma unroll
            for (int i = 0; i < 8; i++) av[i] = *(const float4*)(src + i * 4);
        }

        // ---- MMA: 4 k-steps, hoisted fragments, 3 split terms ----
        #pragma unroll
        for (int ks = 0; ks < 4; ks++) {
            const uint32_t kb = (uint32_t)(ks * 32);   // 16 bf16 = 32 bytes
            uint32_t ahi[4][4];
            uint32_t alo[4][4];
            #pragma unroll
            for (int mt = 0; mt < 4; mt++) {
                ldmx4(ahi[mt], aoff_hi + (uint32_t)(mt * 16 * AST * 2) + kb);
                ldmx4(alo[mt], aoff_lo + (uint32_t)(mt * 16 * AST * 2) + kb);
            }
            uint32_t bhi[4];
            uint32_t blo[4];
            ldmx4(bhi, boff_hi + kb);
            ldmx4(blo, boff_lo + kb);
            #pragma unroll
            for (int mt = 0; mt < 4; mt++) {
                mma16816(acc[mt][0], ahi[mt], bhi[0], bhi[1]);
                mma16816(acc[mt][1], ahi[mt], bhi[2], bhi[3]);
                mma16816(acc[mt][0], alo[mt], bhi[0], bhi[1]);
                mma16816(acc[mt][1], alo[mt], bhi[2], bhi[3]);
                mma16816(acc[mt][0], ahi[mt], blo[0], blo[1]);
                mma16816(acc[mt][1], ahi[mt], blo[2], blo[3]);
            }
        }
        __syncthreads();
    }

    // ---- epilogue: + bias, direct stores ----
    #pragma unroll
    for (int mt = 0; mt < 4; mt++) {
        const int m0 = bm + wm + mt * 16 + (lane >> 2);
        #pragma unroll
        for (int nt = 0; nt < 2; nt++) {
            const int nl = wn + nt * 8 + (lane & 3) * 2;
            const float b0 = sbias[nl];
            const float b1 = sbias[nl + 1];
            float2 v0;
            float2 v1;
            v0.x = acc[mt][nt][0] + b0;
            v0.y = acc[mt][nt][1] + b1;
            v1.x = acc[mt][nt][2] + b0;
            v1.y = acc[mt][nt][3] + b1;
            __stcs((float2*)&g_xz[(size_t)m0 * ZC + bn + nl], v0);
            __stcs((float2*)&g_xz[(size_t)(m0 + 8) * ZC + bn + nl], v1);
        }
    }
}

// ---------------- per-batch-group barrier --------------------------------------
__device__ __forceinline__ void group_bar(unsigned* ctr, unsigned target) {
    __threadfence();
    __syncthreads();
    if (threadIdx.x == 0) {
        atomicAdd(ctr, 1u);
        unsigned v;
        do {
            asm volatile("ld.global.acquire.gpu.u32 %0, [%1];"
                         : "=r"(v) : "l"(ctr) : "memory");
        } while (v < target);
    }
    __syncthreads();
}

// ---------------- K2: LSTM via mma.sync (R9-passing, unchanged) -----------------
#define WST 264
#define ZST 136
#define L4_WHI 0
#define L4_WLO 67584
#define L4_HHI 135168
#define L4_HLO 143616
#define L4_ZP  152064
#define SMEM_L4 221696

__global__ __launch_bounds__(512, 1)
void k_lstm4() {
    extern __shared__ char sml[];
    __nv_bfloat16* sWhi = (__nv_bfloat16*)(sml + L4_WHI);
    __nv_bfloat16* sWlo = (__nv_bfloat16*)(sml + L4_WLO);
    __nv_bfloat16* sHhi = (__nv_bfloat16*)(sml + L4_HHI);
    __nv_bfloat16* sHlo = (__nv_bfloat16*)(sml + L4_HLO);
    float* sZp = (float*)(sml + L4_ZP);
    const uint32_t sbase = smem_u32(sml);

    const int tid = threadIdx.x;
    const int g  = blockIdx.x & 7;
    const int bg = blockIdx.x >> 3;
    const int u0 = g * 32;
    const int b0 = bg * 16;
    unsigned* const ctr = &g_bar[bg * 32];

    {
        const int n = tid >> 2;
        const int c = tid & 3;
        const int gcol = (n >> 5) * 256 + u0 + (n & 31);
        const size_t src = (size_t)gcol * 256 + c * 64;
        const int dst = n * WST + c * 64;
        #pragma unroll
        for (int i = 0; i < 8; i++) {
            *(uint4*)&sWhi[dst + i * 8] = *(const uint4*)&g_Whhi[src + i * 8];
            *(uint4*)&sWlo[dst + i * 8] = *(const uint4*)&g_Whlo[src + i * 8];
        }
    }

    const int wid  = tid >> 5;
    const int lane = tid & 31;
    const int nh = wid & 1;
    const int kg = wid >> 1;
    const int n0 = nh * 64;
    const int k0 = kg * 32;

    const uint32_t a_part = (uint32_t)((lane & 15) * WST + (lane >> 4) * 8) * 2;
    const uint32_t aoff_hi = sbase + L4_HHI + a_part;
    const uint32_t aoff_lo = sbase + L4_HLO + a_part;
    const uint32_t brow = (uint32_t)(n0 + ((lane >> 4) & 1) * 8 + (lane & 7));
    const uint32_t bk   = (uint32_t)(((lane >> 3) & 1) * 8);
    const uint32_t b_part = (brow * WST + bk) * 2;
    const uint32_t boff_hi = sbase + L4_WHI + b_part;
    const uint32_t boff_lo = sbase + L4_WLO + b_part;

    const int gu = lane;
    const int gb = wid;
    float c_reg = 0.f;
    float h_reg = 0.f;
    const int slen = g_seqlen[b0 + gb];
    const size_t xzg = ((size_t)(b0 + gb) * Tc) * ZC + u0 + gu;
    const size_t og  = ((size_t)(b0 + gb) * Tc) * Hc + u0 + gu;
    float* const gh0 = &g_h[0][b0 + gb][u0 + gu];
    float* const gh1 = &g_h[1][b0 + gb][u0 + gu];

    const int srow = tid >> 5;
    const int skof = lane * 8;
    const float* const hsrc0 = &g_h[0][b0 + srow][skof];
    const float* const hsrc1 = &g_h[1][b0 + srow][skof];
    const int hdst = srow * WST + skof;

    for (int t = 0; t < Tc; t++) {
        const size_t xb = xzg + (size_t)t * ZC;
        float xg0 = __ldcs(&g_xz[xb]);
        float xg1 = __ldcs(&g_xz[xb + 256]);
        float xg2 = __ldcs(&g_xz[xb + 512]);
        float xg3 = __ldcs(&g_xz[xb + 768]);

        if (t == 0) {
            uint4 z4 = make_uint4(0u, 0u, 0u, 0u);
            *(uint4*)&sHhi[hdst] = z4;
            *(uint4*)&sHlo[hdst] = z4;
        } else {
            const float* hs = (t & 1) ? hsrc1 : hsrc0;
            float4 v0 = __ldcg((const float4*)hs);
            float4 v1 = __ldcg((const float4*)(hs + 4));
            __nv_bfloat162 h0 = __floats2bfloat162_rn(v0.x, v0.y);
            __nv_bfloat162 h1 = __floats2bfloat162_rn(v0.z, v0.w);
            __nv_bfloat162 h2 = __floats2bfloat162_rn(v1.x, v1.y);
            __nv_bfloat162 h3 = __floats2bfloat162_rn(v1.z, v1.w);
            __nv_bfloat162 l0 = __floats2bfloat162_rn(v0.x - __bfloat162float(h0.x),
                                                      v0.y - __bfloat162float(h0.y));
            __nv_bfloat162 l1 = __floats2bfloat162_rn(v0.z - __bfloat162float(h1.x),
                                                      v0.w - __bfloat162float(h1.y));
            __nv_bfloat162 l2 = __floats2bfloat162_rn(v1.x - __bfloat162float(h2.x),
                                                      v1.y - __bfloat162float(h2.y));
            __nv_bfloat162 l3 = __floats2bfloat162_rn(v1.z - __bfloat162float(h3.x),
                                                      v1.w - __bfloat162float(h3.y));
            uint4 ph;
            ph.x = *(uint32_t*)&h0; ph.y = *(uint32_t*)&h1;
            ph.z = *(uint32_t*)&h2; ph.w = *(uint32_t*)&h3;
            uint4 pl;
            pl.x = *(uint32_t*)&l0; pl.y = *(uint32_t*)&l1;
            pl.z = *(uint32_t*)&l2; pl.w = *(uint32_t*)&l3;
            *(uint4*)&sHhi[hdst] = ph;
            *(uint4*)&sHlo[hdst] = pl;
        }
        __syncthreads();

        float acc[8][4];
        #pragma unroll
        for (int nt = 0; nt < 8; nt++)
            #pragma unroll
            for (int i = 0; i < 4; i++) acc[nt][i] = 0.f;

        #pragma unroll
        for (int ks = 0; ks < 2; ks++) {
            const uint32_t kb = (uint32_t)((k0 + ks * 16) * 2);
            uint32_t ahi[4], alo[4];
            ldmx4(ahi, aoff_hi + kb);
            ldmx4(alo, aoff_lo + kb);
            #pragma unroll
            for (int p = 0; p < 4; p++) {
                const uint32_t pb = (uint32_t)(p * 16 * WST * 2) + kb;
                uint32_t bhi[4], blo[4];
                ldmx4(bhi, boff_hi + pb);
                ldmx4(blo, boff_lo + pb);
                mma16816(acc[2 * p],     ahi, bhi[0], bhi[1]);
                mma16816(acc[2 * p + 1], ahi, bhi[2], bhi[3]);
                mma16816(acc[2 * p],     alo, bhi[0], bhi[1]);
                mma16816(acc[2 * p + 1], alo, bhi[2], bhi[3]);
                mma16816(acc[2 * p],     ahi, blo[0], blo[1]);
                mma16816(acc[2 * p + 1], ahi, blo[2], blo[3]);
            }
        }

        {
            const int m  = lane >> 2;
            const int cb = (lane & 3) * 2;
            #pragma unroll
            for (int nt = 0; nt < 8; nt++) {
                const int col = n0 + nt * 8 + cb;
                *(float2*)&sZp[(kg * 16 + m) * ZST + col] =
                    make_float2(acc[nt][0], acc[nt][1]);
                *(float2*)&sZp[(kg * 16 + m + 8) * ZST + col] =
                    make_float2(acc[nt][2], acc[nt][3]);
            }
        }
        __syncthreads();

        float zi = xg0;
        float zj = xg1;
        float zf = xg2;
        float zo = xg3;
        #pragma unroll
        for (int p = 0; p < 8; p++) {
            const float* zp = &sZp[(p * 16 + gb) * ZST];
            zi += zp[gu];
            zj += zp[32 + gu];
            zf += zp[64 + gu];
            zo += zp[96 + gu];
        }
        float cn = c_reg * sigm(zf + 1.f) + sigm(zi) * tanh_f(zj);
        float hn = tanh_f(cn) * sigm(zo);
        bool m = (t < slen);
        c_reg = m ? cn : c_reg;
        h_reg = m ? hn : h_reg;
        __stcs(&g_outs[og + (size_t)t * Hc], m ? hn : 0.f);
        __stcg(((t + 1) & 1) ? gh1 : gh0, h_reg);

        group_bar(ctr, (unsigned)(t + 1) * 8u);
    }
}

// ---------------- K3: attention scores -----------------------------------------
__global__ __launch_bounds__(128)
void k_vu(const float* __restrict__ w_om, const float* __restrict__ b_om,
          const float* __restrict__ u_om) {
    __shared__ float so[16][Hc];
    __shared__ float sred[16][4];

    const int tid = threadIdx.x;
    const size_t base = (size_t)blockIdx.x * 16;

    for (int i = tid; i < 16 * 64; i += 128) {
        int r = i >> 6;
        int c = (i & 63) << 2;
        *(float4*)&so[r][c] = *(const float4*)&g_outs[(base + r) * Hc + c];
    }
    __syncthreads();

    u64 acc[8];
    #pragma unroll
    for (int r = 0; r < 8; r++) acc[r] = 0ull;

    for (int k = 0; k < Hc; k += 4) {
        float wa = w_om[(k + 0) * Ac + tid];
        float wb = w_om[(k + 1) * Ac + tid];
        float wc = w_om[(k + 2) * Ac + tid];
        float wd = w_om[(k + 3) * Ac + tid];
        u64 p0 = pack2(wa, wa);
        u64 p1 = pack2(wb, wb);
        u64 p2 = pack2(wc, wc);
        u64 p3 = pack2(wd, wd);
        #pragma unroll
        for (int r = 0; r < 8; r++) {
            float4 va = *(const float4*)&so[2 * r][k];
            float4 vb = *(const float4*)&so[2 * r + 1][k];
            fma2(acc[r], pack2(va.x, vb.x), p0);
            fma2(acc[r], pack2(va.y, vb.y), p1);
            fma2(acc[r], pack2(va.z, vb.z), p2);
            fma2(acc[r], pack2(va.w, vb.w), p3);
        }
    }

    const float bo = b_om[tid];
    const float uo = u_om[tid];
    float vr[16];
    #pragma unroll
    for (int r = 0; r < 8; r++) {
        float2 f = unpack2(acc[r]);
        vr[2 * r] = f.x;
        vr[2 * r + 1] = f.y;
    }
    #pragma unroll
    for (int r = 0; r < 16; r++) {
        float v = tanh_f(vr[r] + bo) * uo;
        #pragma unroll
        for (int o = 16; o; o >>= 1) v += __shfl_xor_sync(~0u, v, o);
        if ((tid & 31) == 0) sred[r][tid >> 5] = v;
    }
    __syncthreads();
    if (tid < 16) {
        g_vu[base + tid] = sred[tid][0] + sred[tid][1] + sred[tid][2] + sred[tid][3];
    }
}

// ---------------- block reductions ----------------------------------------------
__device__ __forceinline__ float blk_sum(float v, float* sr, int tid) {
    #pragma unroll
    for (int o = 16; o; o >>= 1) v += __shfl_xor_sync(~0u, v, o);
    if ((tid & 31) == 0) sr[tid >> 5] = v;
    __syncthreads();
    if (tid < 32) {
        float xx = (tid < 8) ? sr[tid] : 0.f;
        #pragma unroll
        for (int o = 4; o; o >>= 1) xx += __shfl_xor_sync(~0u, xx, o);
        if (tid == 0) sr[0] = xx;
    }
    __syncthreads();
    float r = sr[0];
    __syncthreads();
    return r;
}
__device__ __forceinline__ float blk_max(float v, float* sr, int tid) {
    #pragma unroll
    for (int o = 16; o; o >>= 1) v = fmaxf(v, __shfl_xor_sync(~0u, v, o));
    if ((tid & 31) == 0) sr[tid >> 5] = v;
    __syncthreads();
    if (tid < 32) {
        float xx = (tid < 8) ? sr[tid] : -INFINITY;
        #pragma unroll
        for (int o = 4; o; o >>= 1) xx = fmaxf(xx, __shfl_xor_sync(~0u, xx, o));
        if (tid == 0) sr[0] = xx;
    }
    __syncthreads();
    float r = sr[0];
    __syncthreads();
    return r;
}

// ---------------- K4: softmax over T, weighted sum, head ------------------------
__global__ __launch_bounds__(256)
void k_final(const float* __restrict__ w2, const float* __restrict__ b2,
             float* __restrict__ out) {
    __shared__ float sa[Tc];
    __shared__ float sr[32];

    const int b = blockIdx.x;
    const int tid = threadIdx.x;
    const float v0 = g_vu[b * Tc + tid];
    const float v1 = g_vu[b * Tc + 256 + tid];

    const float m = blk_max(fmaxf(v0, v1), sr, tid);
    const float e0 = expf(v0 - m);
    const float e1 = expf(v1 - m);
    sa[tid] = e0;
    sa[tid + 256] = e1;
    const float Z = blk_sum(e0 + e1, sr, tid);
    const float Zinv = 1.0f / Z;

    const float* op = g_outs + (size_t)b * Tc * Hc + tid;
    float acc = 0.f;
    #pragma unroll 4
    for (int t = 0; t < Tc; t++) {
        acc = fmaf(__ldcs(&op[(size_t)t * Hc]), sa[t], acc);
    }
    acc *= Zinv;

    const float l0 = blk_sum(acc * w2[tid * 2], sr, tid);
    const float l1 = blk_sum(acc * w2[tid * 2 + 1], sr, tid);

    if (tid == 0) {
        float a0 = l0 + b2[0];
        float a1 = l1 + b2[1];
        float mm = fmaxf(a0, a1);
        float x0 = expf(a0 - mm);
        float x1 = expf(a1 - mm);
        float s = 1.0f / (x0 + x1);
        out[b * 2 + 0] = x0 * s;
        out[b * 2 + 1] = x1 * s;
    }
}

// ---------------- launcher -------------------------------------------------------
extern "C" void kernel_launch(void* const* d_in, const int* in_sizes, int n_in,
                              void* d_out, int out_size) {
    const int*   x     = (const int*)  d_in[0];
    const float* embed = (const float*)d_in[1];
    const float* lk    = (const float*)d_in[2];
    const float* bias  = (const float*)d_in[3];
    const float* w_om  = (const float*)d_in[4];
    const float* b_om  = (const float*)d_in[5];
    const float* u_om  = (const float*)d_in[6];
    const float* w2    = (const float*)d_in[7];
    const float* b2    = (const float*)d_in[8];
    float* out = (float*)d_out;

    cudaFuncSetAttribute(k_xgemm2, cudaFuncAttributeMaxDynamicSharedMemorySize,
                         SMX_TOTAL);
    cudaFuncSetAttribute(k_lstm4, cudaFuncAttributeMaxDynamicSharedMemorySize,
                         SMEM_L4);

    k_seqlen<<<Bc, 256>>>(x);
    k_init<<<1, 512>>>();

    dim3 gw(8, 32);
    dim3 bw(32, 8);
    k_wsplit<<<gw, bw>>>(lk, 0, 0);     // W_x -> g_Bhi/g_Blo
    k_wsplit<<<gw, bw>>>(lk, 256, 1);   // W_h -> g_Whhi/g_Whlo

    dim3 g1(ZC / 64, (Bc * Tc) / 128);  // (16, 1024)
    k_xgemm2<<<g1, 256, SMX_TOTAL>>>(x, embed, bias);

    k_lstm4<<<NCTA_L, 512, SMEM_L4>>>();

    k_vu<<<(Bc * Tc) / 16, 128>>>(w_om, b_om, u_om);

    k_final<<<Bc, 256>>>(w2, b2, out);
}

// round 11
// speedup vs baseline: 6.1326x; 1.0965x over previous
#include <cuda_runtime.h>
#include <cuda_bf16.h>
#include <stdint.h>
#include <math.h>

#define Bc 256
#define Tc 512
#define Dc 256
#define Hc 256
#define Ac 128
#define ZC 1024
#define Vc 50000

#define NCTA_L 128

// ---------------- scratch globals --------------------------------------------
__device__ float g_xz[(size_t)Bc * Tc * ZC];
__device__ float g_outs[(size_t)Bc * Tc * Hc];
__device__ float g_vu[Bc * Tc];
__device__ int   g_seqlen[Bc];
__device__ float g_h[2][Bc][Hc];
__device__ unsigned g_bar[16 * 32];
__device__ __nv_bfloat16 g_Bhi[1024 * 256];   // W_x^T hi, [n][k]
__device__ __nv_bfloat16 g_Blo[1024 * 256];   // W_x^T lo, [n][k]
__device__ __nv_bfloat16 g_Whhi[1024 * 256];  // W_h^T hi, [n][k]
__device__ __nv_bfloat16 g_Whlo[1024 * 256];  // W_h^T lo, [n][k]
__device__ __nv_bfloat16 g_Ehi[(size_t)Vc * 256];  // embed hi, [v][k]
__device__ __nv_bfloat16 g_Elo[(size_t)Vc * 256];  // embed lo, [v][k]

typedef unsigned long long u64;

__device__ __forceinline__ u64 pack2(float lo, float hi) {
    u64 r;
    asm("mov.b64 %0, {%1, %2};" : "=l"(r) : "f"(lo), "f"(hi));
    return r;
}
__device__ __forceinline__ void fma2(u64& d, u64 a, u64 b) {
    asm("fma.rn.f32x2 %0, %1, %2, %0;" : "+l"(d) : "l"(a), "l"(b));
}
__device__ __forceinline__ float2 unpack2(u64 v) {
    float2 f;
    asm("mov.b64 {%0, %1}, %2;" : "=f"(f.x), "=f"(f.y) : "l"(v));
    return f;
}
__device__ __forceinline__ float sigm(float x) { return 1.0f / (1.0f + __expf(-x)); }
__device__ __forceinline__ float tanh_f(float x) {
    float ax = fabsf(x);
    float e = __expf(-2.0f * ax);
    float r = (1.0f - e) / (1.0f + e);
    return copysignf(r, x);
}
__device__ __forceinline__ uint32_t smem_u32(const void* p) {
    uint32_t a;
    asm("{ .reg .u64 t; cvta.to.shared.u64 t, %1; cvt.u32.u64 %0, t; }"
        : "=r"(a) : "l"(p));
    return a;
}

// ---------------- mma.sync helpers --------------------------------------------
__device__ __forceinline__ void ldmx4(uint32_t* r, uint32_t addr) {
    asm volatile("ldmatrix.sync.aligned.m8n8.x4.shared.b16 {%0,%1,%2,%3}, [%4];"
                 : "=r"(r[0]), "=r"(r[1]), "=r"(r[2]), "=r"(r[3]) : "r"(addr));
}
__device__ __forceinline__ void mma16816(float* c, const uint32_t* a,
                                         uint32_t b0, uint32_t b1) {
    asm volatile(
        "mma.sync.aligned.m16n8k16.row.col.f32.bf16.bf16.f32 "
        "{%0,%1,%2,%3}, {%4,%5,%6,%7}, {%8,%9}, {%0,%1,%2,%3};"
        : "+f"(c[0]), "+f"(c[1]), "+f"(c[2]), "+f"(c[3])
        : "r"(a[0]), "r"(a[1]), "r"(a[2]), "r"(a[3]), "r"(b0), "r"(b1));
}

// ---------------- K0: seq_len --------------------------------------------------
__global__ void k_seqlen(const int* __restrict__ x) {
    const int b = blockIdx.x;
    const int tid = threadIdx.x;
    int c = (x[b * Tc + tid] != 0) + (x[b * Tc + 256 + tid] != 0);
    #pragma unroll
    for (int o = 16; o; o >>= 1) c += __shfl_xor_sync(~0u, c, o);
    __shared__ int s[8];
    if ((tid & 31) == 0) s[tid >> 5] = c;
    __syncthreads();
    if (tid == 0) {
        int t = 0;
        #pragma unroll
        for (int i = 0; i < 8; i++) t += s[i];
        g_seqlen[b] = t;
    }
}

__global__ void k_init() {
    if (threadIdx.x < 16 * 32) g_bar[threadIdx.x] = 0u;
}

// ---------------- K0b: W transpose + bf16 hi/lo split --------------------------
__global__ void k_wsplit(const float* __restrict__ lk, int koff, int which) {
    __shared__ float s[32][33];
    const int kt = blockIdx.x * 32;
    const int nt = blockIdx.y * 32;
    const int tx = threadIdx.x;
    const int ty = threadIdx.y;
    #pragma unroll
    for (int i = 0; i < 4; i++) {
        s[ty + 8 * i][tx] = lk[(size_t)(koff + kt + ty + 8 * i) * ZC + nt + tx];
    }
    __syncthreads();
    __nv_bfloat16* dhi = which ? g_Whhi : g_Bhi;
    __nv_bfloat16* dlo = which ? g_Whlo : g_Blo;
    #pragma unroll
    for (int i = 0; i < 4; i++) {
        const int n = ty + 8 * i;
        float v = s[tx][n];
        __nv_bfloat16 h = __float2bfloat16(v);
        float lo = v - __bfloat162float(h);
        dhi[(size_t)(nt + n) * 256 + kt + tx] = h;
        dlo[(size_t)(nt + n) * 256 + kt + tx] = __float2bfloat16(lo);
    }
}

// ---------------- K0c: embedding table bf16 hi/lo split ------------------------
// 12.8M elements; each thread splits 8 consecutive floats.
__global__ __launch_bounds__(256)
void k_esplit(const float* __restrict__ embed) {
    const size_t base = ((size_t)blockIdx.x * 256 + threadIdx.x) * 8;
    if (base >= (size_t)Vc * 256) return;
    float4 v0 = *(const float4*)(embed + base);
    float4 v1 = *(const float4*)(embed + base + 4);
    __nv_bfloat162 h0 = __floats2bfloat162_rn(v0.x, v0.y);
    __nv_bfloat162 h1 = __floats2bfloat162_rn(v0.z, v0.w);
    __nv_bfloat162 h2 = __floats2bfloat162_rn(v1.x, v1.y);
    __nv_bfloat162 h3 = __floats2bfloat162_rn(v1.z, v1.w);
    __nv_bfloat162 l0 = __floats2bfloat162_rn(v0.x - __bfloat162float(h0.x),
                                              v0.y - __bfloat162float(h0.y));
    __nv_bfloat162 l1 = __floats2bfloat162_rn(v0.z - __bfloat162float(h1.x),
                                              v0.w - __bfloat162float(h1.y));
    __nv_bfloat162 l2 = __floats2bfloat162_rn(v1.x - __bfloat162float(h2.x),
                                              v1.y - __bfloat162float(h2.y));
    __nv_bfloat162 l3 = __floats2bfloat162_rn(v1.z - __bfloat162float(h3.x),
                                              v1.w - __bfloat162float(h3.y));
    uint4 ph;
    ph.x = *(uint32_t*)&h0; ph.y = *(uint32_t*)&h1;
    ph.z = *(uint32_t*)&h2; ph.w = *(uint32_t*)&h3;
    uint4 pl;
    pl.x = *(uint32_t*)&l0; pl.y = *(uint32_t*)&l1;
    pl.z = *(uint32_t*)&l2; pl.w = *(uint32_t*)&l3;
    __stcs((uint4*)&g_Ehi[base], ph);
    __stcs((uint4*)&g_Elo[base], pl);
}

// ---------------- K1: xz = embed[x] @ W_x + bias via mma.sync ------------------
// CTA tile 128x128, pre-split bf16 A gather, hoisted fragments.
#define AST 72
#define X_TOK  0
#define X_BIAS 512
#define X_AHI  1024
#define X_ALO  (X_AHI + 128*AST*2)
#define X_BHI  (X_ALO + 128*AST*2)
#define X_BLO  (X_BHI + 128*AST*2)
#define SMX_TOTAL (X_BLO + 128*AST*2)   // 74752

extern __shared__ char smx[];

__global__ __launch_bounds__(256, 2)
void k_xgemm3(const int* __restrict__ x, const float* __restrict__ bias) {
    const uint32_t sb = smem_u32(smx);
    const int tid  = threadIdx.x;
    const int wid  = tid >> 5;
    const int lane = tid & 31;
    const int bn = blockIdx.x * 128;
    const int bm = blockIdx.y * 128;

    int*   stok  = (int*)(smx + X_TOK);
    float* sbias = (float*)(smx + X_BIAS);
    __nv_bfloat16* sAhi = (__nv_bfloat16*)(smx + X_AHI);
    __nv_bfloat16* sAlo = (__nv_bfloat16*)(smx + X_ALO);
    __nv_bfloat16* sBhi = (__nv_bfloat16*)(smx + X_BHI);
    __nv_bfloat16* sBlo = (__nv_bfloat16*)(smx + X_BLO);

    if (tid < 128) {
        stok[tid]  = x[bm + tid];
        sbias[tid] = bias[bn + tid];
    }
    __syncthreads();

    const int wm = (wid & 1) * 64;
    const int wn = (wid >> 1) * 32;

    float acc[4][4][4];
    #pragma unroll
    for (int mt = 0; mt < 4; mt++)
        #pragma unroll
        for (int nt = 0; nt < 4; nt++)
            #pragma unroll
            for (int i = 0; i < 4; i++) acc[mt][nt][i] = 0.f;

    // loader: 2 threads/row, 32 bf16 (64B) each
    const int lrow = tid >> 1;
    const int lkh  = (tid & 1) * 32;
    const size_t abase = (size_t)stok[lrow] * 256 + lkh;
    const size_t bbase = (size_t)(bn + lrow) * 256 + lkh;
    const int sdst = lrow * AST + lkh;

    // ldmatrix address components (R8-validated mapping)
    const uint32_t a_row = (uint32_t)(wm + (lane & 15));
    const uint32_t a_kof = (uint32_t)((lane >> 4) * 8);
    const uint32_t b_row = (uint32_t)(wn + ((lane >> 4) & 1) * 8 + (lane & 7));
    const uint32_t b_kof = (uint32_t)(((lane >> 3) & 1) * 8);
    const uint32_t aoff_hi = sb + X_AHI + (a_row * AST + a_kof) * 2;
    const uint32_t aoff_lo = sb + X_ALO + (a_row * AST + a_kof) * 2;
    const uint32_t boff_hi = sb + X_BHI + (b_row * AST + b_kof) * 2;
    const uint32_t boff_lo = sb + X_BLO + (b_row * AST + b_kof) * 2;

    for (int ck = 0; ck < 4; ck++) {
        const int kb64 = ck * 64;
        // ---- gather A (bf16 hi/lo, pre-split) + stream B ----
        {
            uint4 ah0 = *(const uint4*)&g_Ehi[abase + kb64];
            uint4 ah1 = *(const uint4*)&g_Ehi[abase + kb64 + 8];
            uint4 ah2 = *(const uint4*)&g_Ehi[abase + kb64 + 16];
            uint4 ah3 = *(const uint4*)&g_Ehi[abase + kb64 + 24];
            uint4 al0 = *(const uint4*)&g_Elo[abase + kb64];
            uint4 al1 = *(const uint4*)&g_Elo[abase + kb64 + 8];
            uint4 al2 = *(const uint4*)&g_Elo[abase + kb64 + 16];
            uint4 al3 = *(const uint4*)&g_Elo[abase + kb64 + 24];
            uint4 bh0 = *(const uint4*)&g_Bhi[bbase + kb64];
            uint4 bh1 = *(const uint4*)&g_Bhi[bbase + kb64 + 8];
            uint4 bh2 = *(const uint4*)&g_Bhi[bbase + kb64 + 16];
            uint4 bh3 = *(const uint4*)&g_Bhi[bbase + kb64 + 24];
            uint4 bl0 = *(const uint4*)&g_Blo[bbase + kb64];
            uint4 bl1 = *(const uint4*)&g_Blo[bbase + kb64 + 8];
            uint4 bl2 = *(const uint4*)&g_Blo[bbase + kb64 + 16];
            uint4 bl3 = *(const uint4*)&g_Blo[bbase + kb64 + 24];
            *(uint4*)&sAhi[sdst]      = ah0;
            *(uint4*)&sAhi[sdst + 8]  = ah1;
            *(uint4*)&sAhi[sdst + 16] = ah2;
            *(uint4*)&sAhi[sdst + 24] = ah3;
            *(uint4*)&sAlo[sdst]      = al0;
            *(uint4*)&sAlo[sdst + 8]  = al1;
            *(uint4*)&sAlo[sdst + 16] = al2;
            *(uint4*)&sAlo[sdst + 24] = al3;
            *(uint4*)&sBhi[sdst]      = bh0;
            *(uint4*)&sBhi[sdst + 8]  = bh1;
            *(uint4*)&sBhi[sdst + 16] = bh2;
            *(uint4*)&sBhi[sdst + 24] = bh3;
            *(uint4*)&sBlo[sdst]      = bl0;
            *(uint4*)&sBlo[sdst + 8]  = bl1;
            *(uint4*)&sBlo[sdst + 16] = bl2;
            *(uint4*)&sBlo[sdst + 24] = bl3;
        }
        __syncthreads();

        // ---- MMA: 4 k-steps, hoisted B frags, A per mt, 3 split terms ----
        #pragma unroll
        for (int ks = 0; ks < 4; ks++) {
            const uint32_t kb = (uint32_t)(ks * 32);   // 16 bf16 = 32 B
            uint32_t bhi[2][4];
            uint32_t blo[2][4];
            #pragma unroll
            for (int np = 0; np < 2; np++) {
                const uint32_t pb = (uint32_t)(np * 16 * AST * 2) + kb;
                ldmx4(bhi[np], boff_hi + pb);
                ldmx4(blo[np], boff_lo + pb);
            }
            #pragma unroll
            for (int mt = 0; mt < 4; mt++) {
                const uint32_t mb = (uint32_t)(mt * 16 * AST * 2) + kb;
                uint32_t ahi[4];
                uint32_t alo[4];
                ldmx4(ahi, aoff_hi + mb);
                ldmx4(alo, aoff_lo + mb);
                #pragma unroll
                for (int nt = 0; nt < 4; nt++) {
                    const uint32_t b0 = bhi[nt >> 1][(nt & 1) * 2];
                    const uint32_t b1 = bhi[nt >> 1][(nt & 1) * 2 + 1];
                    const uint32_t c0 = blo[nt >> 1][(nt & 1) * 2];
                    const uint32_t c1 = blo[nt >> 1][(nt & 1) * 2 + 1];
                    mma16816(acc[mt][nt], ahi, b0, b1);
                    mma16816(acc[mt][nt], alo, b0, b1);
                    mma16816(acc[mt][nt], ahi, c0, c1);
                }
            }
        }
        __syncthreads();
    }

    // ---- epilogue: + bias, direct stores ----
    #pragma unroll
    for (int mt = 0; mt < 4; mt++) {
        const int m0 = bm + wm + mt * 16 + (lane >> 2);
        #pragma unroll
        for (int nt = 0; nt < 4; nt++) {
            const int nl = wn + nt * 8 + (lane & 3) * 2;
            const float b0 = sbias[nl];
            const float b1 = sbias[nl + 1];
            float2 v0;
            float2 v1;
            v0.x = acc[mt][nt][0] + b0;
            v0.y = acc[mt][nt][1] + b1;
            v1.x = acc[mt][nt][2] + b0;
            v1.y = acc[mt][nt][3] + b1;
            __stcs((float2*)&g_xz[(size_t)m0 * ZC + bn + nl], v0);
            __stcs((float2*)&g_xz[(size_t)(m0 + 8) * ZC + bn + nl], v1);
        }
    }
}

// ---------------- per-batch-group barrier --------------------------------------
__device__ __forceinline__ void group_bar(unsigned* ctr, unsigned target) {
    __threadfence();
    __syncthreads();
    if (threadIdx.x == 0) {
        atomicAdd(ctr, 1u);
        unsigned v;
        do {
            asm volatile("ld.global.acquire.gpu.u32 %0, [%1];"
                         : "=r"(v) : "l"(ctr) : "memory");
        } while (v < target);
    }
    __syncthreads();
}

// ---------------- K2: LSTM via mma.sync (R9-passing, unchanged) -----------------
#define WST 264
#define ZST 136
#define L4_WHI 0
#define L4_WLO 67584
#define L4_HHI 135168
#define L4_HLO 143616
#define L4_ZP  152064
#define SMEM_L4 221696

__global__ __launch_bounds__(512, 1)
void k_lstm4() {
    extern __shared__ char sml[];
    __nv_bfloat16* sWhi = (__nv_bfloat16*)(sml + L4_WHI);
    __nv_bfloat16* sWlo = (__nv_bfloat16*)(sml + L4_WLO);
    __nv_bfloat16* sHhi = (__nv_bfloat16*)(sml + L4_HHI);
    __nv_bfloat16* sHlo = (__nv_bfloat16*)(sml + L4_HLO);
    float* sZp = (float*)(sml + L4_ZP);
    const uint32_t sbase = smem_u32(sml);

    const int tid = threadIdx.x;
    const int g  = blockIdx.x & 7;
    const int bg = blockIdx.x >> 3;
    const int u0 = g * 32;
    const int b0 = bg * 16;
    unsigned* const ctr = &g_bar[bg * 32];

    {
        const int n = tid >> 2;
        const int c = tid & 3;
        const int gcol = (n >> 5) * 256 + u0 + (n & 31);
        const size_t src = (size_t)gcol * 256 + c * 64;
        const int dst = n * WST + c * 64;
        #pragma unroll
        for (int i = 0; i < 8; i++) {
            *(uint4*)&sWhi[dst + i * 8] = *(const uint4*)&g_Whhi[src + i * 8];
            *(uint4*)&sWlo[dst + i * 8] = *(const uint4*)&g_Whlo[src + i * 8];
        }
    }

    const int wid  = tid >> 5;
    const int lane = tid & 31;
    const int nh = wid & 1;
    const int kg = wid >> 1;
    const int n0 = nh * 64;
    const int k0 = kg * 32;

    const uint32_t a_part = (uint32_t)((lane & 15) * WST + (lane >> 4) * 8) * 2;
    const uint32_t aoff_hi = sbase + L4_HHI + a_part;
    const uint32_t aoff_lo = sbase + L4_HLO + a_part;
    const uint32_t brow = (uint32_t)(n0 + ((lane >> 4) & 1) * 8 + (lane & 7));
    const uint32_t bk   = (uint32_t)(((lane >> 3) & 1) * 8);
    const uint32_t b_part = (brow * WST + bk) * 2;
    const uint32_t boff_hi = sbase + L4_WHI + b_part;
    const uint32_t boff_lo = sbase + L4_WLO + b_part;

    const int gu = lane;
    const int gb = wid;
    float c_reg = 0.f;
    float h_reg = 0.f;
    const int slen = g_seqlen[b0 + gb];
    const size_t xzg = ((size_t)(b0 + gb) * Tc) * ZC + u0 + gu;
    const size_t og  = ((size_t)(b0 + gb) * Tc) * Hc + u0 + gu;
    float* const gh0 = &g_h[0][b0 + gb][u0 + gu];
    float* const gh1 = &g_h[1][b0 + gb][u0 + gu];

    const int srow = tid >> 5;
    const int skof = lane * 8;
    const float* const hsrc0 = &g_h[0][b0 + srow][skof];
    const float* const hsrc1 = &g_h[1][b0 + srow][skof];
    const int hdst = srow * WST + skof;

    for (int t = 0; t < Tc; t++) {
        const size_t xb = xzg + (size_t)t * ZC;
        float xg0 = __ldcs(&g_xz[xb]);
        float xg1 = __ldcs(&g_xz[xb + 256]);
        float xg2 = __ldcs(&g_xz[xb + 512]);
        float xg3 = __ldcs(&g_xz[xb + 768]);

        if (t == 0) {
            uint4 z4 = make_uint4(0u, 0u, 0u, 0u);
            *(uint4*)&sHhi[hdst] = z4;
            *(uint4*)&sHlo[hdst] = z4;
        } else {
            const float* hs = (t & 1) ? hsrc1 : hsrc0;
            float4 v0 = __ldcg((const float4*)hs);
            float4 v1 = __ldcg((const float4*)(hs + 4));
            __nv_bfloat162 h0 = __floats2bfloat162_rn(v0.x, v0.y);
            __nv_bfloat162 h1 = __floats2bfloat162_rn(v0.z, v0.w);
            __nv_bfloat162 h2 = __floats2bfloat162_rn(v1.x, v1.y);
            __nv_bfloat162 h3 = __floats2bfloat162_rn(v1.z, v1.w);
            __nv_bfloat162 l0 = __floats2bfloat162_rn(v0.x - __bfloat162float(h0.x),
                                                      v0.y - __bfloat162float(h0.y));
            __nv_bfloat162 l1 = __floats2bfloat162_rn(v0.z - __bfloat162float(h1.x),
                                                      v0.w - __bfloat162float(h1.y));
            __nv_bfloat162 l2 = __floats2bfloat162_rn(v1.x - __bfloat162float(h2.x),
                                                      v1.y - __bfloat162float(h2.y));
            __nv_bfloat162 l3 = __floats2bfloat162_rn(v1.z - __bfloat162float(h3.x),
                                                      v1.w - __bfloat162float(h3.y));
            uint4 ph;
            ph.x = *(uint32_t*)&h0; ph.y = *(uint32_t*)&h1;
            ph.z = *(uint32_t*)&h2; ph.w = *(uint32_t*)&h3;
            uint4 pl;
            pl.x = *(uint32_t*)&l0; pl.y = *(uint32_t*)&l1;
            pl.z = *(uint32_t*)&l2; pl.w = *(uint32_t*)&l3;
            *(uint4*)&sHhi[hdst] = ph;
            *(uint4*)&sHlo[hdst] = pl;
        }
        __syncthreads();

        float acc[8][4];
        #pragma unroll
        for (int nt = 0; nt < 8; nt++)
            #pragma unroll
            for (int i = 0; i < 4; i++) acc[nt][i] = 0.f;

        #pragma unroll
        for (int ks = 0; ks < 2; ks++) {
            const uint32_t kb = (uint32_t)((k0 + ks * 16) * 2);
            uint32_t ahi[4], alo[4];
            ldmx4(ahi, aoff_hi + kb);
            ldmx4(alo, aoff_lo + kb);
            #pragma unroll
            for (int p = 0; p < 4; p++) {
                const uint32_t pb = (uint32_t)(p * 16 * WST * 2) + kb;
                uint32_t bhi[4], blo[4];
                ldmx4(bhi, boff_hi + pb);
                ldmx4(blo, boff_lo + pb);
                mma16816(acc[2 * p],     ahi, bhi[0], bhi[1]);
                mma16816(acc[2 * p + 1], ahi, bhi[2], bhi[3]);
                mma16816(acc[2 * p],     alo, bhi[0], bhi[1]);
                mma16816(acc[2 * p + 1], alo, bhi[2], bhi[3]);
                mma16816(acc[2 * p],     ahi, blo[0], blo[1]);
                mma16816(acc[2 * p + 1], ahi, blo[2], blo[3]);
            }
        }

        {
            const int m  = lane >> 2;
            const int cb = (lane & 3) * 2;
            #pragma unroll
            for (int nt = 0; nt < 8; nt++) {
                const int col = n0 + nt * 8 + cb;
                *(float2*)&sZp[(kg * 16 + m) * ZST + col] =
                    make_float2(acc[nt][0], acc[nt][1]);
                *(float2*)&sZp[(kg * 16 + m + 8) * ZST + col] =
                    make_float2(acc[nt][2], acc[nt][3]);
            }
        }
        __syncthreads();

        float zi = xg0;
        float zj = xg1;
        float zf = xg2;
        float zo = xg3;
        #pragma unroll
        for (int p = 0; p < 8; p++) {
            const float* zp = &sZp[(p * 16 + gb) * ZST];
            zi += zp[gu];
            zj += zp[32 + gu];
            zf += zp[64 + gu];
            zo += zp[96 + gu];
        }
        float cn = c_reg * sigm(zf + 1.f) + sigm(zi) * tanh_f(zj);
        float hn = tanh_f(cn) * sigm(zo);
        bool m = (t < slen);
        c_reg = m ? cn : c_reg;
        h_reg = m ? hn : h_reg;
        __stcs(&g_outs[og + (size_t)t * Hc], m ? hn : 0.f);
        __stcg(((t + 1) & 1) ? gh1 : gh0, h_reg);

        group_bar(ctr, (unsigned)(t + 1) * 8u);
    }
}

// ---------------- K3: attention scores -----------------------------------------
__global__ __launch_bounds__(128)
void k_vu(const float* __restrict__ w_om, const float* __restrict__ b_om,
          const float* __restrict__ u_om) {
    __shared__ float so[16][Hc];
    __shared__ float sred[16][4];

    const int tid = threadIdx.x;
    const size_t base = (size_t)blockIdx.x * 16;

    for (int i = tid; i < 16 * 64; i += 128) {
        int r = i >> 6;
        int c = (i & 63) << 2;
        *(float4*)&so[r][c] = *(const float4*)&g_outs[(base + r) * Hc + c];
    }
    __syncthreads();

    u64 acc[8];
    #pragma unroll
    for (int r = 0; r < 8; r++) acc[r] = 0ull;

    for (int k = 0; k < Hc; k += 4) {
        float wa = w_om[(k + 0) * Ac + tid];
        float wb = w_om[(k + 1) * Ac + tid];
        float wc = w_om[(k + 2) * Ac + tid];
        float wd = w_om[(k + 3) * Ac + tid];
        u64 p0 = pack2(wa, wa);
        u64 p1 = pack2(wb, wb);
        u64 p2 = pack2(wc, wc);
        u64 p3 = pack2(wd, wd);
        #pragma unroll
        for (int r = 0; r < 8; r++) {
            float4 va = *(const float4*)&so[2 * r][k];
            float4 vb = *(const float4*)&so[2 * r + 1][k];
            fma2(acc[r], pack2(va.x, vb.x), p0);
            fma2(acc[r], pack2(va.y, vb.y), p1);
            fma2(acc[r], pack2(va.z, vb.z), p2);
            fma2(acc[r], pack2(va.w, vb.w), p3);
        }
    }

    const float bo = b_om[tid];
    const float uo = u_om[tid];
    float vr[16];
    #pragma unroll
    for (int r = 0; r < 8; r++) {
        float2 f = unpack2(acc[r]);
        vr[2 * r] = f.x;
        vr[2 * r + 1] = f.y;
    }
    #pragma unroll
    for (int r = 0; r < 16; r++) {
        float v = tanh_f(vr[r] + bo) * uo;
        #pragma unroll
        for (int o = 16; o; o >>= 1) v += __shfl_xor_sync(~0u, v, o);
        if ((tid & 31) == 0) sred[r][tid >> 5] = v;
    }
    __syncthreads();
    if (tid < 16) {
        g_vu[base + tid] = sred[tid][0] + sred[tid][1] + sred[tid][2] + sred[tid][3];
    }
}

// ---------------- block reductions ----------------------------------------------
__device__ __forceinline__ float blk_sum(float v, float* sr, int tid) {
    #pragma unroll
    for (int o = 16; o; o >>= 1) v += __shfl_xor_sync(~0u, v, o);
    if ((tid & 31) == 0) sr[tid >> 5] = v;
    __syncthreads();
    if (tid < 32) {
        float xx = (tid < 8) ? sr[tid] : 0.f;
        #pragma unroll
        for (int o = 4; o; o >>= 1) xx += __shfl_xor_sync(~0u, xx, o);
        if (tid == 0) sr[0] = xx;
    }
    __syncthreads();
    float r = sr[0];
    __syncthreads();
    return r;
}
__device__ __forceinline__ float blk_max(float v, float* sr, int tid) {
    #pragma unroll
    for (int o = 16; o; o >>= 1) v = fmaxf(v, __shfl_xor_sync(~0u, v, o));
    if ((tid & 31) == 0) sr[tid >> 5] = v;
    __syncthreads();
    if (tid < 32) {
        float xx = (tid < 8) ? sr[tid] : -INFINITY;
        #pragma unroll
        for (int o = 4; o; o >>= 1) xx = fmaxf(xx, __shfl_xor_sync(~0u, xx, o));
        if (tid == 0) sr[0] = xx;
    }
    __syncthreads();
    float r = sr[0];
    __syncthreads();
    return r;
}

// ---------------- K4: softmax over T, weighted sum, head ------------------------
__global__ __launch_bounds__(256)
void k_final(const float* __restrict__ w2, const float* __restrict__ b2,
             float* __restrict__ out) {
    __shared__ float sa[Tc];
    __shared__ float sr[32];

    const int b = blockIdx.x;
    const int tid = threadIdx.x;
    const float v0 = g_vu[b * Tc + tid];
    const float v1 = g_vu[b * Tc + 256 + tid];

    const float m = blk_max(fmaxf(v0, v1), sr, tid);
    const float e0 = expf(v0 - m);
    const float e1 = expf(v1 - m);
    sa[tid] = e0;
    sa[tid + 256] = e1;
    const float Z = blk_sum(e0 + e1, sr, tid);
    const float Zinv = 1.0f / Z;

    const float* op = g_outs + (size_t)b * Tc * Hc + tid;
    float acc = 0.f;
    #pragma unroll 4
    for (int t = 0; t < Tc; t++) {
        acc = fmaf(__ldcs(&op[(size_t)t * Hc]), sa[t], acc);
    }
    acc *= Zinv;

    const float l0 = blk_sum(acc * w2[tid * 2], sr, tid);
    const float l1 = blk_sum(acc * w2[tid * 2 + 1], sr, tid);

    if (tid == 0) {
        float a0 = l0 + b2[0];
        float a1 = l1 + b2[1];
        float mm = fmaxf(a0, a1);
        float x0 = expf(a0 - mm);
        float x1 = expf(a1 - mm);
        float s = 1.0f / (x0 + x1);
        out[b * 2 + 0] = x0 * s;
        out[b * 2 + 1] = x1 * s;
    }
}

// ---------------- launcher -------------------------------------------------------
extern "C" void kernel_launch(void* const* d_in, const int* in_sizes, int n_in,
                              void* d_out, int out_size) {
    const int*   x     = (const int*)  d_in[0];
    const float* embed = (const float*)d_in[1];
    const float* lk    = (const float*)d_in[2];
    const float* bias  = (const float*)d_in[3];
    const float* w_om  = (const float*)d_in[4];
    const float* b_om  = (const float*)d_in[5];
    const float* u_om  = (const float*)d_in[6];
    const float* w2    = (const float*)d_in[7];
    const float* b2    = (const float*)d_in[8];
    float* out = (float*)d_out;

    cudaFuncSetAttribute(k_xgemm3, cudaFuncAttributeMaxDynamicSharedMemorySize,
                         SMX_TOTAL);
    cudaFuncSetAttribute(k_lstm4, cudaFuncAttributeMaxDynamicSharedMemorySize,
                         SMEM_L4);

    k_seqlen<<<Bc, 256>>>(x);
    k_init<<<1, 512>>>();

    dim3 gw(8, 32);
    dim3 bw(32, 8);
    k_wsplit<<<gw, bw>>>(lk, 0, 0);     // W_x -> g_Bhi/g_Blo
    k_wsplit<<<gw, bw>>>(lk, 256, 1);   // W_h -> g_Whhi/g_Whlo

    k_esplit<<<(Vc * 256) / (256 * 8), 256>>>(embed);   // 6250 blocks

    dim3 g1(ZC / 128, (Bc * Tc) / 128);   // (8, 1024)
    k_xgemm3<<<g1, 256, SMX_TOTAL>>>(x, bias);

    k_lstm4<<<NCTA_L, 512, SMEM_L4>>>();

    k_vu<<<(Bc * Tc) / 16, 128>>>(w_om, b_om, u_om);

    k_final<<<Bc, 256>>>(w2, b2, out);
}

// round 12
// speedup vs baseline: 6.5243x; 1.0639x over previous
#include <cuda_runtime.h>
#include <cuda_bf16.h>
#include <stdint.h>
#include <math.h>

#define Bc 256
#define Tc 512
#define Dc 256
#define Hc 256
#define Ac 128
#define ZC 1024
#define Vc 50000

#define NCTA_L 128

// ---------------- scratch globals --------------------------------------------
__device__ float g_xz[(size_t)Bc * Tc * ZC];
__device__ float g_outs[(size_t)Bc * Tc * Hc];
__device__ float g_vu[Bc * Tc];
__device__ int   g_seqlen[Bc];
__device__ __nv_bfloat16 g_hhi[2][Bc][Hc];    // h exchange, bf16 hi
__device__ __nv_bfloat16 g_hlo[2][Bc][Hc];    // h exchange, bf16 lo
__device__ unsigned g_bar[16 * 32];
__device__ __nv_bfloat16 g_Bhi[1024 * 256];   // W_x^T hi, [n][k]
__device__ __nv_bfloat16 g_Blo[1024 * 256];   // W_x^T lo, [n][k]
__device__ __nv_bfloat16 g_Whhi[1024 * 256];  // W_h^T hi, [n][k]
__device__ __nv_bfloat16 g_Whlo[1024 * 256];  // W_h^T lo, [n][k]
__device__ __nv_bfloat16 g_Ehi[(size_t)Vc * 256];  // embed hi, [v][k]
__device__ __nv_bfloat16 g_Elo[(size_t)Vc * 256];  // embed lo, [v][k]

typedef unsigned long long u64;

__device__ __forceinline__ u64 pack2(float lo, float hi) {
    u64 r;
    asm("mov.b64 %0, {%1, %2};" : "=l"(r) : "f"(lo), "f"(hi));
    return r;
}
__device__ __forceinline__ void fma2(u64& d, u64 a, u64 b) {
    asm("fma.rn.f32x2 %0, %1, %2, %0;" : "+l"(d) : "l"(a), "l"(b));
}
__device__ __forceinline__ float2 unpack2(u64 v) {
    float2 f;
    asm("mov.b64 {%0, %1}, %2;" : "=f"(f.x), "=f"(f.y) : "l"(v));
    return f;
}
__device__ __forceinline__ float sigm(float x) { return 1.0f / (1.0f + __expf(-x)); }
__device__ __forceinline__ float tanh_f(float x) {
    float ax = fabsf(x);
    float e = __expf(-2.0f * ax);
    float r = (1.0f - e) / (1.0f + e);
    return copysignf(r, x);
}
__device__ __forceinline__ uint32_t smem_u32(const void* p) {
    uint32_t a;
    asm("{ .reg .u64 t; cvta.to.shared.u64 t, %1; cvt.u32.u64 %0, t; }"
        : "=r"(a) : "l"(p));
    return a;
}

// ---------------- mma.sync / cp.async helpers ----------------------------------
__device__ __forceinline__ void ldmx4(uint32_t* r, uint32_t addr) {
    asm volatile("ldmatrix.sync.aligned.m8n8.x4.shared.b16 {%0,%1,%2,%3}, [%4];"
                 : "=r"(r[0]), "=r"(r[1]), "=r"(r[2]), "=r"(r[3]) : "r"(addr));
}
__device__ __forceinline__ void mma16816(float* c, const uint32_t* a,
                                         uint32_t b0, uint32_t b1) {
    asm volatile(
        "mma.sync.aligned.m16n8k16.row.col.f32.bf16.bf16.f32 "
        "{%0,%1,%2,%3}, {%4,%5,%6,%7}, {%8,%9}, {%0,%1,%2,%3};"
        : "+f"(c[0]), "+f"(c[1]), "+f"(c[2]), "+f"(c[3])
        : "r"(a[0]), "r"(a[1]), "r"(a[2]), "r"(a[3]), "r"(b0), "r"(b1));
}
#define CP16(dst, src) \
    asm volatile("cp.async.cg.shared.global [%0], [%1], 16;" \
                 :: "r"(dst), "l"(src) : "memory")
#define CP_COMMIT() asm volatile("cp.async.commit_group;" ::: "memory")
#define CP_WAIT1()  asm volatile("cp.async.wait_group 1;" ::: "memory")
#define CP_WAIT0()  asm volatile("cp.async.wait_group 0;" ::: "memory")

// ---------------- K0: seq_len --------------------------------------------------
__global__ void k_seqlen(const int* __restrict__ x) {
    const int b = blockIdx.x;
    const int tid = threadIdx.x;
    int c = (x[b * Tc + tid] != 0) + (x[b * Tc + 256 + tid] != 0);
    #pragma unroll
    for (int o = 16; o; o >>= 1) c += __shfl_xor_sync(~0u, c, o);
    __shared__ int s[8];
    if ((tid & 31) == 0) s[tid >> 5] = c;
    __syncthreads();
    if (tid == 0) {
        int t = 0;
        #pragma unroll
        for (int i = 0; i < 8; i++) t += s[i];
        g_seqlen[b] = t;
    }
}

__global__ void k_init() {
    if (threadIdx.x < 16 * 32) g_bar[threadIdx.x] = 0u;
}

// ---------------- K0b: W transpose + bf16 hi/lo split --------------------------
__global__ void k_wsplit(const float* __restrict__ lk, int koff, int which) {
    __shared__ float s[32][33];
    const int kt = blockIdx.x * 32;
    const int nt = blockIdx.y * 32;
    const int tx = threadIdx.x;
    const int ty = threadIdx.y;
    #pragma unroll
    for (int i = 0; i < 4; i++) {
        s[ty + 8 * i][tx] = lk[(size_t)(koff + kt + ty + 8 * i) * ZC + nt + tx];
    }
    __syncthreads();
    __nv_bfloat16* dhi = which ? g_Whhi : g_Bhi;
    __nv_bfloat16* dlo = which ? g_Whlo : g_Blo;
    #pragma unroll
    for (int i = 0; i < 4; i++) {
        const int n = ty + 8 * i;
        float v = s[tx][n];
        __nv_bfloat16 h = __float2bfloat16(v);
        float lo = v - __bfloat162float(h);
        dhi[(size_t)(nt + n) * 256 + kt + tx] = h;
        dlo[(size_t)(nt + n) * 256 + kt + tx] = __float2bfloat16(lo);
    }
}

// ---------------- K0c: embedding table bf16 hi/lo split ------------------------
__global__ __launch_bounds__(256)
void k_esplit(const float* __restrict__ embed) {
    const size_t base = ((size_t)blockIdx.x * 256 + threadIdx.x) * 8;
    if (base >= (size_t)Vc * 256) return;
    float4 v0 = *(const float4*)(embed + base);
    float4 v1 = *(const float4*)(embed + base + 4);
    __nv_bfloat162 h0 = __floats2bfloat162_rn(v0.x, v0.y);
    __nv_bfloat162 h1 = __floats2bfloat162_rn(v0.z, v0.w);
    __nv_bfloat162 h2 = __floats2bfloat162_rn(v1.x, v1.y);
    __nv_bfloat162 h3 = __floats2bfloat162_rn(v1.z, v1.w);
    __nv_bfloat162 l0 = __floats2bfloat162_rn(v0.x - __bfloat162float(h0.x),
                                              v0.y - __bfloat162float(h0.y));
    __nv_bfloat162 l1 = __floats2bfloat162_rn(v0.z - __bfloat162float(h1.x),
                                              v0.w - __bfloat162float(h1.y));
    __nv_bfloat162 l2 = __floats2bfloat162_rn(v1.x - __bfloat162float(h2.x),
                                              v1.y - __bfloat162float(h2.y));
    __nv_bfloat162 l3 = __floats2bfloat162_rn(v1.z - __bfloat162float(h3.x),
                                              v1.w - __bfloat162float(h3.y));
    uint4 ph;
    ph.x = *(uint32_t*)&h0; ph.y = *(uint32_t*)&h1;
    ph.z = *(uint32_t*)&h2; ph.w = *(uint32_t*)&h3;
    uint4 pl;
    pl.x = *(uint32_t*)&l0; pl.y = *(uint32_t*)&l1;
    pl.z = *(uint32_t*)&l2; pl.w = *(uint32_t*)&l3;
    __stcs((uint4*)&g_Ehi[base], ph);
    __stcs((uint4*)&g_Elo[base], pl);
}

// ---------------- K1: xz GEMM, cp.async 2-stage pipeline -----------------------
// CTA tile 128x128, K=256 in 8 chunks of 32, double-buffered via cp.async.
#define AST2 40                         // bf16 row stride (80B): LDSM conflict-free
#define X_TOK  0
#define X_BIAS 512
#define X_ARR  10240                    // bytes per array per stage (128*40*2)
#define X_STG  (4 * X_ARR)              // 40960 per stage
#define X_BASE 1024
#define SMX_TOTAL (X_BASE + 2 * X_STG)  // 82944

extern __shared__ char smx[];

__global__ __launch_bounds__(256, 2)
void k_xgemm4(const int* __restrict__ x, const float* __restrict__ bias) {
    const uint32_t sb = smem_u32(smx);
    const int tid  = threadIdx.x;
    const int wid  = tid >> 5;
    const int lane = tid & 31;
    const int bn = blockIdx.x * 128;
    const int bm = blockIdx.y * 128;

    int*   stok  = (int*)(smx + X_TOK);
    float* sbias = (float*)(smx + X_BIAS);

    if (tid < 128) {
        stok[tid]  = x[bm + tid];
        sbias[tid] = bias[bn + tid];
    }
    __syncthreads();

    const int wm = (wid & 1) * 64;
    const int wn = (wid >> 1) * 32;

    float acc[4][4][4];
    #pragma unroll
    for (int mt = 0; mt < 4; mt++)
        #pragma unroll
        for (int nt = 0; nt < 4; nt++)
            #pragma unroll
            for (int i = 0; i < 4; i++) acc[mt][nt][i] = 0.f;

    // loader: 2 threads/row, 16 k each (2 x 16B per array)
    const int lrow = tid >> 1;
    const int lk16 = (tid & 1) * 16;
    const size_t asrc = (size_t)stok[lrow] * 256 + lk16;
    const size_t bsrc = (size_t)(bn + lrow) * 256 + lk16;
    const uint32_t ldst = (uint32_t)((lrow * AST2 + lk16) * 2);  // byte offset in array

    // ldmatrix address components
    const uint32_t a_comp = (uint32_t)(((wm + (lane & 15)) * AST2 + (lane >> 4) * 8) * 2);
    const uint32_t b_comp = (uint32_t)(((wn + ((lane >> 4) & 1) * 8 + (lane & 7)) * AST2
                                        + ((lane >> 3) & 1) * 8) * 2);

#define X4_ISSUE(CK, STG) do {                                                 \
    const int _kb = (CK) * 32;                                                 \
    const uint32_t _st = sb + X_BASE + (STG) * X_STG + ldst;                   \
    CP16(_st,                 (const char*)&g_Ehi[asrc + _kb]);                \
    CP16(_st + 16,            (const char*)&g_Ehi[asrc + _kb + 8]);            \
    CP16(_st + X_ARR,         (const char*)&g_Elo[asrc + _kb]);                \
    CP16(_st + X_ARR + 16,    (const char*)&g_Elo[asrc + _kb + 8]);            \
    CP16(_st + 2*X_ARR,       (const char*)&g_Bhi[bsrc + _kb]);                \
    CP16(_st + 2*X_ARR + 16,  (const char*)&g_Bhi[bsrc + _kb + 8]);            \
    CP16(_st + 3*X_ARR,       (const char*)&g_Blo[bsrc + _kb]);                \
    CP16(_st + 3*X_ARR + 16,  (const char*)&g_Blo[bsrc + _kb + 8]);            \
    CP_COMMIT();                                                               \
} while (0)

    X4_ISSUE(0, 0);

    for (int ck = 0; ck < 8; ck++) {
        if (ck < 7) {
            X4_ISSUE(ck + 1, (ck + 1) & 1);
            CP_WAIT1();
        } else {
            CP_WAIT0();
        }
        __syncthreads();

        const uint32_t stg = sb + X_BASE + (uint32_t)((ck & 1) * X_STG);
        const uint32_t aoff_hi = stg + a_comp;
        const uint32_t aoff_lo = stg + X_ARR + a_comp;
        const uint32_t boff_hi = stg + 2 * X_ARR + b_comp;
        const uint32_t boff_lo = stg + 3 * X_ARR + b_comp;

        #pragma unroll
        for (int ks = 0; ks < 2; ks++) {
            const uint32_t kb = (uint32_t)(ks * 32);   // 16 bf16 = 32 B
            uint32_t bhi[2][4];
            uint32_t blo[2][4];
            #pragma unroll
            for (int np = 0; np < 2; np++) {
                const uint32_t pb = (uint32_t)(np * 16 * AST2 * 2) + kb;
                ldmx4(bhi[np], boff_hi + pb);
                ldmx4(blo[np], boff_lo + pb);
            }
            #pragma unroll
            for (int mt = 0; mt < 4; mt++) {
                const uint32_t mb = (uint32_t)(mt * 16 * AST2 * 2) + kb;
                uint32_t ahi[4];
                uint32_t alo[4];
                ldmx4(ahi, aoff_hi + mb);
                ldmx4(alo, aoff_lo + mb);
                #pragma unroll
                for (int nt = 0; nt < 4; nt++) {
                    const uint32_t b0 = bhi[nt >> 1][(nt & 1) * 2];
                    const uint32_t b1 = bhi[nt >> 1][(nt & 1) * 2 + 1];
                    const uint32_t c0 = blo[nt >> 1][(nt & 1) * 2];
                    const uint32_t c1 = blo[nt >> 1][(nt & 1) * 2 + 1];
                    mma16816(acc[mt][nt], ahi, b0, b1);
                    mma16816(acc[mt][nt], alo, b0, b1);
                    mma16816(acc[mt][nt], ahi, c0, c1);
                }
            }
        }
        __syncthreads();
    }

    // ---- epilogue: + bias, direct stores ----
    #pragma unroll
    for (int mt = 0; mt < 4; mt++) {
        const int m0 = bm + wm + mt * 16 + (lane >> 2);
        #pragma unroll
        for (int nt = 0; nt < 4; nt++) {
            const int nl = wn + nt * 8 + (lane & 3) * 2;
            const float b0 = sbias[nl];
            const float b1 = sbias[nl + 1];
            float2 v0;
            float2 v1;
            v0.x = acc[mt][nt][0] + b0;
            v0.y = acc[mt][nt][1] + b1;
            v1.x = acc[mt][nt][2] + b0;
            v1.y = acc[mt][nt][3] + b1;
            __stcs((float2*)&g_xz[(size_t)m0 * ZC + bn + nl], v0);
            __stcs((float2*)&g_xz[(size_t)(m0 + 8) * ZC + bn + nl], v1);
        }
    }
}

// ---------------- K2: LSTM via mma.sync, bf16 h exchange -----------------------
#define WST 264
#define ZST 136
#define L4_WHI 0
#define L4_WLO 67584
#define L4_HHI 135168
#define L4_HLO 143616
#define L4_ZP  152064
#define SMEM_L4 221696

__global__ __launch_bounds__(512, 1)
void k_lstm5() {
    extern __shared__ char sml[];
    __nv_bfloat16* sWhi = (__nv_bfloat16*)(sml + L4_WHI);
    __nv_bfloat16* sWlo = (__nv_bfloat16*)(sml + L4_WLO);
    __nv_bfloat16* sHhi = (__nv_bfloat16*)(sml + L4_HHI);
    __nv_bfloat16* sHlo = (__nv_bfloat16*)(sml + L4_HLO);
    float* sZp = (float*)(sml + L4_ZP);
    const uint32_t sbase = smem_u32(sml);

    const int tid = threadIdx.x;
    const int g  = blockIdx.x & 7;
    const int bg = blockIdx.x >> 3;
    const int u0 = g * 32;
    const int b0 = bg * 16;
    unsigned* const ctr = &g_bar[bg * 32];

    // W_h slice -> SMEM (once)
    {
        const int n = tid >> 2;
        const int c = tid & 3;
        const int gcol = (n >> 5) * 256 + u0 + (n & 31);
        const size_t src = (size_t)gcol * 256 + c * 64;
        const int dst = n * WST + c * 64;
        #pragma unroll
        for (int i = 0; i < 8; i++) {
            *(uint4*)&sWhi[dst + i * 8] = *(const uint4*)&g_Whhi[src + i * 8];
            *(uint4*)&sWlo[dst + i * 8] = *(const uint4*)&g_Whlo[src + i * 8];
        }
    }

    const int wid  = tid >> 5;
    const int lane = tid & 31;
    const int nh = wid & 1;
    const int kg = wid >> 1;
    const int n0 = nh * 64;
    const int k0 = kg * 32;

    const uint32_t a_part = (uint32_t)((lane & 15) * WST + (lane >> 4) * 8) * 2;
    const uint32_t aoff_hi = sbase + L4_HHI + a_part;
    const uint32_t aoff_lo = sbase + L4_HLO + a_part;
    const uint32_t brow = (uint32_t)(n0 + ((lane >> 4) & 1) * 8 + (lane & 7));
    const uint32_t bk   = (uint32_t)(((lane >> 3) & 1) * 8);
    const uint32_t b_part = (brow * WST + bk) * 2;
    const uint32_t boff_hi = sbase + L4_WHI + b_part;
    const uint32_t boff_lo = sbase + L4_WLO + b_part;

    const int gu = lane;
    const int gb = wid;
    float c_reg = 0.f;
    float h_reg = 0.f;
    const int slen = g_seqlen[b0 + gb];
    const size_t xzg = ((size_t)(b0 + gb) * Tc) * ZC + u0 + gu;
    const size_t og  = ((size_t)(b0 + gb) * Tc) * Hc + u0 + gu;
    __nv_bfloat16* const ghh0 = &g_hhi[0][b0 + gb][u0 + gu];
    __nv_bfloat16* const ghh1 = &g_hhi[1][b0 + gb][u0 + gu];
    __nv_bfloat16* const ghl0 = &g_hlo[0][b0 + gb][u0 + gu];
    __nv_bfloat16* const ghl1 = &g_hlo[1][b0 + gb][u0 + gu];

    // h staging: 512 threads x 8 bf16 = 16x256 (hi + lo)
    const int srow = tid >> 5;
    const int skof = lane * 8;
    const __nv_bfloat16* const hshi0 = &g_hhi[0][b0 + srow][skof];
    const __nv_bfloat16* const hshi1 = &g_hhi[1][b0 + srow][skof];
    const __nv_bfloat16* const hslo0 = &g_hlo[0][b0 + srow][skof];
    const __nv_bfloat16* const hslo1 = &g_hlo[1][b0 + srow][skof];
    const int hdst = srow * WST + skof;

    // prefetch xz for t=0
    float xg0 = __ldcs(&g_xz[xzg]);
    float xg1 = __ldcs(&g_xz[xzg + 256]);
    float xg2 = __ldcs(&g_xz[xzg + 512]);
    float xg3 = __ldcs(&g_xz[xzg + 768]);

    for (int t = 0; t < Tc; t++) {
        // stage h(t-1) (pre-split bf16)
        if (t == 0) {
            uint4 z4 = make_uint4(0u, 0u, 0u, 0u);
            *(uint4*)&sHhi[hdst] = z4;
            *(uint4*)&sHlo[hdst] = z4;
        } else {
            const int bsel = t & 1;
            uint4 vh = __ldcg((const uint4*)(bsel ? hshi1 : hshi0));
            uint4 vl = __ldcg((const uint4*)(bsel ? hslo1 : hslo0));
            *(uint4*)&sHhi[hdst] = vh;
            *(uint4*)&sHlo[hdst] = vl;
        }
        __syncthreads();

        // ---- z partial: 16 m x 64 n x 32 k, 3 split terms ----
        float acc[8][4];
        #pragma unroll
        for (int nt = 0; nt < 8; nt++)
            #pragma unroll
            for (int i = 0; i < 4; i++) acc[nt][i] = 0.f;

        #pragma unroll
        for (int ks = 0; ks < 2; ks++) {
            const uint32_t kb = (uint32_t)((k0 + ks * 16) * 2);
            uint32_t ahi[4], alo[4];
            ldmx4(ahi, aoff_hi + kb);
            ldmx4(alo, aoff_lo + kb);
            #pragma unroll
            for (int p = 0; p < 4; p++) {
                const uint32_t pb = (uint32_t)(p * 16 * WST * 2) + kb;
                uint32_t bhi[4], blo[4];
                ldmx4(bhi, boff_hi + pb);
                ldmx4(blo, boff_lo + pb);
                mma16816(acc[2 * p],     ahi, bhi[0], bhi[1]);
                mma16816(acc[2 * p + 1], ahi, bhi[2], bhi[3]);
                mma16816(acc[2 * p],     alo, bhi[0], bhi[1]);
                mma16816(acc[2 * p + 1], alo, bhi[2], bhi[3]);
                mma16816(acc[2 * p],     ahi, blo[0], blo[1]);
                mma16816(acc[2 * p + 1], ahi, blo[2], blo[3]);
            }
        }

        {
            const int m  = lane >> 2;
            const int cb = (lane & 3) * 2;
            #pragma unroll
            for (int nt = 0; nt < 8; nt++) {
                const int col = n0 + nt * 8 + cb;
                *(float2*)&sZp[(kg * 16 + m) * ZST + col] =
                    make_float2(acc[nt][0], acc[nt][1]);
                *(float2*)&sZp[(kg * 16 + m + 8) * ZST + col] =
                    make_float2(acc[nt][2], acc[nt][3]);
            }
        }
        __syncthreads();

        // ---- gates ----
        float zi = xg0;
        float zj = xg1;
        float zf = xg2;
        float zo = xg3;
        #pragma unroll
        for (int p = 0; p < 8; p++) {
            const float* zp = &sZp[(p * 16 + gb) * ZST];
            zi += zp[gu];
            zj += zp[32 + gu];
            zf += zp[64 + gu];
            zo += zp[96 + gu];
        }
        float cn = c_reg * sigm(zf + 1.f) + sigm(zi) * tanh_f(zj);
        float hn = tanh_f(cn) * sigm(zo);
        bool m = (t < slen);
        c_reg = m ? cn : c_reg;
        h_reg = m ? hn : h_reg;

        // store h (pre-split) for next step
        {
            __nv_bfloat16 hh = __float2bfloat16(h_reg);
            __nv_bfloat16 hl = __float2bfloat16(h_reg - __bfloat162float(hh));
            const int nb = (t + 1) & 1;
            *(nb ? ghh1 : ghh0) = hh;
            *(nb ? ghl1 : ghl0) = hl;
        }

        // barrier arrive
        __threadfence();
        __syncthreads();
        if (tid == 0) atomicAdd(ctr, 1u);

        // work hidden under barrier skew: outs store + next xz prefetch
        __stcs(&g_outs[og + (size_t)t * Hc], m ? hn : 0.f);
        if (t + 1 < Tc) {
            const size_t xb = xzg + (size_t)(t + 1) * ZC;
            xg0 = __ldcs(&g_xz[xb]);
            xg1 = __ldcs(&g_xz[xb + 256]);
            xg2 = __ldcs(&g_xz[xb + 512]);
            xg3 = __ldcs(&g_xz[xb + 768]);
        }

        // barrier wait
        if (tid == 0) {
            const unsigned target = (unsigned)(t + 1) * 8u;
            unsigned v;
            do {
                asm volatile("ld.global.acquire.gpu.u32 %0, [%1];"
                             : "=r"(v) : "l"(ctr) : "memory");
            } while (v < target);
        }
        __syncthreads();
    }
}

// ---------------- K3: attention scores -----------------------------------------
__global__ __launch_bounds__(128)
void k_vu(const float* __restrict__ w_om, const float* __restrict__ b_om,
          const float* __restrict__ u_om) {
    __shared__ float so[16][Hc];
    __shared__ float sred[16][4];

    const int tid = threadIdx.x;
    const size_t base = (size_t)blockIdx.x * 16;

    for (int i = tid; i < 16 * 64; i += 128) {
        int r = i >> 6;
        int c = (i & 63) << 2;
        *(float4*)&so[r][c] = *(const float4*)&g_outs[(base + r) * Hc + c];
    }
    __syncthreads();

    u64 acc[8];
    #pragma unroll
    for (int r = 0; r < 8; r++) acc[r] = 0ull;

    for (int k = 0; k < Hc; k += 4) {
        float wa = w_om[(k + 0) * Ac + tid];
        float wb = w_om[(k + 1) * Ac + tid];
        float wc = w_om[(k + 2) * Ac + tid];
        float wd = w_om[(k + 3) * Ac + tid];
        u64 p0 = pack2(wa, wa);
        u64 p1 = pack2(wb, wb);
        u64 p2 = pack2(wc, wc);
        u64 p3 = pack2(wd, wd);
        #pragma unroll
        for (int r = 0; r < 8; r++) {
            float4 va = *(const float4*)&so[2 * r][k];
            float4 vb = *(const float4*)&so[2 * r + 1][k];
            fma2(acc[r], pack2(va.x, vb.x), p0);
            fma2(acc[r], pack2(va.y, vb.y), p1);
            fma2(acc[r], pack2(va.z, vb.z), p2);
            fma2(acc[r], pack2(va.w, vb.w), p3);
        }
    }

    const float bo = b_om[tid];
    const float uo = u_om[tid];
    float vr[16];
    #pragma unroll
    for (int r = 0; r < 8; r++) {
        float2 f = unpack2(acc[r]);
        vr[2 * r] = f.x;
        vr[2 * r + 1] = f.y;
    }
    #pragma unroll
    for (int r = 0; r < 16; r++) {
        float v = tanh_f(vr[r] + bo) * uo;
        #pragma unroll
        for (int o = 16; o; o >>= 1) v += __shfl_xor_sync(~0u, v, o);
        if ((tid & 31) == 0) sred[r][tid >> 5] = v;
    }
    __syncthreads();
    if (tid < 16) {
        g_vu[base + tid] = sred[tid][0] + sred[tid][1] + sred[tid][2] + sred[tid][3];
    }
}

// ---------------- block reductions ----------------------------------------------
__device__ __forceinline__ float blk_sum(float v, float* sr, int tid) {
    #pragma unroll
    for (int o = 16; o; o >>= 1) v += __shfl_xor_sync(~0u, v, o);
    if ((tid & 31) == 0) sr[tid >> 5] = v;
    __syncthreads();
    if (tid < 32) {
        float xx = (tid < 8) ? sr[tid] : 0.f;
        #pragma unroll
        for (int o = 4; o; o >>= 1) xx += __shfl_xor_sync(~0u, xx, o);
        if (tid == 0) sr[0] = xx;
    }
    __syncthreads();
    float r = sr[0];
    __syncthreads();
    return r;
}
__device__ __forceinline__ float blk_max(float v, float* sr, int tid) {
    #pragma unroll
    for (int o = 16; o; o >>= 1) v = fmaxf(v, __shfl_xor_sync(~0u, v, o));
    if ((tid & 31) == 0) sr[tid >> 5] = v;
    __syncthreads();
    if (tid < 32) {
        float xx = (tid < 8) ? sr[tid] : -INFINITY;
        #pragma unroll
        for (int o = 4; o; o >>= 1) xx = fmaxf(xx, __shfl_xor_sync(~0u, xx, o));
        if (tid == 0) sr[0] = xx;
    }
    __syncthreads();
    float r = sr[0];
    __syncthreads();
    return r;
}

// ---------------- K4: softmax over T, weighted sum, head ------------------------
__global__ __launch_bounds__(256)
void k_final(const float* __restrict__ w2, const float* __restrict__ b2,
             float* __restrict__ out) {
    __shared__ float sa[Tc];
    __shared__ float sr[32];

    const int b = blockIdx.x;
    const int tid = threadIdx.x;
    const float v0 = g_vu[b * Tc + tid];
    const float v1 = g_vu[b * Tc + 256 + tid];

    const float m = blk_max(fmaxf(v0, v1), sr, tid);
    const float e0 = expf(v0 - m);
    const float e1 = expf(v1 - m);
    sa[tid] = e0;
    sa[tid + 256] = e1;
    const float Z = blk_sum(e0 + e1, sr, tid);
    const float Zinv = 1.0f / Z;

    const float* op = g_outs + (size_t)b * Tc * Hc + tid;
    float a0 = 0.f;
    float a1 = 0.f;
    float a2 = 0.f;
    float a3 = 0.f;
    for (int t = 0; t < Tc; t += 4) {
        a0 = fmaf(__ldcs(&op[(size_t)t * Hc]),       sa[t],     a0);
        a1 = fmaf(__ldcs(&op[(size_t)(t + 1) * Hc]), sa[t + 1], a1);
        a2 = fmaf(__ldcs(&op[(size_t)(t + 2) * Hc]), sa[t + 2], a2);
        a3 = fmaf(__ldcs(&op[(size_t)(t + 3) * Hc]), sa[t + 3], a3);
    }
    float acc = ((a0 + a1) + (a2 + a3)) * Zinv;

    const float l0 = blk_sum(acc * w2[tid * 2], sr, tid);
    const float l1 = blk_sum(acc * w2[tid * 2 + 1], sr, tid);

    if (tid == 0) {
        float aa0 = l0 + b2[0];
        float aa1 = l1 + b2[1];
        float mm = fmaxf(aa0, aa1);
        float x0 = expf(aa0 - mm);
        float x1 = expf(aa1 - mm);
        float s = 1.0f / (x0 + x1);
        out[b * 2 + 0] = x0 * s;
        out[b * 2 + 1] = x1 * s;
    }
}

// ---------------- launcher -------------------------------------------------------
extern "C" void kernel_launch(void* const* d_in, const int* in_sizes, int n_in,
                              void* d_out, int out_size) {
    const int*   x     = (const int*)  d_in[0];
    const float* embed = (const float*)d_in[1];
    const float* lk    = (const float*)d_in[2];
    const float* bias  = (const float*)d_in[3];
    const float* w_om  = (const float*)d_in[4];
    const float* b_om  = (const float*)d_in[5];
    const float* u_om  = (const float*)d_in[6];
    const float* w2    = (const float*)d_in[7];
    const float* b2    = (const float*)d_in[8];
    float* out = (float*)d_out;

    cudaFuncSetAttribute(k_xgemm4, cudaFuncAttributeMaxDynamicSharedMemorySize,
                         SMX_TOTAL);
    cudaFuncSetAttribute(k_lstm5, cudaFuncAttributeMaxDynamicSharedMemorySize,
                         SMEM_L4);

    k_seqlen<<<Bc, 256>>>(x);
    k_init<<<1, 512>>>();

    dim3 gw(8, 32);
    dim3 bw(32, 8);
    k_wsplit<<<gw, bw>>>(lk, 0, 0);     // W_x -> g_Bhi/g_Blo
    k_wsplit<<<gw, bw>>>(lk, 256, 1);   // W_h -> g_Whhi/g_Whlo

    k_esplit<<<(Vc * 256) / (256 * 8), 256>>>(embed);

    dim3 g1(ZC / 128, (Bc * Tc) / 128);   // (8, 1024)
    k_xgemm4<<<g1, 256, SMX_TOTAL>>>(x, bias);

    k_lstm5<<<NCTA_L, 512, SMEM_L4>>>();

    k_vu<<<(Bc * Tc) / 16, 128>>>(w_om, b_om, u_om);

    k_final<<<Bc, 256>>>(w2, b2, out);
}

// round 13
// speedup vs baseline: 6.7822x; 1.0395x over previous
#include <cuda_runtime.h>
#include <cuda_bf16.h>
#include <stdint.h>
#include <math.h>

#define Bc 256
#define Tc 512
#define Dc 256
#define Hc 256
#define Ac 128
#define ZC 1024
#define Vc 50000

#define NCTA_L 128

// ---------------- scratch globals --------------------------------------------
__device__ float g_xz[(size_t)Bc * Tc * ZC];
__device__ __nv_bfloat16 g_ohi[(size_t)Bc * Tc * Hc];  // outs, bf16 hi
__device__ __nv_bfloat16 g_olo[(size_t)Bc * Tc * Hc];  // outs, bf16 lo
__device__ float g_vu[Bc * Tc];
__device__ int   g_seqlen[Bc];
__device__ __nv_bfloat16 g_hhi[2][Bc][Hc];
__device__ __nv_bfloat16 g_hlo[2][Bc][Hc];
__device__ unsigned g_bar[16 * 32];
__device__ __nv_bfloat16 g_Bhi[1024 * 256];   // W_x^T hi, [n][k]
__device__ __nv_bfloat16 g_Blo[1024 * 256];
__device__ __nv_bfloat16 g_Whhi[1024 * 256];  // W_h^T hi, [n][k]
__device__ __nv_bfloat16 g_Whlo[1024 * 256];
__device__ __nv_bfloat16 g_WOhi[128 * 256];   // w_omega^T hi, [a][k]
__device__ __nv_bfloat16 g_WOlo[128 * 256];
__device__ __nv_bfloat16 g_Ehi[(size_t)Vc * 256];
__device__ __nv_bfloat16 g_Elo[(size_t)Vc * 256];

typedef unsigned long long u64;

__device__ __forceinline__ float sigm(float x) { return 1.0f / (1.0f + __expf(-x)); }
__device__ __forceinline__ float tanh_f(float x) {
    float ax = fabsf(x);
    float e = __expf(-2.0f * ax);
    float r = (1.0f - e) / (1.0f + e);
    return copysignf(r, x);
}
__device__ __forceinline__ uint32_t smem_u32(const void* p) {
    uint32_t a;
    asm("{ .reg .u64 t; cvta.to.shared.u64 t, %1; cvt.u32.u64 %0, t; }"
        : "=r"(a) : "l"(p));
    return a;
}

// ---------------- mma.sync / cp.async helpers ----------------------------------
__device__ __forceinline__ void ldmx4(uint32_t* r, uint32_t addr) {
    asm volatile("ldmatrix.sync.aligned.m8n8.x4.shared.b16 {%0,%1,%2,%3}, [%4];"
                 : "=r"(r[0]), "=r"(r[1]), "=r"(r[2]), "=r"(r[3]) : "r"(addr));
}
__device__ __forceinline__ void mma16816(float* c, const uint32_t* a,
                                         uint32_t b0, uint32_t b1) {
    asm volatile(
        "mma.sync.aligned.m16n8k16.row.col.f32.bf16.bf16.f32 "
        "{%0,%1,%2,%3}, {%4,%5,%6,%7}, {%8,%9}, {%0,%1,%2,%3};"
        : "+f"(c[0]), "+f"(c[1]), "+f"(c[2]), "+f"(c[3])
        : "r"(a[0]), "r"(a[1]), "r"(a[2]), "r"(a[3]), "r"(b0), "r"(b1));
}
#define CP16(dst, src) \
    asm volatile("cp.async.cg.shared.global [%0], [%1], 16;" \
                 :: "r"(dst), "l"(src) : "memory")
#define CP_COMMIT() asm volatile("cp.async.commit_group;" ::: "memory")
#define CP_WAIT1()  asm volatile("cp.async.wait_group 1;" ::: "memory")
#define CP_WAIT0()  asm volatile("cp.async.wait_group 0;" ::: "memory")

// ---------------- K0: seq_len --------------------------------------------------
__global__ void k_seqlen(const int* __restrict__ x) {
    const int b = blockIdx.x;
    const int tid = threadIdx.x;
    int c = (x[b * Tc + tid] != 0) + (x[b * Tc + 256 + tid] != 0);
    #pragma unroll
    for (int o = 16; o; o >>= 1) c += __shfl_xor_sync(~0u, c, o);
    __shared__ int s[8];
    if ((tid & 31) == 0) s[tid >> 5] = c;
    __syncthreads();
    if (tid == 0) {
        int t = 0;
        #pragma unroll
        for (int i = 0; i < 8; i++) t += s[i];
        g_seqlen[b] = t;
    }
}

__global__ void k_init() {
    if (threadIdx.x < 16 * 32) g_bar[threadIdx.x] = 0u;
}

// ---------------- K0b: W transpose + bf16 hi/lo split --------------------------
__global__ void k_wsplit(const float* __restrict__ lk, int koff, int which) {
    __shared__ float s[32][33];
    const int kt = blockIdx.x * 32;
    const int nt = blockIdx.y * 32;
    const int tx = threadIdx.x;
    const int ty = threadIdx.y;
    #pragma unroll
    for (int i = 0; i < 4; i++) {
        s[ty + 8 * i][tx] = lk[(size_t)(koff + kt + ty + 8 * i) * ZC + nt + tx];
    }
    __syncthreads();
    __nv_bfloat16* dhi = which ? g_Whhi : g_Bhi;
    __nv_bfloat16* dlo = which ? g_Whlo : g_Blo;
    #pragma unroll
    for (int i = 0; i < 4; i++) {
        const int n = ty + 8 * i;
        float v = s[tx][n];
        __nv_bfloat16 h = __float2bfloat16(v);
        float lo = v - __bfloat162float(h);
        dhi[(size_t)(nt + n) * 256 + kt + tx] = h;
        dlo[(size_t)(nt + n) * 256 + kt + tx] = __float2bfloat16(lo);
    }
}

// ---------------- K0b2: w_omega transpose + split (256x128 -> [a][k]) ----------
__global__ void k_wosplit(const float* __restrict__ w_om) {
    __shared__ float s[32][33];
    const int kt = blockIdx.x * 32;   // 0..224
    const int at = blockIdx.y * 32;   // 0..96
    const int tx = threadIdx.x;
    const int ty = threadIdx.y;
    #pragma unroll
    for (int i = 0; i < 4; i++) {
        s[ty + 8 * i][tx] = w_om[(size_t)(kt + ty + 8 * i) * Ac + at + tx];
    }
    __syncthreads();
    #pragma unroll
    for (int i = 0; i < 4; i++) {
        const int n = ty + 8 * i;
        float v = s[tx][n];
        __nv_bfloat16 h = __float2bfloat16(v);
        float lo = v - __bfloat162float(h);
        g_WOhi[(size_t)(at + n) * 256 + kt + tx] = h;
        g_WOlo[(size_t)(at + n) * 256 + kt + tx] = __float2bfloat16(lo);
    }
}

// ---------------- K0c: embedding table bf16 hi/lo split ------------------------
__global__ __launch_bounds__(256)
void k_esplit(const float* __restrict__ embed) {
    const size_t base = ((size_t)blockIdx.x * 256 + threadIdx.x) * 8;
    if (base >= (size_t)Vc * 256) return;
    float4 v0 = *(const float4*)(embed + base);
    float4 v1 = *(const float4*)(embed + base + 4);
    __nv_bfloat162 h0 = __floats2bfloat162_rn(v0.x, v0.y);
    __nv_bfloat162 h1 = __floats2bfloat162_rn(v0.z, v0.w);
    __nv_bfloat162 h2 = __floats2bfloat162_rn(v1.x, v1.y);
    __nv_bfloat162 h3 = __floats2bfloat162_rn(v1.z, v1.w);
    __nv_bfloat162 l0 = __floats2bfloat162_rn(v0.x - __bfloat162float(h0.x),
                                              v0.y - __bfloat162float(h0.y));
    __nv_bfloat162 l1 = __floats2bfloat162_rn(v0.z - __bfloat162float(h1.x),
                                              v0.w - __bfloat162float(h1.y));
    __nv_bfloat162 l2 = __floats2bfloat162_rn(v1.x - __bfloat162float(h2.x),
                                              v1.y - __bfloat162float(h2.y));
    __nv_bfloat162 l3 = __floats2bfloat162_rn(v1.z - __bfloat162float(h3.x),
                                              v1.w - __bfloat162float(h3.y));
    uint4 ph;
    ph.x = *(uint32_t*)&h0; ph.y = *(uint32_t*)&h1;
    ph.z = *(uint32_t*)&h2; ph.w = *(uint32_t*)&h3;
    uint4 pl;
    pl.x = *(uint32_t*)&l0; pl.y = *(uint32_t*)&l1;
    pl.z = *(uint32_t*)&l2; pl.w = *(uint32_t*)&l3;
    __stcs((uint4*)&g_Ehi[base], ph);
    __stcs((uint4*)&g_Elo[base], pl);
}

// ---------------- shared GEMM pipeline constants -------------------------------
#define AST2 40
#define X_TOK  0
#define X_BIAS 512
#define X_ARR  10240
#define X_STG  (4 * X_ARR)
#define X_BASE 1024
#define SMX_TOTAL (X_BASE + 2 * X_STG)      // 82944

#define VU_BASE 4096
#define SMV_TOTAL (VU_BASE + 2 * X_STG)     // 86016

extern __shared__ char smx[];

// ---------------- K1: xz GEMM (R12-passing, unchanged) -------------------------
__global__ __launch_bounds__(256, 2)
void k_xgemm4(const int* __restrict__ x, const float* __restrict__ bias) {
    const uint32_t sb = smem_u32(smx);
    const int tid  = threadIdx.x;
    const int wid  = tid >> 5;
    const int lane = tid & 31;
    const int bn = blockIdx.x * 128;
    const int bm = blockIdx.y * 128;

    int*   stok  = (int*)(smx + X_TOK);
    float* sbias = (float*)(smx + X_BIAS);

    if (tid < 128) {
        stok[tid]  = x[bm + tid];
        sbias[tid] = bias[bn + tid];
    }
    __syncthreads();

    const int wm = (wid & 1) * 64;
    const int wn = (wid >> 1) * 32;

    float acc[4][4][4];
    #pragma unroll
    for (int mt = 0; mt < 4; mt++)
        #pragma unroll
        for (int nt = 0; nt < 4; nt++)
            #pragma unroll
            for (int i = 0; i < 4; i++) acc[mt][nt][i] = 0.f;

    const int lrow = tid >> 1;
    const int lk16 = (tid & 1) * 16;
    const size_t asrc = (size_t)stok[lrow] * 256 + lk16;
    const size_t bsrc = (size_t)(bn + lrow) * 256 + lk16;
    const uint32_t ldst = (uint32_t)((lrow * AST2 + lk16) * 2);

    const uint32_t a_comp = (uint32_t)(((wm + (lane & 15)) * AST2 + (lane >> 4) * 8) * 2);
    const uint32_t b_comp = (uint32_t)(((wn + ((lane >> 4) & 1) * 8 + (lane & 7)) * AST2
                                        + ((lane >> 3) & 1) * 8) * 2);

#define X4_ISSUE(CK, STG) do {                                                 \
    const int _kb = (CK) * 32;                                                 \
    const uint32_t _st = sb + X_BASE + (STG) * X_STG + ldst;                   \
    CP16(_st,                 (const char*)&g_Ehi[asrc + _kb]);                \
    CP16(_st + 16,            (const char*)&g_Ehi[asrc + _kb + 8]);            \
    CP16(_st + X_ARR,         (const char*)&g_Elo[asrc + _kb]);                \
    CP16(_st + X_ARR + 16,    (const char*)&g_Elo[asrc + _kb + 8]);            \
    CP16(_st + 2*X_ARR,       (const char*)&g_Bhi[bsrc + _kb]);                \
    CP16(_st + 2*X_ARR + 16,  (const char*)&g_Bhi[bsrc + _kb + 8]);            \
    CP16(_st + 3*X_ARR,       (const char*)&g_Blo[bsrc + _kb]);                \
    CP16(_st + 3*X_ARR + 16,  (const char*)&g_Blo[bsrc + _kb + 8]);            \
    CP_COMMIT();                                                               \
} while (0)

    X4_ISSUE(0, 0);

    for (int ck = 0; ck < 8; ck++) {
        if (ck < 7) {
            X4_ISSUE(ck + 1, (ck + 1) & 1);
            CP_WAIT1();
        } else {
            CP_WAIT0();
        }
        __syncthreads();

        const uint32_t stg = sb + X_BASE + (uint32_t)((ck & 1) * X_STG);
        const uint32_t aoff_hi = stg + a_comp;
        const uint32_t aoff_lo = stg + X_ARR + a_comp;
        const uint32_t boff_hi = stg + 2 * X_ARR + b_comp;
        const uint32_t boff_lo = stg + 3 * X_ARR + b_comp;

        #pragma unroll
        for (int ks = 0; ks < 2; ks++) {
            const uint32_t kb = (uint32_t)(ks * 32);
            uint32_t bhi[2][4];
            uint32_t blo[2][4];
            #pragma unroll
            for (int np = 0; np < 2; np++) {
                const uint32_t pb = (uint32_t)(np * 16 * AST2 * 2) + kb;
                ldmx4(bhi[np], boff_hi + pb);
                ldmx4(blo[np], boff_lo + pb);
            }
            #pragma unroll
            for (int mt = 0; mt < 4; mt++) {
                const uint32_t mb = (uint32_t)(mt * 16 * AST2 * 2) + kb;
                uint32_t ahi[4];
                uint32_t alo[4];
                ldmx4(ahi, aoff_hi + mb);
                ldmx4(alo, aoff_lo + mb);
                #pragma unroll
                for (int nt = 0; nt < 4; nt++) {
                    const uint32_t b0 = bhi[nt >> 1][(nt & 1) * 2];
                    const uint32_t b1 = bhi[nt >> 1][(nt & 1) * 2 + 1];
                    const uint32_t c0 = blo[nt >> 1][(nt & 1) * 2];
                    const uint32_t c1 = blo[nt >> 1][(nt & 1) * 2 + 1];
                    mma16816(acc[mt][nt], ahi, b0, b1);
                    mma16816(acc[mt][nt], alo, b0, b1);
                    mma16816(acc[mt][nt], ahi, c0, c1);
                }
            }
        }
        __syncthreads();
    }

    #pragma unroll
    for (int mt = 0; mt < 4; mt++) {
        const int m0 = bm + wm + mt * 16 + (lane >> 2);
        #pragma unroll
        for (int nt = 0; nt < 4; nt++) {
            const int nl = wn + nt * 8 + (lane & 3) * 2;
            const float b0 = sbias[nl];
            const float b1 = sbias[nl + 1];
            float2 v0;
            float2 v1;
            v0.x = acc[mt][nt][0] + b0;
            v0.y = acc[mt][nt][1] + b1;
            v1.x = acc[mt][nt][2] + b0;
            v1.y = acc[mt][nt][3] + b1;
            __stcs((float2*)&g_xz[(size_t)m0 * ZC + bn + nl], v0);
            __stcs((float2*)&g_xz[(size_t)(m0 + 8) * ZC + bn + nl], v1);
        }
    }
}

// ---------------- K2: LSTM (R12-passing + bf16 outs) ---------------------------
#define WST 264
#define ZST 136
#define L4_WHI 0
#define L4_WLO 67584
#define L4_HHI 135168
#define L4_HLO 143616
#define L4_ZP  152064
#define SMEM_L4 221696

__global__ __launch_bounds__(512, 1)
void k_lstm5() {
    extern __shared__ char sml[];
    __nv_bfloat16* sWhi = (__nv_bfloat16*)(sml + L4_WHI);
    __nv_bfloat16* sWlo = (__nv_bfloat16*)(sml + L4_WLO);
    __nv_bfloat16* sHhi = (__nv_bfloat16*)(sml + L4_HHI);
    __nv_bfloat16* sHlo = (__nv_bfloat16*)(sml + L4_HLO);
    float* sZp = (float*)(sml + L4_ZP);
    const uint32_t sbase = smem_u32(sml);

    const int tid = threadIdx.x;
    const int g  = blockIdx.x & 7;
    const int bg = blockIdx.x >> 3;
    const int u0 = g * 32;
    const int b0 = bg * 16;
    unsigned* const ctr = &g_bar[bg * 32];

    {
        const int n = tid >> 2;
        const int c = tid & 3;
        const int gcol = (n >> 5) * 256 + u0 + (n & 31);
        const size_t src = (size_t)gcol * 256 + c * 64;
        const int dst = n * WST + c * 64;
        #pragma unroll
        for (int i = 0; i < 8; i++) {
            *(uint4*)&sWhi[dst + i * 8] = *(const uint4*)&g_Whhi[src + i * 8];
            *(uint4*)&sWlo[dst + i * 8] = *(const uint4*)&g_Whlo[src + i * 8];
        }
    }

    const int wid  = tid >> 5;
    const int lane = tid & 31;
    const int nh = wid & 1;
    const int kg = wid >> 1;
    const int n0 = nh * 64;
    const int k0 = kg * 32;

    const uint32_t a_part = (uint32_t)((lane & 15) * WST + (lane >> 4) * 8) * 2;
    const uint32_t aoff_hi = sbase + L4_HHI + a_part;
    const uint32_t aoff_lo = sbase + L4_HLO + a_part;
    const uint32_t brow = (uint32_t)(n0 + ((lane >> 4) & 1) * 8 + (lane & 7));
    const uint32_t bk   = (uint32_t)(((lane >> 3) & 1) * 8);
    const uint32_t b_part = (brow * WST + bk) * 2;
    const uint32_t boff_hi = sbase + L4_WHI + b_part;
    const uint32_t boff_lo = sbase + L4_WLO + b_part;

    const int gu = lane;
    const int gb = wid;
    float c_reg = 0.f;
    float h_reg = 0.f;
    const int slen = g_seqlen[b0 + gb];
    const size_t xzg = ((size_t)(b0 + gb) * Tc) * ZC + u0 + gu;
    const size_t og  = ((size_t)(b0 + gb) * Tc) * Hc + u0 + gu;
    __nv_bfloat16* const ghh0 = &g_hhi[0][b0 + gb][u0 + gu];
    __nv_bfloat16* const ghh1 = &g_hhi[1][b0 + gb][u0 + gu];
    __nv_bfloat16* const ghl0 = &g_hlo[0][b0 + gb][u0 + gu];
    __nv_bfloat16* const ghl1 = &g_hlo[1][b0 + gb][u0 + gu];

    const int srow = tid >> 5;
    const int skof = lane * 8;
    const __nv_bfloat16* const hshi0 = &g_hhi[0][b0 + srow][skof];
    const __nv_bfloat16* const hshi1 = &g_hhi[1][b0 + srow][skof];
    const __nv_bfloat16* const hslo0 = &g_hlo[0][b0 + srow][skof];
    const __nv_bfloat16* const hslo1 = &g_hlo[1][b0 + srow][skof];
    const int hdst = srow * WST + skof;

    float xg0 = __ldcs(&g_xz[xzg]);
    float xg1 = __ldcs(&g_xz[xzg + 256]);
    float xg2 = __ldcs(&g_xz[xzg + 512]);
    float xg3 = __ldcs(&g_xz[xzg + 768]);

    for (int t = 0; t < Tc; t++) {
        if (t == 0) {
            uint4 z4 = make_uint4(0u, 0u, 0u, 0u);
            *(uint4*)&sHhi[hdst] = z4;
            *(uint4*)&sHlo[hdst] = z4;
        } else {
            const int bsel = t & 1;
            uint4 vh = __ldcg((const uint4*)(bsel ? hshi1 : hshi0));
            uint4 vl = __ldcg((const uint4*)(bsel ? hslo1 : hslo0));
            *(uint4*)&sHhi[hdst] = vh;
            *(uint4*)&sHlo[hdst] = vl;
        }
        __syncthreads();

        float acc[8][4];
        #pragma unroll
        for (int nt = 0; nt < 8; nt++)
            #pragma unroll
            for (int i = 0; i < 4; i++) acc[nt][i] = 0.f;

        #pragma unroll
        for (int ks = 0; ks < 2; ks++) {
            const uint32_t kb = (uint32_t)((k0 + ks * 16) * 2);
            uint32_t ahi[4], alo[4];
            ldmx4(ahi, aoff_hi + kb);
            ldmx4(alo, aoff_lo + kb);
            #pragma unroll
            for (int p = 0; p < 4; p++) {
                const uint32_t pb = (uint32_t)(p * 16 * WST * 2) + kb;
                uint32_t bhi[4], blo[4];
                ldmx4(bhi, boff_hi + pb);
                ldmx4(blo, boff_lo + pb);
                mma16816(acc[2 * p],     ahi, bhi[0], bhi[1]);
                mma16816(acc[2 * p + 1], ahi, bhi[2], bhi[3]);
                mma16816(acc[2 * p],     alo, bhi[0], bhi[1]);
                mma16816(acc[2 * p + 1], alo, bhi[2], bhi[3]);
                mma16816(acc[2 * p],     ahi, blo[0], blo[1]);
                mma16816(acc[2 * p + 1], ahi, blo[2], blo[3]);
            }
        }

        {
            const int m  = lane >> 2;
            const int cb = (lane & 3) * 2;
            #pragma unroll
            for (int nt = 0; nt < 8; nt++) {
                const int col = n0 + nt * 8 + cb;
                *(float2*)&sZp[(kg * 16 + m) * ZST + col] =
                    make_float2(acc[nt][0], acc[nt][1]);
                *(float2*)&sZp[(kg * 16 + m + 8) * ZST + col] =
                    make_float2(acc[nt][2], acc[nt][3]);
            }
        }
        __syncthreads();

        float zi = xg0;
        float zj = xg1;
        float zf = xg2;
        float zo = xg3;
        #pragma unroll
        for (int p = 0; p < 8; p++) {
            const float* zp = &sZp[(p * 16 + gb) * ZST];
            zi += zp[gu];
            zj += zp[32 + gu];
            zf += zp[64 + gu];
            zo += zp[96 + gu];
        }
        float cn = c_reg * sigm(zf + 1.f) + sigm(zi) * tanh_f(zj);
        float hn = tanh_f(cn) * sigm(zo);
        bool m = (t < slen);
        c_reg = m ? cn : c_reg;
        h_reg = m ? hn : h_reg;

        {
            __nv_bfloat16 hh = __float2bfloat16(h_reg);
            __nv_bfloat16 hl = __float2bfloat16(h_reg - __bfloat162float(hh));
            const int nb = (t + 1) & 1;
            *(nb ? ghh1 : ghh0) = hh;
            *(nb ? ghl1 : ghl0) = hl;
        }

        __threadfence();
        __syncthreads();
        if (tid == 0) atomicAdd(ctr, 1u);

        // hidden under barrier skew: outs store (bf16 hi/lo) + next xz prefetch
        {
            float o = m ? hn : 0.f;
            __nv_bfloat16 oh = __float2bfloat16(o);
            __nv_bfloat16 ol = __float2bfloat16(o - __bfloat162float(oh));
            g_ohi[og + (size_t)t * Hc] = oh;
            g_olo[og + (size_t)t * Hc] = ol;
        }
        if (t + 1 < Tc) {
            const size_t xb = xzg + (size_t)(t + 1) * ZC;
            xg0 = __ldcs(&g_xz[xb]);
            xg1 = __ldcs(&g_xz[xb + 256]);
            xg2 = __ldcs(&g_xz[xb + 512]);
            xg3 = __ldcs(&g_xz[xb + 768]);
        }

        if (tid == 0) {
            const unsigned target = (unsigned)(t + 1) * 8u;
            unsigned v;
            do {
                asm volatile("ld.global.acquire.gpu.u32 %0, [%1];"
                             : "=r"(v) : "l"(ctr) : "memory");
            } while (v < target);
        }
        __syncthreads();
    }
}

// ---------------- K3: attention scores via HMMA --------------------------------
// grid 1024 m-tiles x 1 n-tile(128 = A). K=256 over outs hi/lo; epilogue does
// tanh(+b_om)*u_om and row-sums into g_vu.
__global__ __launch_bounds__(256, 2)
void k_vu2(const float* __restrict__ b_om, const float* __restrict__ u_om) {
    const uint32_t sb = smem_u32(smx);
    const int tid  = threadIdx.x;
    const int wid  = tid >> 5;
    const int lane = tid & 31;
    const int bm = blockIdx.x * 128;

    float* sbom = (float*)(smx + 0);
    float* suom = (float*)(smx + 512);
    float* sred = (float*)(smx + 1024);   // [128][4]

    if (tid < 128) {
        sbom[tid] = b_om[tid];
        suom[tid] = u_om[tid];
    }
    __syncthreads();

    const int wm = (wid & 1) * 64;
    const int wn = (wid >> 1) * 32;

    float acc[4][4][4];
    #pragma unroll
    for (int mt = 0; mt < 4; mt++)
        #pragma unroll
        for (int nt = 0; nt < 4; nt++)
            #pragma unroll
            for (int i = 0; i < 4; i++) acc[mt][nt][i] = 0.f;

    const int lrow = tid >> 1;
    const int lk16 = (tid & 1) * 16;
    const size_t asrc = (size_t)(bm + lrow) * 256 + lk16;
    const size_t bsrc = (size_t)lrow * 256 + lk16;
    const uint32_t ldst = (uint32_t)((lrow * AST2 + lk16) * 2);

    const uint32_t a_comp = (uint32_t)(((wm + (lane & 15)) * AST2 + (lane >> 4) * 8) * 2);
    const uint32_t b_comp = (uint32_t)(((wn + ((lane >> 4) & 1) * 8 + (lane & 7)) * AST2
                                        + ((lane >> 3) & 1) * 8) * 2);

#define VU_ISSUE(CK, STG) do {                                                 \
    const int _kb = (CK) * 32;                                                 \
    const uint32_t _st = sb + VU_BASE + (STG) * X_STG + ldst;                  \
    CP16(_st,                 (const char*)&g_ohi[asrc + _kb]);                \
    CP16(_st + 16,            (const char*)&g_ohi[asrc + _kb + 8]);            \
    CP16(_st + X_ARR,         (const char*)&g_olo[asrc + _kb]);                \
    CP16(_st + X_ARR + 16,    (const char*)&g_olo[asrc + _kb + 8]);            \
    CP16(_st + 2*X_ARR,       (const char*)&g_WOhi[bsrc + _kb]);               \
    CP16(_st + 2*X_ARR + 16,  (const char*)&g_WOhi[bsrc + _kb + 8]);           \
    CP16(_st + 3*X_ARR,       (const char*)&g_WOlo[bsrc + _kb]);               \
    CP16(_st + 3*X_ARR + 16,  (const char*)&g_WOlo[bsrc + _kb + 8]);           \
    CP_COMMIT();                                                               \
} while (0)

    VU_ISSUE(0, 0);

    for (int ck = 0; ck < 8; ck++) {
        if (ck < 7) {
            VU_ISSUE(ck + 1, (ck + 1) & 1);
            CP_WAIT1();
        } else {
            CP_WAIT0();
        }
        __syncthreads();

        const uint32_t stg = sb + VU_BASE + (uint32_t)((ck & 1) * X_STG);
        const uint32_t aoff_hi = stg + a_comp;
        const uint32_t aoff_lo = stg + X_ARR + a_comp;
        const uint32_t boff_hi = stg + 2 * X_ARR + b_comp;
        const uint32_t boff_lo = stg + 3 * X_ARR + b_comp;

        #pragma unroll
        for (int ks = 0; ks < 2; ks++) {
            const uint32_t kb = (uint32_t)(ks * 32);
            uint32_t bhi[2][4];
            uint32_t blo[2][4];
            #pragma unroll
            for (int np = 0; np < 2; np++) {
                const uint32_t pb = (uint32_t)(np * 16 * AST2 * 2) + kb;
                ldmx4(bhi[np], boff_hi + pb);
                ldmx4(blo[np], boff_lo + pb);
            }
            #pragma unroll
            for (int mt = 0; mt < 4; mt++) {
                const uint32_t mb = (uint32_t)(mt * 16 * AST2 * 2) + kb;
                uint32_t ahi[4];
                uint32_t alo[4];
                ldmx4(ahi, aoff_hi + mb);
                ldmx4(alo, aoff_lo + mb);
                #pragma unroll
                for (int nt = 0; nt < 4; nt++) {
                    const uint32_t b0 = bhi[nt >> 1][(nt & 1) * 2];
                    const uint32_t b1 = bhi[nt >> 1][(nt & 1) * 2 + 1];
                    const uint32_t c0 = blo[nt >> 1][(nt & 1) * 2];
                    const uint32_t c1 = blo[nt >> 1][(nt & 1) * 2 + 1];
                    mma16816(acc[mt][nt], ahi, b0, b1);
                    mma16816(acc[mt][nt], alo, b0, b1);
                    mma16816(acc[mt][nt], ahi, c0, c1);
                }
            }
        }
        __syncthreads();
    }

    // ---- epilogue: tanh(+b)*u, row-sum over n=128 ----
    #pragma unroll
    for (int mt = 0; mt < 4; mt++) {
        float rsum[2];
        rsum[0] = 0.f;
        rsum[1] = 0.f;
        #pragma unroll
        for (int nt = 0; nt < 4; nt++) {
            #pragma unroll
            for (int i = 0; i < 4; i++) {
                const int col = wn + nt * 8 + (lane & 3) * 2 + (i & 1);
                float v = tanh_f(acc[mt][nt][i] + sbom[col]) * suom[col];
                rsum[i >> 1] += v;
            }
        }
        #pragma unroll
        for (int hf = 0; hf < 2; hf++) {
            float r = rsum[hf];
            r += __shfl_xor_sync(~0u, r, 1);
            r += __shfl_xor_sync(~0u, r, 2);
            if ((lane & 3) == 0) {
                const int row = wm + mt * 16 + (lane >> 2) + hf * 8;
                sred[row * 4 + (wid >> 1)] = r;
            }
        }
    }
    __syncthreads();
    if (tid < 128) {
        g_vu[bm + tid] = sred[tid * 4] + sred[tid * 4 + 1]
                       + sred[tid * 4 + 2] + sred[tid * 4 + 3];
    }
}

// ---------------- block reductions ----------------------------------------------
__device__ __forceinline__ float blk_sum(float v, float* sr, int tid) {
    #pragma unroll
    for (int o = 16; o; o >>= 1) v += __shfl_xor_sync(~0u, v, o);
    if ((tid & 31) == 0) sr[tid >> 5] = v;
    __syncthreads();
    if (tid < 32) {
        float xx = (tid < 8) ? sr[tid] : 0.f;
        #pragma unroll
        for (int o = 4; o; o >>= 1) xx += __shfl_xor_sync(~0u, xx, o);
        if (tid == 0) sr[0] = xx;
    }
    __syncthreads();
    float r = sr[0];
    __syncthreads();
    return r;
}
__device__ __forceinline__ float blk_max(float v, float* sr, int tid) {
    #pragma unroll
    for (int o = 16; o; o >>= 1) v = fmaxf(v, __shfl_xor_sync(~0u, v, o));
    if ((tid & 31) == 0) sr[tid >> 5] = v;
    __syncthreads();
    if (tid < 32) {
        float xx = (tid < 8) ? sr[tid] : -INFINITY;
        #pragma unroll
        for (int o = 4; o; o >>= 1) xx = fmaxf(xx, __shfl_xor_sync(~0u, xx, o));
        if (tid == 0) sr[0] = xx;
    }
    __syncthreads();
    float r = sr[0];
    __syncthreads();
    return r;
}

// ---------------- K4: softmax over T, weighted sum, head ------------------------
__global__ __launch_bounds__(256)
void k_final(const float* __restrict__ w2, const float* __restrict__ b2,
             float* __restrict__ out) {
    __shared__ float sa[Tc];
    __shared__ float sr[32];

    const int b = blockIdx.x;
    const int tid = threadIdx.x;
    const float v0 = g_vu[b * Tc + tid];
    const float v1 = g_vu[b * Tc + 256 + tid];

    const float m = blk_max(fmaxf(v0, v1), sr, tid);
    const float e0 = expf(v0 - m);
    const float e1 = expf(v1 - m);
    sa[tid] = e0;
    sa[tid + 256] = e1;
    const float Z = blk_sum(e0 + e1, sr, tid);
    const float Zinv = 1.0f / Z;

    const __nv_bfloat16* oph = g_ohi + (size_t)b * Tc * Hc + tid;
    const __nv_bfloat16* opl = g_olo + (size_t)b * Tc * Hc + tid;
    float a[8];
    #pragma unroll
    for (int i = 0; i < 8; i++) a[i] = 0.f;
    for (int t = 0; t < Tc; t += 8) {
        #pragma unroll
        for (int i = 0; i < 8; i++) {
            const size_t off = (size_t)(t + i) * Hc;
            float v = __bfloat162float(oph[off]) + __bfloat162float(opl[off]);
            a[i] = fmaf(v, sa[t + i], a[i]);
        }
    }
    float acc = (((a[0] + a[1]) + (a[2] + a[3])) +
                 ((a[4] + a[5]) + (a[6] + a[7]))) * Zinv;

    const float l0 = blk_sum(acc * w2[tid * 2], sr, tid);
    const float l1 = blk_sum(acc * w2[tid * 2 + 1], sr, tid);

    if (tid == 0) {
        float aa0 = l0 + b2[0];
        float aa1 = l1 + b2[1];
        float mm = fmaxf(aa0, aa1);
        float x0 = expf(aa0 - mm);
        float x1 = expf(aa1 - mm);
        float s = 1.0f / (x0 + x1);
        out[b * 2 + 0] = x0 * s;
        out[b * 2 + 1] = x1 * s;
    }
}

// ---------------- launcher -------------------------------------------------------
extern "C" void kernel_launch(void* const* d_in, const int* in_sizes, int n_in,
                              void* d_out, int out_size) {
    const int*   x     = (const int*)  d_in[0];
    const float* embed = (const float*)d_in[1];
    const float* lk    = (const float*)d_in[2];
    const float* bias  = (const float*)d_in[3];
    const float* w_om  = (const float*)d_in[4];
    const float* b_om  = (const float*)d_in[5];
    const float* u_om  = (const float*)d_in[6];
    const float* w2    = (const float*)d_in[7];
    const float* b2    = (const float*)d_in[8];
    float* out = (float*)d_out;

    cudaFuncSetAttribute(k_xgemm4, cudaFuncAttributeMaxDynamicSharedMemorySize,
                         SMX_TOTAL);
    cudaFuncSetAttribute(k_vu2, cudaFuncAttributeMaxDynamicSharedMemorySize,
                         SMV_TOTAL);
    cudaFuncSetAttribute(k_lstm5, cudaFuncAttributeMaxDynamicSharedMemorySize,
                         SMEM_L4);

    k_seqlen<<<Bc, 256>>>(x);
    k_init<<<1, 512>>>();

    dim3 gw(8, 32);
    dim3 bw(32, 8);
    k_wsplit<<<gw, bw>>>(lk, 0, 0);     // W_x
    k_wsplit<<<gw, bw>>>(lk, 256, 1);   // W_h

    dim3 gwo(8, 4);
    k_wosplit<<<gwo, bw>>>(w_om);

    k_esplit<<<(Vc * 256) / (256 * 8), 256>>>(embed);

    dim3 g1(ZC / 128, (Bc * Tc) / 128);
    k_xgemm4<<<g1, 256, SMX_TOTAL>>>(x, bias);

    k_lstm5<<<NCTA_L, 512, SMEM_L4>>>();

    k_vu2<<<(Bc * Tc) / 128, 256, SMV_TOTAL>>>(b_om, u_om);

    k_final<<<Bc, 256>>>(w2, b2, out);
}